// round 4
// baseline (speedup 1.0000x reference)
#include <cuda_runtime.h>
#include <stdint.h>

#define G    16
#define NSEQ 4096
#define DD   64
#define CC   128
#define NC   32

// g_S now holds S^T: ST[e][d] = sum_j v[j][e] * k[j][d]  (exclusive-prefixed by pass2)
__device__ __align__(16) float g_S[2ull * G * NC * DD * DD];
__device__ __align__(16) float g_ksum[2ull * G * NC * DD];

typedef unsigned long long u64t;
__device__ __forceinline__ void fma2(u64t& d, u64t a, u64t b) {
    asm("fma.rn.f32x2 %0, %1, %2, %0;" : "+l"(d) : "l"(a), "l"(b));
}
__device__ __forceinline__ float lanesum(u64t p) {
    float2 f = *reinterpret_cast<float2*>(&p);
    return f.x + f.y;
}

// ---------------------------------------------------------------------------
// Pass 1: ST[e][d] = sum_j v[j][e] k[j][d];  ksum[d] = sum_j k[j][d]
// (identical math to before with A<->B swapped so the output is transposed)
// ---------------------------------------------------------------------------
__global__ __launch_bounds__(256) void pass1_kernel(const float* __restrict__ k1g,
                                                    const float* __restrict__ k2g,
                                                    const float* __restrict__ vg) {
    extern __shared__ float sm1[];
    float* as = sm1;            // v rows [j][e]
    float* bs = sm1 + CC * DD;  // k rows [j][d]
    const int c = blockIdx.x, g = blockIdx.y, m = blockIdx.z;
    const int tid = threadIdx.x;
    const size_t cbase = ((size_t)g * NSEQ + (size_t)c * CC) * DD;
    const float* vp = vg + cbase;
    const float* kp = (m ? k2g : k1g) + cbase;
    #pragma unroll
    for (int u = 0; u < 8; u++) {
        int idx = u * 256 + tid;
        ((float4*)as)[idx] = ((const float4*)vp)[idx];
        ((float4*)bs)[idx] = ((const float4*)kp)[idx];
    }
    __syncthreads();
    const int e0 = (tid >> 4) * 4, d0 = (tid & 15) * 4;
    // packed over d: acc[e][dp] lanes = (d0+2dp, d0+2dp+1)
    u64t acc[4][2];
    #pragma unroll
    for (int a = 0; a < 4; a++) { acc[a][0] = 0ull; acc[a][1] = 0ull; }
    #pragma unroll 4
    for (int j = 0; j < CC; j++) {
        u64t k0 = *(const u64t*)&bs[j * DD + d0];
        u64t k1 = *(const u64t*)&bs[j * DD + d0 + 2];
        float4 vv = *(const float4*)&as[j * DD + e0];
        float ve[4] = {vv.x, vv.y, vv.z, vv.w};
        #pragma unroll
        for (int a = 0; a < 4; a++) {
            float2 bb = make_float2(ve[a], ve[a]);
            u64t bp = *reinterpret_cast<u64t*>(&bb);
            fma2(acc[a][0], bp, k0);
            fma2(acc[a][1], bp, k1);
        }
    }
    float* Sp = &g_S[(((size_t)m * G + g) * NC + c) * (size_t)(DD * DD)];
    #pragma unroll
    for (int a = 0; a < 4; a++) {
        float2 x0 = *reinterpret_cast<float2*>(&acc[a][0]);
        float2 x1 = *reinterpret_cast<float2*>(&acc[a][1]);
        *(float4*)&Sp[(e0 + a) * DD + d0] = make_float4(x0.x, x0.y, x1.x, x1.y);
    }
    if (tid < DD) {
        float s = 0.f;
        #pragma unroll 4
        for (int j = 0; j < CC; j++) s += bs[j * DD + tid];
        g_ksum[(((size_t)m * G + g) * NC + c) * DD + tid] = s;
    }
}

// ---------------------------------------------------------------------------
// Pass 2: in-place EXCLUSIVE prefix sum over chunks (elementwise, layout-agnostic)
// ---------------------------------------------------------------------------
__global__ __launch_bounds__(256) void pass2_kernel() {
    const int g = blockIdx.x, m = blockIdx.y, tid = threadIdx.x;
    float* base = &g_S[(((size_t)m * G + g) * NC) * (size_t)(DD * DD)];
    float run[16];
    #pragma unroll
    for (int u = 0; u < 16; u++) run[u] = 0.f;
    for (int c = 0; c < NC; c++) {
        float* p = base + (size_t)c * (DD * DD);
        #pragma unroll
        for (int u = 0; u < 16; u++) {
            int idx = u * 256 + tid;
            float t = p[idx];
            p[idx] = run[u];
            run[u] += t;
        }
    }
    if (tid < DD) {
        float r = 0.f;
        float* kb = &g_ksum[(((size_t)m * G + g) * NC) * DD];
        for (int c = 0; c < NC; c++) {
            float t = kb[c * DD + tid];
            kb[c * DD + tid] = r;
            r += t;
        }
    }
}

// ---------------------------------------------------------------------------
// Pass 3 smem layout (float indices)
//   Q1[128][68] @0      Q2 @8704     K1 @17408    K2 @26112
//   T [128][132] @17408 (aliases K1+K2 after stage A)
//   VT[64][130]  @34816
//   ST1[64][68]  @43136  ST2 @47488
//   DEN[128][16] @51840  QKP @53888  DNV @54016  KP1 @54144  KP2 @54208
// ---------------------------------------------------------------------------
#define QP   68
#define TP   132
#define VP   130
#define SP   68
#define O_Q1 0
#define O_Q2 8704
#define O_K1 17408
#define O_K2 26112
#define O_T  17408
#define O_VT 34816
#define O_S1 43136
#define O_S2 47488
#define O_DEN 51840
#define O_QKP 53888
#define O_DNV 54016
#define O_KP1 54144
#define O_KP2 54208
#define SMEM3_FLOATS 54272
#define SMEM3_BYTES (SMEM3_FLOATS * 4)

__global__ __launch_bounds__(256) void pass3_kernel(const float* __restrict__ q1g,
                                                    const float* __restrict__ q2g,
                                                    const float* __restrict__ k1g,
                                                    const float* __restrict__ k2g,
                                                    const float* __restrict__ vg,
                                                    float* __restrict__ outg) {
    extern __shared__ float sm[];
    const int c = blockIdx.x, g = blockIdx.y, tid = threadIdx.x;
    const size_t cbase = ((size_t)g * NSEQ + (size_t)c * CC) * DD;

    // ---- load phase: q1,q2,k1,k2 padded rows; v transposed; ST1,ST2; KP ----
    #pragma unroll
    for (int u = 0; u < 8; u++) {
        int idx = u * 256 + tid;
        int row = idx >> 4, c4 = (idx & 15) * 4;
        *(float4*)&sm[O_Q1 + row * QP + c4] = ((const float4*)(q1g + cbase))[idx];
        *(float4*)&sm[O_Q2 + row * QP + c4] = ((const float4*)(q2g + cbase))[idx];
        *(float4*)&sm[O_K1 + row * QP + c4] = ((const float4*)(k1g + cbase))[idx];
        *(float4*)&sm[O_K2 + row * QP + c4] = ((const float4*)(k2g + cbase))[idx];
        float4 vv = ((const float4*)(vg + cbase))[idx];
        sm[O_VT + (c4 + 0) * VP + row] = vv.x;
        sm[O_VT + (c4 + 1) * VP + row] = vv.y;
        sm[O_VT + (c4 + 2) * VP + row] = vv.z;
        sm[O_VT + (c4 + 3) * VP + row] = vv.w;
    }
    {
        const float4* s1 = (const float4*)&g_S[(((size_t)0 * G + g) * NC + c) * (size_t)(DD * DD)];
        const float4* s2 = (const float4*)&g_S[(((size_t)1 * G + g) * NC + c) * (size_t)(DD * DD)];
        #pragma unroll
        for (int u = 0; u < 4; u++) {
            int idx = u * 256 + tid;
            int row = idx >> 4, c4 = (idx & 15) * 4;
            *(float4*)&sm[O_S1 + row * SP + c4] = s1[idx];
            *(float4*)&sm[O_S2 + row * SP + c4] = s2[idx];
        }
    }
    if (tid < DD) {
        sm[O_KP1 + tid] = g_ksum[(((size_t)0 * G + g) * NC + c) * DD + tid];
        sm[O_KP2 + tid] = g_ksum[(((size_t)1 * G + g) * NC + c) * DD + tid];
    }
    __syncthreads();

    // qkpre: q1_i.KP1 + q2_i.KP2
    if (tid < CC) {
        float a = 0.f;
        #pragma unroll 8
        for (int d = 0; d < DD; d++)
            a += sm[O_Q1 + tid * QP + d] * sm[O_KP1 + d] + sm[O_Q2 + tid * QP + d] * sm[O_KP2 + d];
        sm[O_QKP + tid] = a;
    }

    const int ig = tid >> 4, jg = tid & 15;
    const int i0 = ig * 8, j0 = jg * 8;

    // ---- Stage A: T[i][j] = q1_i.k1_j + q2_i.k2_j, packed over d ----
    u64t acc[8][8];
    #pragma unroll
    for (int a = 0; a < 8; a++)
        #pragma unroll
        for (int b = 0; b < 8; b++) acc[a][b] = 0ull;

    #pragma unroll 1
    for (int m = 0; m < 2; m++) {
        const float* Q = sm + (m ? O_Q2 : O_Q1);
        const float* K = sm + (m ? O_K2 : O_K1);
        #pragma unroll 1
        for (int dp = 0; dp < 32; dp++) {
            u64t qv[8], kv[8];
            #pragma unroll
            for (int ii = 0; ii < 8; ii++) qv[ii] = *(const u64t*)&Q[(i0 + ii) * QP + dp * 2];
            #pragma unroll
            for (int jj = 0; jj < 8; jj++) kv[jj] = *(const u64t*)&K[(j0 + jj) * QP + dp * 2];
            #pragma unroll
            for (int ii = 0; ii < 8; ii++)
                #pragma unroll
                for (int jj = 0; jj < 8; jj++)
                    fma2(acc[ii][jj], qv[ii], kv[jj]);
        }
    }
    __syncthreads();  // done reading K region before T overwrites it

    // mask, write T, row-sum partials
    #pragma unroll
    for (int ii = 0; ii < 8; ii++) {
        const int i = i0 + ii;
        float rs = 0.f;
        #pragma unroll
        for (int jj = 0; jj < 8; jj++) {
            float t = (j0 + jj <= i) ? lanesum(acc[ii][jj]) : 0.f;
            rs += t;
            sm[O_T + i * TP + j0 + jj] = t;
        }
        sm[O_DEN + i * 16 + jg] = rs;
    }
    __syncthreads();

    if (tid < CC) {
        float s = sm[O_QKP + tid];
        #pragma unroll
        for (int p = 0; p < 16; p++) s += sm[O_DEN + tid * 16 + p];
        sm[O_DNV + tid] = 1.0f / (s + 1e-10f);
    }
    __syncthreads();

    // ---- Stage B: out = T.v (packed over j) + q1.S1^T + q2.S2^T (packed over d) ----
    const int e0 = jg * 4;
    u64t a2[8][4];
    #pragma unroll
    for (int a = 0; a < 8; a++)
        #pragma unroll
        for (int b = 0; b < 4; b++) a2[a][b] = 0ull;

    #pragma unroll 1
    for (int jp = 0; jp < 64; jp++) {
        u64t tv[8], vv[4];
        #pragma unroll
        for (int ii = 0; ii < 8; ii++) tv[ii] = *(const u64t*)&sm[O_T + (i0 + ii) * TP + jp * 2];
        #pragma unroll
        for (int ee = 0; ee < 4; ee++) vv[ee] = *(const u64t*)&sm[O_VT + (e0 + ee) * VP + jp * 2];
        #pragma unroll
        for (int ii = 0; ii < 8; ii++)
            #pragma unroll
            for (int ee = 0; ee < 4; ee++)
                fma2(a2[ii][ee], tv[ii], vv[ee]);
    }
    #pragma unroll 1
    for (int m = 0; m < 2; m++) {
        const float* Q = sm + (m ? O_Q2 : O_Q1);
        const float* S = sm + (m ? O_S2 : O_S1);
        #pragma unroll 1
        for (int dp = 0; dp < 32; dp++) {
            u64t qv[8], sv[4];
            #pragma unroll
            for (int ii = 0; ii < 8; ii++) qv[ii] = *(const u64t*)&Q[(i0 + ii) * QP + dp * 2];
            #pragma unroll
            for (int ee = 0; ee < 4; ee++) sv[ee] = *(const u64t*)&S[(e0 + ee) * SP + dp * 2];
            #pragma unroll
            for (int ii = 0; ii < 8; ii++)
                #pragma unroll
                for (int ee = 0; ee < 4; ee++)
                    fma2(a2[ii][ee], qv[ii], sv[ee]);
        }
    }

    float* op = outg + cbase;
    #pragma unroll
    for (int ii = 0; ii < 8; ii++) {
        float dv = sm[O_DNV + i0 + ii];
        *(float4*)&op[(i0 + ii) * DD + e0] =
            make_float4(lanesum(a2[ii][0]) * dv, lanesum(a2[ii][1]) * dv,
                        lanesum(a2[ii][2]) * dv, lanesum(a2[ii][3]) * dv);
    }
}

// ---------------------------------------------------------------------------
extern "C" void kernel_launch(void* const* d_in, const int* in_sizes, int n_in,
                              void* d_out, int out_size) {
    const float* q  = (const float*)d_in[0];
    const float* k  = (const float*)d_in[1];
    const float* qr = (const float*)d_in[2];
    const float* kr = (const float*)d_in[3];
    const float* v  = (const float*)d_in[4];
    float* out = (float*)d_out;

    cudaFuncSetAttribute(pass1_kernel, cudaFuncAttributeMaxDynamicSharedMemorySize, 2 * CC * DD * 4);
    cudaFuncSetAttribute(pass3_kernel, cudaFuncAttributeMaxDynamicSharedMemorySize, SMEM3_BYTES);

    dim3 g1(NC, G, 2);
    pass1_kernel<<<g1, 256, 2 * CC * DD * 4>>>(k, kr, v);
    dim3 g2(G, 2);
    pass2_kernel<<<g2, 256>>>();
    dim3 g3(NC, G);
    pass3_kernel<<<g3, 256, SMEM3_BYTES>>>(q, qr, k, kr, v, out);
}

// round 5
// speedup vs baseline: 2.6829x; 2.6829x over previous
#include <cuda_runtime.h>
#include <cuda_bf16.h>
#include <stdint.h>

#define G    16
#define NSEQ 4096
#define DD   64
#define CC   128
#define NC   32

// g_S holds S^T: ST[e][d] = sum_j v[j][e] * k[j][d]  (exclusive-prefixed by pass2)
__device__ __align__(16) float g_S[2ull * G * NC * DD * DD];
__device__ __align__(16) float g_ksum[2ull * G * NC * DD];

typedef unsigned long long u64t;
__device__ __forceinline__ void fma2(u64t& d, u64t a, u64t b) {
    asm("fma.rn.f32x2 %0, %1, %2, %0;" : "+l"(d) : "l"(a), "l"(b));
}

// ---------------------------------------------------------------------------
// Pass 1: ST[e][d] = sum_j v[j][e] k[j][d];  ksum[d] = sum_j k[j][d]
// ---------------------------------------------------------------------------
__global__ __launch_bounds__(256) void pass1_kernel(const float* __restrict__ k1g,
                                                    const float* __restrict__ k2g,
                                                    const float* __restrict__ vg) {
    extern __shared__ float sm1[];
    float* as = sm1;
    float* bs = sm1 + CC * DD;
    const int c = blockIdx.x, g = blockIdx.y, m = blockIdx.z;
    const int tid = threadIdx.x;
    const size_t cbase = ((size_t)g * NSEQ + (size_t)c * CC) * DD;
    const float* vp = vg + cbase;
    const float* kp = (m ? k2g : k1g) + cbase;
    #pragma unroll
    for (int u = 0; u < 8; u++) {
        int idx = u * 256 + tid;
        ((float4*)as)[idx] = ((const float4*)vp)[idx];
        ((float4*)bs)[idx] = ((const float4*)kp)[idx];
    }
    __syncthreads();
    const int e0 = (tid >> 4) * 4, d0 = (tid & 15) * 4;
    u64t acc[4][2];
    #pragma unroll
    for (int a = 0; a < 4; a++) { acc[a][0] = 0ull; acc[a][1] = 0ull; }
    #pragma unroll 4
    for (int j = 0; j < CC; j++) {
        u64t k0 = *(const u64t*)&bs[j * DD + d0];
        u64t k1 = *(const u64t*)&bs[j * DD + d0 + 2];
        float4 vv = *(const float4*)&as[j * DD + e0];
        float ve[4] = {vv.x, vv.y, vv.z, vv.w};
        #pragma unroll
        for (int a = 0; a < 4; a++) {
            float2 bb = make_float2(ve[a], ve[a]);
            u64t bp = *reinterpret_cast<u64t*>(&bb);
            fma2(acc[a][0], bp, k0);
            fma2(acc[a][1], bp, k1);
        }
    }
    float* Sp = &g_S[(((size_t)m * G + g) * NC + c) * (size_t)(DD * DD)];
    #pragma unroll
    for (int a = 0; a < 4; a++) {
        float2 x0 = *reinterpret_cast<float2*>(&acc[a][0]);
        float2 x1 = *reinterpret_cast<float2*>(&acc[a][1]);
        *(float4*)&Sp[(e0 + a) * DD + d0] = make_float4(x0.x, x0.y, x1.x, x1.y);
    }
    if (tid < DD) {
        float s = 0.f;
        #pragma unroll 4
        for (int j = 0; j < CC; j++) s += bs[j * DD + tid];
        g_ksum[(((size_t)m * G + g) * NC + c) * DD + tid] = s;
    }
}

// ---------------------------------------------------------------------------
// Pass 2: in-place EXCLUSIVE prefix sum over chunks
// ---------------------------------------------------------------------------
__global__ __launch_bounds__(256) void pass2_kernel() {
    const int g = blockIdx.x, m = blockIdx.y, tid = threadIdx.x;
    float* base = &g_S[(((size_t)m * G + g) * NC) * (size_t)(DD * DD)];
    float run[16];
    #pragma unroll
    for (int u = 0; u < 16; u++) run[u] = 0.f;
    for (int c = 0; c < NC; c++) {
        float* p = base + (size_t)c * (DD * DD);
        #pragma unroll
        for (int u = 0; u < 16; u++) {
            int idx = u * 256 + tid;
            float t = p[idx];
            p[idx] = run[u];
            run[u] += t;
        }
    }
    if (tid < DD) {
        float r = 0.f;
        float* kb = &g_ksum[(((size_t)m * G + g) * NC) * DD];
        for (int c = 0; c < NC; c++) {
            float t = kb[c * DD + tid];
            kb[c * DD + tid] = r;
            r += t;
        }
    }
}

// ---------------------------------------------------------------------------
// Pass 3: mma.sync bf16 hi/lo. Word-offset smem map (uint32 units):
//  Q1H 0     Q1L 4608  Q2H 9216  Q2L 13824   (128 rows x 36 words, pitch 72 b16)
//  K1H 18432 K1L 23040 K2H 27648 K2L 32256   (same shape; dead after stage A)
//  TH  18432 (128 x 68 words, pitch 136 b16) TL 27136   (alias K region)
//  VTH 36864 (64 x 68)  VTL 41216
//  S1H 45568 (64 x 36)  S1L 47872  S2H 50176  S2L 52480
//  QKP 54784 (128 f32)  KP1 54912 (64 f32)  KP2 54976   end 55040 words
// ---------------------------------------------------------------------------
#define W_Q1H 0
#define W_Q1L 4608
#define W_Q2H 9216
#define W_Q2L 13824
#define W_K1H 18432
#define W_K1L 23040
#define W_K2H 27648
#define W_K2L 32256
#define W_TH  18432
#define W_TL  27136
#define W_VTH 36864
#define W_VTL 41216
#define W_S1H 45568
#define W_S1L 47872
#define W_S2H 50176
#define W_S2L 52480
#define W_QKP 54784
#define W_KP1 54912
#define W_KP2 54976
#define SMEM3_BYTES (55040 * 4)

__device__ __forceinline__ void mma_bf16(float* c, uint32_t a0, uint32_t a1, uint32_t a2, uint32_t a3,
                                         uint32_t b0, uint32_t b1) {
    asm("mma.sync.aligned.m16n8k16.row.col.f32.bf16.bf16.f32 "
        "{%0,%1,%2,%3},{%4,%5,%6,%7},{%8,%9},{%0,%1,%2,%3};"
        : "+f"(c[0]), "+f"(c[1]), "+f"(c[2]), "+f"(c[3])
        : "r"(a0), "r"(a1), "r"(a2), "r"(a3), "r"(b0), "r"(b1));
}
__device__ __forceinline__ void split2(float x, float y, uint32_t& hw, uint32_t& lw) {
    __nv_bfloat16 hx = __float2bfloat16(x), hy = __float2bfloat16(y);
    float rx = x - __bfloat162float(hx), ry = y - __bfloat162float(hy);
    __nv_bfloat16 lx = __float2bfloat16(rx), ly = __float2bfloat16(ry);
    hw = (uint32_t)*(uint16_t*)&hx | ((uint32_t)*(uint16_t*)&hy << 16);
    lw = (uint32_t)*(uint16_t*)&lx | ((uint32_t)*(uint16_t*)&ly << 16);
}

__global__ __launch_bounds__(256) void pass3_kernel(const float* __restrict__ q1g,
                                                    const float* __restrict__ q2g,
                                                    const float* __restrict__ k1g,
                                                    const float* __restrict__ k2g,
                                                    const float* __restrict__ vg,
                                                    float* __restrict__ outg) {
    extern __shared__ uint32_t smw[];
    const int c = blockIdx.x, g = blockIdx.y, tid = threadIdx.x;
    const int w = tid >> 5, lane = tid & 31;
    const int gq = lane >> 2, tq = lane & 3;
    const size_t cbase = ((size_t)g * NSEQ + (size_t)c * CC) * DD;

    float* QKPf = (float*)(smw + W_QKP);
    float* KP1f = (float*)(smw + W_KP1);
    float* KP2f = (float*)(smw + W_KP2);

    // ---- phase 1: convert inputs to bf16 hi/lo tiles ----
    {
        const float2* q1p = (const float2*)(q1g + cbase);
        const float2* q2p = (const float2*)(q2g + cbase);
        const float2* k1p = (const float2*)(k1g + cbase);
        const float2* k2p = (const float2*)(k2g + cbase);
        #pragma unroll
        for (int it = 0; it < 16; it++) {
            int idx = it * 256 + tid;          // 4096 d-pairs
            int off = (idx >> 5) * 36 + (idx & 31);
            uint32_t hw, lw; float2 xv;
            xv = q1p[idx]; split2(xv.x, xv.y, hw, lw); smw[W_Q1H + off] = hw; smw[W_Q1L + off] = lw;
            xv = q2p[idx]; split2(xv.x, xv.y, hw, lw); smw[W_Q2H + off] = hw; smw[W_Q2L + off] = lw;
            xv = k1p[idx]; split2(xv.x, xv.y, hw, lw); smw[W_K1H + off] = hw; smw[W_K1L + off] = lw;
            xv = k2p[idx]; split2(xv.x, xv.y, hw, lw); smw[W_K2H + off] = hw; smw[W_K2L + off] = lw;
        }
        uint16_t* vth = (uint16_t*)(smw + W_VTH);
        uint16_t* vtl = (uint16_t*)(smw + W_VTL);
        const float* vp = vg + cbase;
        #pragma unroll
        for (int it = 0; it < 32; it++) {
            int idx = it * 256 + tid;          // v[j][e] -> VT[e][j]
            int j = idx >> 6, e = idx & 63;
            float x = vp[idx];
            __nv_bfloat16 hb = __float2bfloat16(x);
            float r = x - __bfloat162float(hb);
            __nv_bfloat16 lb = __float2bfloat16(r);
            vth[e * 136 + j] = *(uint16_t*)&hb;
            vtl[e * 136 + j] = *(uint16_t*)&lb;
        }
        const float2* s1p = (const float2*)&g_S[(((size_t)0 * G + g) * NC + c) * (size_t)(DD * DD)];
        const float2* s2p = (const float2*)&g_S[(((size_t)1 * G + g) * NC + c) * (size_t)(DD * DD)];
        #pragma unroll
        for (int it = 0; it < 8; it++) {
            int idx = it * 256 + tid;          // 2048 d-pairs
            int off = (idx >> 5) * 36 + (idx & 31);
            uint32_t hw, lw; float2 xv;
            xv = s1p[idx]; split2(xv.x, xv.y, hw, lw); smw[W_S1H + off] = hw; smw[W_S1L + off] = lw;
            xv = s2p[idx]; split2(xv.x, xv.y, hw, lw); smw[W_S2H + off] = hw; smw[W_S2L + off] = lw;
        }
        if (tid < DD) {
            KP1f[tid] = g_ksum[(((size_t)0 * G + g) * NC + c) * DD + tid];
            KP2f[tid] = g_ksum[(((size_t)1 * G + g) * NC + c) * DD + tid];
        }
    }
    __syncthreads();

    // qkpre denominator term (f32 exact), overlaps other warps starting MMA
    if (tid < CC) {
        const float* qa = q1g + cbase + (size_t)tid * DD;
        const float* qb = q2g + cbase + (size_t)tid * DD;
        float a = 0.f;
        #pragma unroll 8
        for (int d = 0; d < DD; d++) a += qa[d] * KP1f[d] + qb[d] * KP2f[d];
        QKPf[tid] = a;
    }

    const int band = w * 16;

    // ---- Stage A: T = q1 k1^T + q2 k2^T ----
    float accA[16][4];
    #pragma unroll
    for (int t = 0; t < 16; t++)
        #pragma unroll
        for (int u = 0; u < 4; u++) accA[t][u] = 0.f;

    #pragma unroll 1
    for (int m = 0; m < 2; m++) {
        const uint32_t* QH = smw + (m ? W_Q2H : W_Q1H);
        const uint32_t* QL = smw + (m ? W_Q2L : W_Q1L);
        const uint32_t* KH = smw + (m ? W_K2H : W_K1H);
        const uint32_t* KL = smw + (m ? W_K2L : W_K1L);
        #pragma unroll
        for (int kk = 0; kk < 4; kk++) {
            int ab = (band + gq) * 36 + kk * 8 + tq;
            uint32_t ah0 = QH[ab], ah1 = QH[ab + 288], ah2 = QH[ab + 4], ah3 = QH[ab + 292];
            uint32_t al0 = QL[ab], al1 = QL[ab + 288], al2 = QL[ab + 4], al3 = QL[ab + 292];
            #pragma unroll
            for (int nt = 0; nt < 16; nt++) {
                int bb = (nt * 8 + gq) * 36 + kk * 8 + tq;
                uint32_t bh0 = KH[bb], bh1 = KH[bb + 4];
                mma_bf16(accA[nt], ah0, ah1, ah2, ah3, bh0, bh1);
                mma_bf16(accA[nt], al0, al1, al2, al3, bh0, bh1);
                uint32_t bl0 = KL[bb], bl1 = KL[bb + 4];
                mma_bf16(accA[nt], ah0, ah1, ah2, ah3, bl0, bl1);
            }
        }
    }
    __syncthreads();   // all K reads done (T aliases K); QKP visible

    // ---- epilogue A: mask, row sums, split T -> bf16 hi/lo in smem ----
    const int i0 = band + gq, i1 = i0 + 8;
    float rs0 = 0.f, rs1 = 0.f;
    #pragma unroll
    for (int nt = 0; nt < 16; nt++) {
        int jb = nt * 8 + tq * 2;
        float t00 = (jb <= i0) ? accA[nt][0] : 0.f;
        float t01 = (jb + 1 <= i0) ? accA[nt][1] : 0.f;
        float t10 = (jb <= i1) ? accA[nt][2] : 0.f;
        float t11 = (jb + 1 <= i1) ? accA[nt][3] : 0.f;
        rs0 += t00 + t01; rs1 += t10 + t11;
        uint32_t hw, lw;
        split2(t00, t01, hw, lw);
        smw[W_TH + i0 * 68 + nt * 4 + tq] = hw;
        smw[W_TL + i0 * 68 + nt * 4 + tq] = lw;
        split2(t10, t11, hw, lw);
        smw[W_TH + i1 * 68 + nt * 4 + tq] = hw;
        smw[W_TL + i1 * 68 + nt * 4 + tq] = lw;
    }
    rs0 += __shfl_xor_sync(0xFFFFFFFFu, rs0, 1);
    rs0 += __shfl_xor_sync(0xFFFFFFFFu, rs0, 2);
    rs1 += __shfl_xor_sync(0xFFFFFFFFu, rs1, 1);
    rs1 += __shfl_xor_sync(0xFFFFFFFFu, rs1, 2);
    __syncwarp();      // T tile (warp-local) visible across lanes

    // ---- Stage B: out = T v + q1 S1 + q2 S2 ----
    float accB[8][4];
    #pragma unroll
    for (int t = 0; t < 8; t++)
        #pragma unroll
        for (int u = 0; u < 4; u++) accB[t][u] = 0.f;

    #pragma unroll 1
    for (int kk = 0; kk < 8; kk++) {       // k = j over 128
        int ab = (band + gq) * 68 + kk * 8 + tq;
        uint32_t ah0 = smw[W_TH + ab], ah1 = smw[W_TH + ab + 544], ah2 = smw[W_TH + ab + 4], ah3 = smw[W_TH + ab + 548];
        uint32_t al0 = smw[W_TL + ab], al1 = smw[W_TL + ab + 544], al2 = smw[W_TL + ab + 4], al3 = smw[W_TL + ab + 548];
        #pragma unroll
        for (int nt = 0; nt < 8; nt++) {
            int bb = (nt * 8 + gq) * 68 + kk * 8 + tq;
            uint32_t bh0 = smw[W_VTH + bb], bh1 = smw[W_VTH + bb + 4];
            mma_bf16(accB[nt], ah0, ah1, ah2, ah3, bh0, bh1);
            mma_bf16(accB[nt], al0, al1, al2, al3, bh0, bh1);
            uint32_t bl0 = smw[W_VTL + bb], bl1 = smw[W_VTL + bb + 4];
            mma_bf16(accB[nt], ah0, ah1, ah2, ah3, bl0, bl1);
        }
    }
    #pragma unroll 1
    for (int m = 0; m < 2; m++) {          // k = d over 64
        const uint32_t* QH = smw + (m ? W_Q2H : W_Q1H);
        const uint32_t* QL = smw + (m ? W_Q2L : W_Q1L);
        const uint32_t* SH = smw + (m ? W_S2H : W_S1H);
        const uint32_t* SL = smw + (m ? W_S2L : W_S1L);
        #pragma unroll
        for (int kk = 0; kk < 4; kk++) {
            int ab = (band + gq) * 36 + kk * 8 + tq;
            uint32_t ah0 = QH[ab], ah1 = QH[ab + 288], ah2 = QH[ab + 4], ah3 = QH[ab + 292];
            uint32_t al0 = QL[ab], al1 = QL[ab + 288], al2 = QL[ab + 4], al3 = QL[ab + 292];
            #pragma unroll
            for (int nt = 0; nt < 8; nt++) {
                int bb = (nt * 8 + gq) * 36 + kk * 8 + tq;
                uint32_t bh0 = SH[bb], bh1 = SH[bb + 4];
                mma_bf16(accB[nt], ah0, ah1, ah2, ah3, bh0, bh1);
                mma_bf16(accB[nt], al0, al1, al2, al3, bh0, bh1);
                uint32_t bl0 = SL[bb], bl1 = SL[bb + 4];
                mma_bf16(accB[nt], ah0, ah1, ah2, ah3, bl0, bl1);
            }
        }
    }

    // ---- epilogue B: divide by denominator, store ----
    float dnv0 = 1.0f / (rs0 + QKPf[i0] + 1e-10f);
    float dnv1 = 1.0f / (rs1 + QKPf[i1] + 1e-10f);
    float* op = outg + cbase;
    #pragma unroll
    for (int nt = 0; nt < 8; nt++) {
        int e = nt * 8 + tq * 2;
        *(float2*)&op[i0 * DD + e] = make_float2(accB[nt][0] * dnv0, accB[nt][1] * dnv0);
        *(float2*)&op[i1 * DD + e] = make_float2(accB[nt][2] * dnv1, accB[nt][3] * dnv1);
    }
}

// ---------------------------------------------------------------------------
extern "C" void kernel_launch(void* const* d_in, const int* in_sizes, int n_in,
                              void* d_out, int out_size) {
    const float* q  = (const float*)d_in[0];
    const float* k  = (const float*)d_in[1];
    const float* qr = (const float*)d_in[2];
    const float* kr = (const float*)d_in[3];
    const float* v  = (const float*)d_in[4];
    float* out = (float*)d_out;

    cudaFuncSetAttribute(pass1_kernel, cudaFuncAttributeMaxDynamicSharedMemorySize, 2 * CC * DD * 4);
    cudaFuncSetAttribute(pass3_kernel, cudaFuncAttributeMaxDynamicSharedMemorySize, SMEM3_BYTES);

    dim3 g1(NC, G, 2);
    pass1_kernel<<<g1, 256, 2 * CC * DD * 4>>>(k, kr, v);
    dim3 g2(G, 2);
    pass2_kernel<<<g2, 256>>>();
    dim3 g3(NC, G);
    pass3_kernel<<<g3, 256, SMEM3_BYTES>>>(q, qr, k, kr, v, out);
}

// round 6
// speedup vs baseline: 2.9402x; 1.0959x over previous
#include <cuda_runtime.h>
#include <cuda_bf16.h>
#include <stdint.h>

#define G    16
#define NSEQ 4096
#define DD   64
#define CC   128
#define NC   32

// g_S holds S^T: ST[e][d] = sum_j v[j][e]*k[j][d], exclusive-prefixed by pass2
__device__ __align__(16) float g_S[2ull * G * NC * DD * DD];
__device__ __align__(16) float g_ksum[2ull * G * NC * DD];

__device__ __forceinline__ uint32_t smem_u32(const void* p) {
    uint32_t a;
    asm("{ .reg .u64 t; cvta.to.shared.u64 t, %1; cvt.u32.u64 %0, t; }" : "=r"(a) : "l"(p));
    return a;
}
#define LDM4(r0, r1, r2, r3, addr) \
    asm volatile("ldmatrix.sync.aligned.m8n8.x4.shared.b16 {%0,%1,%2,%3}, [%4];" \
                 : "=r"(r0), "=r"(r1), "=r"(r2), "=r"(r3) : "r"(addr))
__device__ __forceinline__ void mma_bf16(float* c, uint32_t a0, uint32_t a1, uint32_t a2, uint32_t a3,
                                         uint32_t b0, uint32_t b1) {
    asm("mma.sync.aligned.m16n8k16.row.col.f32.bf16.bf16.f32 "
        "{%0,%1,%2,%3},{%4,%5,%6,%7},{%8,%9},{%0,%1,%2,%3};"
        : "+f"(c[0]), "+f"(c[1]), "+f"(c[2]), "+f"(c[3])
        : "r"(a0), "r"(a1), "r"(a2), "r"(a3), "r"(b0), "r"(b1));
}
__device__ __forceinline__ void splitf(float x, uint16_t& h, uint16_t& l) {
    __nv_bfloat16 hb = __float2bfloat16(x);
    float r = x - __bfloat162float(hb);
    __nv_bfloat16 lb = __float2bfloat16(r);
    h = *(uint16_t*)&hb; l = *(uint16_t*)&lb;
}
__device__ __forceinline__ void split2(float x, float y, uint32_t& hw, uint32_t& lw) {
    uint16_t hx, lx, hy, ly;
    splitf(x, hx, lx); splitf(y, hy, ly);
    hw = (uint32_t)hx | ((uint32_t)hy << 16);
    lw = (uint32_t)lx | ((uint32_t)ly << 16);
}
__device__ __forceinline__ float bfls(uint32_t u) {
    __nv_bfloat162 b = *reinterpret_cast<__nv_bfloat162*>(&u);
    return __bfloat162float(b.x) + __bfloat162float(b.y);
}

// ===========================================================================
// Pass 1: ST_m[e][d] = sum_j v[j][e] k_m[j][d] for m=0,1; ksum_m[d].
// Tiles (word offsets, pitch 68 words = 272B): VTH 0, VTL 4352,
//   K1TH 8704, K1TL 13056, K2TH 17408, K2TL 21760.  smem = 26112 w = 104448 B
// ===========================================================================
#define P1_SMEM (26112 * 4)
__global__ __launch_bounds__(256) void pass1_kernel(const float* __restrict__ k1g,
                                                    const float* __restrict__ k2g,
                                                    const float* __restrict__ vg) {
    extern __shared__ uint32_t smw[];
    const int c = blockIdx.x, g = blockIdx.y;
    const int tid = threadIdx.x, w = tid >> 5, lane = tid & 31;
    const int gq = lane >> 2, tq = lane & 3;
    const size_t cbase = ((size_t)g * NSEQ + (size_t)c * CC) * DD;

    // stage transposed bf16 hi/lo tiles
    {
        uint16_t* vh = (uint16_t*)(smw);
        uint16_t* vl = (uint16_t*)(smw + 4352);
        uint16_t* k1h = (uint16_t*)(smw + 8704);
        uint16_t* k1l = (uint16_t*)(smw + 13056);
        uint16_t* k2h = (uint16_t*)(smw + 17408);
        uint16_t* k2l = (uint16_t*)(smw + 21760);
        const float2* vp = (const float2*)(vg + cbase);
        const float2* k1p = (const float2*)(k1g + cbase);
        const float2* k2p = (const float2*)(k2g + cbase);
        #pragma unroll
        for (int it = 0; it < 16; it++) {
            int idx = it * 256 + tid;
            int j = idx >> 5, e = (idx & 31) * 2;
            float2 xv; uint16_t h0, l0, h1, l1;
            xv = vp[idx]; splitf(xv.x, h0, l0); splitf(xv.y, h1, l1);
            vh[e * 136 + j] = h0; vh[(e + 1) * 136 + j] = h1;
            vl[e * 136 + j] = l0; vl[(e + 1) * 136 + j] = l1;
            xv = k1p[idx]; splitf(xv.x, h0, l0); splitf(xv.y, h1, l1);
            k1h[e * 136 + j] = h0; k1h[(e + 1) * 136 + j] = h1;
            k1l[e * 136 + j] = l0; k1l[(e + 1) * 136 + j] = l1;
            xv = k2p[idx]; splitf(xv.x, h0, l0); splitf(xv.y, h1, l1);
            k2h[e * 136 + j] = h0; k2h[(e + 1) * 136 + j] = h1;
            k2l[e * 136 + j] = l0; k2l[(e + 1) * 136 + j] = l1;
        }
    }
    __syncthreads();

    // ksum from hi+lo smem (error ~2^-17, negligible)
    if (tid < 128) {
        int m = tid >> 6, d = tid & 63;
        const uint32_t* kh = smw + (m ? 17408 : 8704) + d * 68;
        const uint32_t* kl = smw + (m ? 21760 : 13056) + d * 68;
        float s = 0.f;
        #pragma unroll 8
        for (int wi = 0; wi < 64; wi++) s += bfls(kh[wi]) + bfls(kl[wi]);
        g_ksum[(((size_t)m * G + g) * NC + c) * DD + d] = s;
    }

    const int band = (w >> 1) * 16, nh = w & 1;
    const uint32_t sbase = smem_u32(smw);
    const uint32_t laneoff = ((lane & 7) + ((lane >> 3) & 1) * 8) * 272 + ((lane >> 4) & 1) * 16;
    const uint32_t avh = sbase + band * 272 + laneoff;
    const uint32_t avl = avh + 17408;

    float accP[2][4][4];
    #pragma unroll
    for (int m = 0; m < 2; m++)
        #pragma unroll
        for (int t = 0; t < 4; t++)
            #pragma unroll
            for (int u = 0; u < 4; u++) accP[m][t][u] = 0.f;

    #pragma unroll
    for (int m = 0; m < 2; m++) {
        uint32_t bh0a = sbase + (m ? 69632u : 34816u) + (uint32_t)nh * 32 * 272 + laneoff;
        uint32_t bl0a = bh0a + 17408;
        #pragma unroll 1
        for (int kk = 0; kk < 8; kk++) {
            uint32_t ah0, ah1, ah2, ah3, al0, al1, al2, al3;
            LDM4(ah0, ah1, ah2, ah3, avh + kk * 32);
            LDM4(al0, al1, al2, al3, avl + kk * 32);
            #pragma unroll
            for (int p = 0; p < 2; p++) {
                uint32_t bh0, bh1, bh2, bh3, bl0, bl1, bl2, bl3;
                LDM4(bh0, bh1, bh2, bh3, bh0a + p * 4352 + kk * 32);
                LDM4(bl0, bl1, bl2, bl3, bl0a + p * 4352 + kk * 32);
                mma_bf16(accP[m][2 * p], ah0, ah1, ah2, ah3, bh0, bh2);
                mma_bf16(accP[m][2 * p], al0, al1, al2, al3, bh0, bh2);
                mma_bf16(accP[m][2 * p], ah0, ah1, ah2, ah3, bl0, bl2);
                mma_bf16(accP[m][2 * p + 1], ah0, ah1, ah2, ah3, bh1, bh3);
                mma_bf16(accP[m][2 * p + 1], al0, al1, al2, al3, bh1, bh3);
                mma_bf16(accP[m][2 * p + 1], ah0, ah1, ah2, ah3, bl1, bl3);
            }
        }
    }
    #pragma unroll
    for (int m = 0; m < 2; m++) {
        float* Sp = &g_S[(((size_t)m * G + g) * NC + c) * (size_t)(DD * DD)];
        #pragma unroll
        for (int t = 0; t < 4; t++) {
            int d0 = nh * 32 + t * 8 + tq * 2;
            int e0 = band + gq;
            *(float2*)&Sp[e0 * DD + d0] = make_float2(accP[m][t][0], accP[m][t][1]);
            *(float2*)&Sp[(e0 + 8) * DD + d0] = make_float2(accP[m][t][2], accP[m][t][3]);
        }
    }
}

// ===========================================================================
// Pass 2: exclusive prefix sum over chunks; 64 CTAs, float4, prefetch pipeline
// ===========================================================================
__global__ __launch_bounds__(256) void pass2_kernel() {
    const int g = blockIdx.x, m = blockIdx.y, h = blockIdx.z, tid = threadIdx.x;
    float* base = &g_S[(((size_t)m * G + g) * NC) * (size_t)(DD * DD)] + h * 2048;
    float4 run0 = make_float4(0.f, 0.f, 0.f, 0.f), run1 = run0;
    const float4* c0 = (const float4*)base;
    float4 cur0 = c0[tid], cur1 = c0[tid + 256];
    #pragma unroll 1
    for (int c = 0; c < NC; c++) {
        float4 nxt0, nxt1;
        if (c + 1 < NC) {
            const float4* pn = (const float4*)(base + (size_t)(c + 1) * (DD * DD));
            nxt0 = pn[tid]; nxt1 = pn[tid + 256];
        }
        float4* p = (float4*)(base + (size_t)c * (DD * DD));
        p[tid] = run0; p[tid + 256] = run1;
        run0.x += cur0.x; run0.y += cur0.y; run0.z += cur0.z; run0.w += cur0.w;
        run1.x += cur1.x; run1.y += cur1.y; run1.z += cur1.z; run1.w += cur1.w;
        cur0 = nxt0; cur1 = nxt1;
    }
    if (h == 0 && tid < DD) {
        float* kb = &g_ksum[(((size_t)m * G + g) * NC) * DD];
        float r = 0.f, cu = kb[tid];
        #pragma unroll 1
        for (int c = 0; c < NC; c++) {
            float nx = (c + 1 < NC) ? kb[(c + 1) * DD + tid] : 0.f;
            kb[c * DD + tid] = r;
            r += cu; cu = nx;
        }
    }
}

// ===========================================================================
// Pass 3. Concatenated-map tiles, pitch 68 words (272B). Byte offsets:
//  QH 0  QL 34816  KH 69632  KL 104448  VTH 139264  VTL 156672
//  SH 174080  SL 191488  QKP 208896  KP 209408   total 209920 B
// ===========================================================================
#define B_QL  34816u
#define B_KH  69632u
#define B_KL  104448u
#define B_VTH 139264u
#define B_VTL 156672u
#define B_SH  174080u
#define B_SL  191488u
#define W_QL  8704
#define W_KH  17408
#define W_KL  26112
#define W_VTH 34816
#define W_VTL 39168
#define W_SH  43520
#define W_SL  47872
#define W_QKP 52224
#define W_KP  52352
#define SMEM3 (52480 * 4)

__global__ __launch_bounds__(256) void pass3_kernel(const float* __restrict__ q1g,
                                                    const float* __restrict__ q2g,
                                                    const float* __restrict__ k1g,
                                                    const float* __restrict__ k2g,
                                                    const float* __restrict__ vg,
                                                    float* __restrict__ outg) {
    extern __shared__ uint32_t smw[];
    const int c = blockIdx.x, g = blockIdx.y, tid = threadIdx.x;
    const int w = tid >> 5, lane = tid & 31;
    const int gq = lane >> 2, tq = lane & 3;
    const size_t cbase = ((size_t)g * NSEQ + (size_t)c * CC) * DD;
    float* QKPf = (float*)(smw + W_QKP);
    float* KPf  = (float*)(smw + W_KP);

    // ---- stage tiles ----
    {
        const float2* q1p = (const float2*)(q1g + cbase);
        const float2* q2p = (const float2*)(q2g + cbase);
        const float2* k1p = (const float2*)(k1g + cbase);
        const float2* k2p = (const float2*)(k2g + cbase);
        #pragma unroll
        for (int it = 0; it < 16; it++) {
            int idx = it * 256 + tid;
            int off = (idx >> 5) * 68 + (idx & 31);
            float2 xv; uint32_t hw, lw;
            xv = q1p[idx]; split2(xv.x, xv.y, hw, lw); smw[off] = hw; smw[W_QL + off] = lw;
            xv = q2p[idx]; split2(xv.x, xv.y, hw, lw); smw[off + 32] = hw; smw[W_QL + off + 32] = lw;
            xv = k1p[idx]; split2(xv.x, xv.y, hw, lw); smw[W_KH + off] = hw; smw[W_KL + off] = lw;
            xv = k2p[idx]; split2(xv.x, xv.y, hw, lw); smw[W_KH + off + 32] = hw; smw[W_KL + off + 32] = lw;
        }
        uint16_t* vth = (uint16_t*)(smw + W_VTH);
        uint16_t* vtl = (uint16_t*)(smw + W_VTL);
        const float2* vp = (const float2*)(vg + cbase);
        #pragma unroll
        for (int it = 0; it < 16; it++) {
            int idx = it * 256 + tid;
            int j = idx >> 5, e = (idx & 31) * 2;
            float2 xv = vp[idx]; uint16_t h0, l0, h1, l1;
            splitf(xv.x, h0, l0); splitf(xv.y, h1, l1);
            vth[e * 136 + j] = h0; vth[(e + 1) * 136 + j] = h1;
            vtl[e * 136 + j] = l0; vtl[(e + 1) * 136 + j] = l1;
        }
        const float2* s1p = (const float2*)&g_S[(((size_t)0 * G + g) * NC + c) * (size_t)(DD * DD)];
        const float2* s2p = (const float2*)&g_S[(((size_t)1 * G + g) * NC + c) * (size_t)(DD * DD)];
        #pragma unroll
        for (int it = 0; it < 8; it++) {
            int idx = it * 256 + tid;
            int off = (idx >> 5) * 68 + (idx & 31);
            float2 xv; uint32_t hw, lw;
            xv = s1p[idx]; split2(xv.x, xv.y, hw, lw); smw[W_SH + off] = hw; smw[W_SL + off] = lw;
            xv = s2p[idx]; split2(xv.x, xv.y, hw, lw); smw[W_SH + off + 32] = hw; smw[W_SL + off + 32] = lw;
        }
        if (tid < DD) {
            KPf[tid]      = g_ksum[(((size_t)0 * G + g) * NC + c) * DD + tid];
            KPf[64 + tid] = g_ksum[(((size_t)1 * G + g) * NC + c) * DD + tid];
        }
    }
    __syncthreads();

    // qkpre (f32 exact, overlaps MMA warps)
    if (tid < CC) {
        const float* qa = q1g + cbase + (size_t)tid * DD;
        const float* qb = q2g + cbase + (size_t)tid * DD;
        float a = 0.f;
        #pragma unroll 8
        for (int d = 0; d < DD; d++) a += qa[d] * KPf[d] + qb[d] * KPf[64 + d];
        QKPf[tid] = a;
    }

    const int band = w * 16;
    const uint32_t sbase = smem_u32(smw);
    const uint32_t laneoff = ((lane & 7) + ((lane >> 3) & 1) * 8) * 272 + ((lane >> 4) & 1) * 16;
    const uint32_t aqh = sbase + band * 272 + laneoff;
    const uint32_t aql = aqh + B_QL;

    // ---- Stage A: T = Qcat Kcat^T ----
    float accA[16][4];
    #pragma unroll
    for (int t = 0; t < 16; t++)
        #pragma unroll
        for (int u = 0; u < 4; u++) accA[t][u] = 0.f;
    {
        const uint32_t bkh = sbase + B_KH + laneoff;
        const uint32_t bkl = sbase + B_KL + laneoff;
        #pragma unroll 1
        for (int kk = 0; kk < 8; kk++) {
            uint32_t ah0, ah1, ah2, ah3, al0, al1, al2, al3;
            LDM4(ah0, ah1, ah2, ah3, aqh + kk * 32);
            LDM4(al0, al1, al2, al3, aql + kk * 32);
            #pragma unroll
            for (int p = 0; p < 8; p++) {
                uint32_t bh0, bh1, bh2, bh3, bl0, bl1, bl2, bl3;
                LDM4(bh0, bh1, bh2, bh3, bkh + p * 4352 + kk * 32);
                LDM4(bl0, bl1, bl2, bl3, bkl + p * 4352 + kk * 32);
                mma_bf16(accA[2 * p], ah0, ah1, ah2, ah3, bh0, bh2);
                mma_bf16(accA[2 * p], al0, al1, al2, al3, bh0, bh2);
                mma_bf16(accA[2 * p], ah0, ah1, ah2, ah3, bl0, bl2);
                mma_bf16(accA[2 * p + 1], ah0, ah1, ah2, ah3, bh1, bh3);
                mma_bf16(accA[2 * p + 1], al0, al1, al2, al3, bh1, bh3);
                mma_bf16(accA[2 * p + 1], ah0, ah1, ah2, ah3, bl1, bl3);
            }
        }
    }

    // ---- epilogue A: mask, row sums, pack T into register A-fragments ----
    const int i0 = band + gq, i1 = i0 + 8;
    uint32_t thA[8][4], tlA[8][4];
    float rs0 = 0.f, rs1 = 0.f;
    #pragma unroll
    for (int kk = 0; kk < 8; kk++) {
        int ce = kk * 16 + tq * 2, co = ce + 8;
        float e00 = (ce <= i0) ? accA[2 * kk][0] : 0.f;
        float e01 = (ce + 1 <= i0) ? accA[2 * kk][1] : 0.f;
        float e10 = (ce <= i1) ? accA[2 * kk][2] : 0.f;
        float e11 = (ce + 1 <= i1) ? accA[2 * kk][3] : 0.f;
        float o00 = (co <= i0) ? accA[2 * kk + 1][0] : 0.f;
        float o01 = (co + 1 <= i0) ? accA[2 * kk + 1][1] : 0.f;
        float o10 = (co <= i1) ? accA[2 * kk + 1][2] : 0.f;
        float o11 = (co + 1 <= i1) ? accA[2 * kk + 1][3] : 0.f;
        rs0 += e00 + e01 + o00 + o01;
        rs1 += e10 + e11 + o10 + o11;
        split2(e00, e01, thA[kk][0], tlA[kk][0]);
        split2(e10, e11, thA[kk][1], tlA[kk][1]);
        split2(o00, o01, thA[kk][2], tlA[kk][2]);
        split2(o10, o11, thA[kk][3], tlA[kk][3]);
    }
    rs0 += __shfl_xor_sync(0xFFFFFFFFu, rs0, 1);
    rs0 += __shfl_xor_sync(0xFFFFFFFFu, rs0, 2);
    rs1 += __shfl_xor_sync(0xFFFFFFFFu, rs1, 1);
    rs1 += __shfl_xor_sync(0xFFFFFFFFu, rs1, 2);
    __syncthreads();   // QKPf visibility

    // ---- Stage B: out = T v + Qcat Scat^T ----
    float accB[8][4];
    #pragma unroll
    for (int t = 0; t < 8; t++)
        #pragma unroll
        for (int u = 0; u < 4; u++) accB[t][u] = 0.f;
    {
        const uint32_t bvh = sbase + B_VTH + laneoff;
        const uint32_t bvl = sbase + B_VTL + laneoff;
        #pragma unroll
        for (int kk = 0; kk < 8; kk++) {
            #pragma unroll
            for (int p = 0; p < 4; p++) {
                uint32_t bh0, bh1, bh2, bh3, bl0, bl1, bl2, bl3;
                LDM4(bh0, bh1, bh2, bh3, bvh + p * 4352 + kk * 32);
                LDM4(bl0, bl1, bl2, bl3, bvl + p * 4352 + kk * 32);
                mma_bf16(accB[2 * p], thA[kk][0], thA[kk][1], thA[kk][2], thA[kk][3], bh0, bh2);
                mma_bf16(accB[2 * p], tlA[kk][0], tlA[kk][1], tlA[kk][2], tlA[kk][3], bh0, bh2);
                mma_bf16(accB[2 * p], thA[kk][0], thA[kk][1], thA[kk][2], thA[kk][3], bl0, bl2);
                mma_bf16(accB[2 * p + 1], thA[kk][0], thA[kk][1], thA[kk][2], thA[kk][3], bh1, bh3);
                mma_bf16(accB[2 * p + 1], tlA[kk][0], tlA[kk][1], tlA[kk][2], tlA[kk][3], bh1, bh3);
                mma_bf16(accB[2 * p + 1], thA[kk][0], thA[kk][1], thA[kk][2], thA[kk][3], bl1, bl3);
            }
        }
        const uint32_t bsh = sbase + B_SH + laneoff;
        const uint32_t bsl = sbase + B_SL + laneoff;
        #pragma unroll 1
        for (int kk = 0; kk < 8; kk++) {
            uint32_t ah0, ah1, ah2, ah3, al0, al1, al2, al3;
            LDM4(ah0, ah1, ah2, ah3, aqh + kk * 32);
            LDM4(al0, al1, al2, al3, aql + kk * 32);
            #pragma unroll
            for (int p = 0; p < 4; p++) {
                uint32_t bh0, bh1, bh2, bh3, bl0, bl1, bl2, bl3;
                LDM4(bh0, bh1, bh2, bh3, bsh + p * 4352 + kk * 32);
                LDM4(bl0, bl1, bl2, bl3, bsl + p * 4352 + kk * 32);
                mma_bf16(accB[2 * p], ah0, ah1, ah2, ah3, bh0, bh2);
                mma_bf16(accB[2 * p], al0, al1, al2, al3, bh0, bh2);
                mma_bf16(accB[2 * p], ah0, ah1, ah2, ah3, bl0, bl2);
                mma_bf16(accB[2 * p + 1], ah0, ah1, ah2, ah3, bh1, bh3);
                mma_bf16(accB[2 * p + 1], al0, al1, al2, al3, bh1, bh3);
                mma_bf16(accB[2 * p + 1], ah0, ah1, ah2, ah3, bl1, bl3);
            }
        }
    }

    // ---- epilogue B ----
    float dnv0 = 1.0f / (rs0 + QKPf[i0] + 1e-10f);
    float dnv1 = 1.0f / (rs1 + QKPf[i1] + 1e-10f);
    float* op = outg + cbase;
    #pragma unroll
    for (int t = 0; t < 8; t++) {
        int e = t * 8 + tq * 2;
        *(float2*)&op[i0 * DD + e] = make_float2(accB[t][0] * dnv0, accB[t][1] * dnv0);
        *(float2*)&op[i1 * DD + e] = make_float2(accB[t][2] * dnv1, accB[t][3] * dnv1);
    }
}

// ---------------------------------------------------------------------------
extern "C" void kernel_launch(void* const* d_in, const int* in_sizes, int n_in,
                              void* d_out, int out_size) {
    const float* q  = (const float*)d_in[0];
    const float* k  = (const float*)d_in[1];
    const float* qr = (const float*)d_in[2];
    const float* kr = (const float*)d_in[3];
    const float* v  = (const float*)d_in[4];
    float* out = (float*)d_out;

    cudaFuncSetAttribute(pass1_kernel, cudaFuncAttributeMaxDynamicSharedMemorySize, P1_SMEM);
    cudaFuncSetAttribute(pass3_kernel, cudaFuncAttributeMaxDynamicSharedMemorySize, SMEM3);

    dim3 g1(NC, G);
    pass1_kernel<<<g1, 256, P1_SMEM>>>(k, kr, v);
    dim3 g2(G, 2, 2);
    pass2_kernel<<<g2, 256>>>();
    dim3 g3(NC, G);
    pass3_kernel<<<g3, 256, SMEM3>>>(q, qr, k, kr, v, out);
}

// round 7
// speedup vs baseline: 3.3835x; 1.1508x over previous
#include <cuda_runtime.h>
#include <cuda_bf16.h>
#include <stdint.h>

#define G    16
#define NSEQ 4096
#define DD   64
#define CC   128
#define NC   32

// g_S holds S^T: ST[e][d] = sum_j v[j][e]*k[j][d], exclusive-prefixed by pass2
__device__ __align__(16) float g_S[2ull * G * NC * DD * DD];
__device__ __align__(16) float g_ksum[2ull * G * NC * DD];

__device__ __forceinline__ uint32_t smem_u32(const void* p) {
    uint32_t a;
    asm("{ .reg .u64 t; cvta.to.shared.u64 t, %1; cvt.u32.u64 %0, t; }" : "=r"(a) : "l"(p));
    return a;
}
#define LDM4(r0, r1, r2, r3, addr) \
    asm volatile("ldmatrix.sync.aligned.m8n8.x4.shared.b16 {%0,%1,%2,%3}, [%4];" \
                 : "=r"(r0), "=r"(r1), "=r"(r2), "=r"(r3) : "r"(addr))
#define LDM4T(r0, r1, r2, r3, addr) \
    asm volatile("ldmatrix.sync.aligned.m8n8.x4.trans.shared.b16 {%0,%1,%2,%3}, [%4];" \
                 : "=r"(r0), "=r"(r1), "=r"(r2), "=r"(r3) : "r"(addr))
__device__ __forceinline__ void mma_bf16(float* c, uint32_t a0, uint32_t a1, uint32_t a2, uint32_t a3,
                                         uint32_t b0, uint32_t b1) {
    asm("mma.sync.aligned.m16n8k16.row.col.f32.bf16.bf16.f32 "
        "{%0,%1,%2,%3},{%4,%5,%6,%7},{%8,%9},{%0,%1,%2,%3};"
        : "+f"(c[0]), "+f"(c[1]), "+f"(c[2]), "+f"(c[3])
        : "r"(a0), "r"(a1), "r"(a2), "r"(a3), "r"(b0), "r"(b1));
}
__device__ __forceinline__ void split2(float x, float y, uint32_t& hw, uint32_t& lw) {
    __nv_bfloat16 hx = __float2bfloat16(x), hy = __float2bfloat16(y);
    float rx = x - __bfloat162float(hx), ry = y - __bfloat162float(hy);
    __nv_bfloat16 lx = __float2bfloat16(rx), ly = __float2bfloat16(ry);
    hw = (uint32_t)*(uint16_t*)&hx | ((uint32_t)*(uint16_t*)&hy << 16);
    lw = (uint32_t)*(uint16_t*)&lx | ((uint32_t)*(uint16_t*)&ly << 16);
}

// ===========================================================================
// Pass 1: ST_m[e][d] = sum_j v[j][e] k_m[j][d]; ksum_m[d] = sum_j k_m[j][d].
// Row-major hi/lo tiles, pitch 36 words (144 B). Word offsets:
//   VH 0  VL 4608  K1H 9216  K1L 13824  K2H 18432  K2L 23040  -> 27648 w
// ===========================================================================
#define P1_SMEM (27648 * 4)
__global__ __launch_bounds__(256) void pass1_kernel(const float* __restrict__ k1g,
                                                    const float* __restrict__ k2g,
                                                    const float* __restrict__ vg) {
    extern __shared__ uint32_t smw[];
    const int c = blockIdx.x, g = blockIdx.y;
    const int tid = threadIdx.x, w = tid >> 5, lane = tid & 31;
    const int gq = lane >> 2, tq = lane & 3;
    const size_t cbase = ((size_t)g * NSEQ + (size_t)c * CC) * DD;

    {   // coalesced row-major staging (conflict-free 32-bit stores)
        const float2* vp  = (const float2*)(vg + cbase);
        const float2* k1p = (const float2*)(k1g + cbase);
        const float2* k2p = (const float2*)(k2g + cbase);
        #pragma unroll
        for (int it = 0; it < 16; it++) {
            int idx = it * 256 + tid;
            int off = (idx >> 5) * 36 + (idx & 31);
            float2 xv; uint32_t hw, lw;
            xv = vp[idx];  split2(xv.x, xv.y, hw, lw); smw[off] = hw;          smw[4608 + off] = lw;
            xv = k1p[idx]; split2(xv.x, xv.y, hw, lw); smw[9216 + off] = hw;   smw[13824 + off] = lw;
            xv = k2p[idx]; split2(xv.x, xv.y, hw, lw); smw[18432 + off] = hw;  smw[23040 + off] = lw;
        }
    }
    // exact f32 ksum from global (coalesced, L2-hot), overlaps staging latency
    if (tid < 128) {
        int m = tid >> 6, d = tid & 63;
        const float* kp = (m ? k2g : k1g) + cbase;
        float s = 0.f;
        #pragma unroll 8
        for (int j = 0; j < CC; j++) s += kp[j * DD + d];
        g_ksum[(((size_t)m * G + g) * NC + c) * DD + d] = s;
    }
    __syncthreads();

    const int band = (w >> 1) * 16, nh = w & 1;
    const uint32_t sbase = smem_u32(smw);
    // trans lane map: row (k/j dim) = (lane&7)+8*((lane>>4)&1); col half (m/n) = (lane>>3)&1
    const uint32_t lt = ((lane & 7) + ((lane >> 4) & 1) * 8) * 144 + ((lane >> 3) & 1) * 16;
    const uint32_t avh = sbase + lt + (uint32_t)band * 2;       // A = v^T, m = e
    const uint32_t avl = avh + 4608 * 4;

    float accP[2][4][4];
    #pragma unroll
    for (int m = 0; m < 2; m++)
        #pragma unroll
        for (int t = 0; t < 4; t++)
            #pragma unroll
            for (int u = 0; u < 4; u++) accP[m][t][u] = 0.f;

    #pragma unroll
    for (int m = 0; m < 2; m++) {
        const uint32_t bkh = sbase + (m ? 18432u : 9216u) * 4 + lt + (uint32_t)nh * 64;
        const uint32_t bkl = bkh + 4608 * 4;
        #pragma unroll 1
        for (int kk = 0; kk < 8; kk++) {
            uint32_t ah0, ah1, ah2, ah3, al0, al1, al2, al3;
            LDM4T(ah0, ah1, ah2, ah3, avh + kk * 2304);
            LDM4T(al0, al1, al2, al3, avl + kk * 2304);
            #pragma unroll
            for (int p = 0; p < 2; p++) {
                uint32_t bh0, bh1, bh2, bh3, bl0, bl1, bl2, bl3;
                LDM4T(bh0, bh1, bh2, bh3, bkh + p * 32 + kk * 2304);
                LDM4T(bl0, bl1, bl2, bl3, bkl + p * 32 + kk * 2304);
                mma_bf16(accP[m][2 * p], ah0, ah1, ah2, ah3, bh0, bh2);
                mma_bf16(accP[m][2 * p], al0, al1, al2, al3, bh0, bh2);
                mma_bf16(accP[m][2 * p], ah0, ah1, ah2, ah3, bl0, bl2);
                mma_bf16(accP[m][2 * p + 1], ah0, ah1, ah2, ah3, bh1, bh3);
                mma_bf16(accP[m][2 * p + 1], al0, al1, al2, al3, bh1, bh3);
                mma_bf16(accP[m][2 * p + 1], ah0, ah1, ah2, ah3, bl1, bl3);
            }
        }
    }
    #pragma unroll
    for (int m = 0; m < 2; m++) {
        float* Sp = &g_S[(((size_t)m * G + g) * NC + c) * (size_t)(DD * DD)];
        #pragma unroll
        for (int t = 0; t < 4; t++) {
            int d0 = nh * 32 + t * 8 + tq * 2;
            int e0 = band + gq;
            *(float2*)&Sp[e0 * DD + d0] = make_float2(accP[m][t][0], accP[m][t][1]);
            *(float2*)&Sp[(e0 + 8) * DD + d0] = make_float2(accP[m][t][2], accP[m][t][3]);
        }
    }
}

// ===========================================================================
// Pass 2: exclusive prefix over chunks; 512 CTAs, one float4 per thread
// ===========================================================================
__global__ __launch_bounds__(128) void pass2_kernel() {
    const int g = blockIdx.x, m = blockIdx.y, h = blockIdx.z, tid = threadIdx.x;
    float* base = &g_S[(((size_t)m * G + g) * NC) * (size_t)(DD * DD)] + h * 512;
    float4 run = make_float4(0.f, 0.f, 0.f, 0.f);
    float4 cur = ((const float4*)base)[tid];
    #pragma unroll 1
    for (int c = 0; c < NC; c++) {
        float4 nxt;
        if (c + 1 < NC) nxt = ((const float4*)(base + (size_t)(c + 1) * (DD * DD)))[tid];
        ((float4*)(base + (size_t)c * (DD * DD)))[tid] = run;
        run.x += cur.x; run.y += cur.y; run.z += cur.z; run.w += cur.w;
        cur = nxt;
    }
    if (h == 0 && tid < DD) {
        float* kb = &g_ksum[(((size_t)m * G + g) * NC) * DD];
        float r = 0.f, cu = kb[tid];
        #pragma unroll 1
        for (int c = 0; c < NC; c++) {
            float nx = (c + 1 < NC) ? kb[(c + 1) * DD + tid] : 0.f;
            kb[c * DD + tid] = r;
            r += cu; cu = nx;
        }
    }
}

// ===========================================================================
// Pass 3. Word offsets:  QH 0 (128x68)  QL 8704  KH 17408  KL 26112
//   VH 34816 (128x36 row-major)  VL 39424  SH 44032 (64x68)  SL 48384
//   QKP 52736  KP 52864   total 52992 w = 211968 B
// ===========================================================================
#define B_QL  34816u
#define B_KH  69632u
#define B_KL  104448u
#define B_VH  139264u
#define B_VL  157696u
#define B_SH  176128u
#define B_SL  193536u
#define W_QL  8704
#define W_KH  17408
#define W_KL  26112
#define W_VH  34816
#define W_VL  39424
#define W_SH  44032
#define W_SL  48384
#define W_QKP 52736
#define W_KP  52864
#define SMEM3 (52992 * 4)

__global__ __launch_bounds__(256) void pass3_kernel(const float* __restrict__ q1g,
                                                    const float* __restrict__ q2g,
                                                    const float* __restrict__ k1g,
                                                    const float* __restrict__ k2g,
                                                    const float* __restrict__ vg,
                                                    float* __restrict__ outg) {
    extern __shared__ uint32_t smw[];
    const int c = blockIdx.x, g = blockIdx.y, tid = threadIdx.x;
    const int w = tid >> 5, lane = tid & 31;
    const int gq = lane >> 2, tq = lane & 3;
    const size_t cbase = ((size_t)g * NSEQ + (size_t)c * CC) * DD;
    float* QKPf = (float*)(smw + W_QKP);
    float* KPf  = (float*)(smw + W_KP);

    // ---- stage tiles (all coalesced row-major) ----
    {
        const float2* q1p = (const float2*)(q1g + cbase);
        const float2* q2p = (const float2*)(q2g + cbase);
        const float2* k1p = (const float2*)(k1g + cbase);
        const float2* k2p = (const float2*)(k2g + cbase);
        const float2* vp  = (const float2*)(vg + cbase);
        #pragma unroll
        for (int it = 0; it < 16; it++) {
            int idx = it * 256 + tid;
            int off = (idx >> 5) * 68 + (idx & 31);
            int offv = (idx >> 5) * 36 + (idx & 31);
            float2 xv; uint32_t hw, lw;
            xv = q1p[idx]; split2(xv.x, xv.y, hw, lw); smw[off] = hw;           smw[W_QL + off] = lw;
            xv = q2p[idx]; split2(xv.x, xv.y, hw, lw); smw[off + 32] = hw;      smw[W_QL + off + 32] = lw;
            xv = k1p[idx]; split2(xv.x, xv.y, hw, lw); smw[W_KH + off] = hw;    smw[W_KL + off] = lw;
            xv = k2p[idx]; split2(xv.x, xv.y, hw, lw); smw[W_KH + off + 32] = hw; smw[W_KL + off + 32] = lw;
            xv = vp[idx];  split2(xv.x, xv.y, hw, lw); smw[W_VH + offv] = hw;   smw[W_VL + offv] = lw;
        }
        const float2* s1p = (const float2*)&g_S[(((size_t)0 * G + g) * NC + c) * (size_t)(DD * DD)];
        const float2* s2p = (const float2*)&g_S[(((size_t)1 * G + g) * NC + c) * (size_t)(DD * DD)];
        #pragma unroll
        for (int it = 0; it < 8; it++) {
            int idx = it * 256 + tid;
            int off = (idx >> 5) * 68 + (idx & 31);
            float2 xv; uint32_t hw, lw;
            xv = s1p[idx]; split2(xv.x, xv.y, hw, lw); smw[W_SH + off] = hw;      smw[W_SL + off] = lw;
            xv = s2p[idx]; split2(xv.x, xv.y, hw, lw); smw[W_SH + off + 32] = hw; smw[W_SL + off + 32] = lw;
        }
        if (tid < DD) {
            KPf[tid]      = g_ksum[(((size_t)0 * G + g) * NC + c) * DD + tid];
            KPf[64 + tid] = g_ksum[(((size_t)1 * G + g) * NC + c) * DD + tid];
        }
    }
    __syncthreads();

    // qkpre (f32 exact, overlaps MMA warps)
    if (tid < CC) {
        const float* qa = q1g + cbase + (size_t)tid * DD;
        const float* qb = q2g + cbase + (size_t)tid * DD;
        float a = 0.f;
        #pragma unroll 8
        for (int d = 0; d < DD; d++) a += qa[d] * KPf[d] + qb[d] * KPf[64 + d];
        QKPf[tid] = a;
    }

    const int band = w * 16;
    const uint32_t sbase = smem_u32(smw);
    const uint32_t laneoff = ((lane & 7) + ((lane >> 3) & 1) * 8) * 272 + ((lane >> 4) & 1) * 16;
    const uint32_t lt = ((lane & 7) + ((lane >> 4) & 1) * 8) * 144 + ((lane >> 3) & 1) * 16;
    const uint32_t aqh = sbase + band * 272 + laneoff;
    const uint32_t aql = aqh + B_QL;

    // ---- Stage A: T = Qcat Kcat^T ----
    float accA[16][4];
    #pragma unroll
    for (int t = 0; t < 16; t++)
        #pragma unroll
        for (int u = 0; u < 4; u++) accA[t][u] = 0.f;
    {
        const uint32_t bkh = sbase + B_KH + laneoff;
        const uint32_t bkl = sbase + B_KL + laneoff;
        #pragma unroll 1
        for (int kk = 0; kk < 8; kk++) {
            uint32_t ah0, ah1, ah2, ah3, al0, al1, al2, al3;
            LDM4(ah0, ah1, ah2, ah3, aqh + kk * 32);
            LDM4(al0, al1, al2, al3, aql + kk * 32);
            #pragma unroll
            for (int p = 0; p < 8; p++) {
                uint32_t bh0, bh1, bh2, bh3, bl0, bl1, bl2, bl3;
                LDM4(bh0, bh1, bh2, bh3, bkh + p * 4352 + kk * 32);
                LDM4(bl0, bl1, bl2, bl3, bkl + p * 4352 + kk * 32);
                mma_bf16(accA[2 * p], ah0, ah1, ah2, ah3, bh0, bh2);
                mma_bf16(accA[2 * p], al0, al1, al2, al3, bh0, bh2);
                mma_bf16(accA[2 * p], ah0, ah1, ah2, ah3, bl0, bl2);
                mma_bf16(accA[2 * p + 1], ah0, ah1, ah2, ah3, bh1, bh3);
                mma_bf16(accA[2 * p + 1], al0, al1, al2, al3, bh1, bh3);
                mma_bf16(accA[2 * p + 1], ah0, ah1, ah2, ah3, bl1, bl3);
            }
        }
    }

    // ---- epilogue A: mask, row sums, pack T into register A-fragments ----
    const int i0 = band + gq, i1 = i0 + 8;
    uint32_t thA[8][4], tlA[8][4];
    float rs0 = 0.f, rs1 = 0.f;
    #pragma unroll
    for (int kk = 0; kk < 8; kk++) {
        int ce = kk * 16 + tq * 2, co = ce + 8;
        float e00 = (ce <= i0) ? accA[2 * kk][0] : 0.f;
        float e01 = (ce + 1 <= i0) ? accA[2 * kk][1] : 0.f;
        float e10 = (ce <= i1) ? accA[2 * kk][2] : 0.f;
        float e11 = (ce + 1 <= i1) ? accA[2 * kk][3] : 0.f;
        float o00 = (co <= i0) ? accA[2 * kk + 1][0] : 0.f;
        float o01 = (co + 1 <= i0) ? accA[2 * kk + 1][1] : 0.f;
        float o10 = (co <= i1) ? accA[2 * kk + 1][2] : 0.f;
        float o11 = (co + 1 <= i1) ? accA[2 * kk + 1][3] : 0.f;
        rs0 += e00 + e01 + o00 + o01;
        rs1 += e10 + e11 + o10 + o11;
        split2(e00, e01, thA[kk][0], tlA[kk][0]);
        split2(e10, e11, thA[kk][1], tlA[kk][1]);
        split2(o00, o01, thA[kk][2], tlA[kk][2]);
        split2(o10, o11, thA[kk][3], tlA[kk][3]);
    }
    rs0 += __shfl_xor_sync(0xFFFFFFFFu, rs0, 1);
    rs0 += __shfl_xor_sync(0xFFFFFFFFu, rs0, 2);
    rs1 += __shfl_xor_sync(0xFFFFFFFFu, rs1, 1);
    rs1 += __shfl_xor_sync(0xFFFFFFFFu, rs1, 2);
    __syncthreads();   // QKPf visibility

    // ---- Stage B: out = T v + Qcat Scat^T ----
    float accB[8][4];
    #pragma unroll
    for (int t = 0; t < 8; t++)
        #pragma unroll
        for (int u = 0; u < 4; u++) accB[t][u] = 0.f;
    {
        const uint32_t bvh = sbase + B_VH + lt;   // v row-major, trans-load B[n=e][k=j]
        const uint32_t bvl = sbase + B_VL + lt;
        #pragma unroll
        for (int kk = 0; kk < 8; kk++) {
            #pragma unroll
            for (int p = 0; p < 4; p++) {
                uint32_t bh0, bh1, bh2, bh3, bl0, bl1, bl2, bl3;
                LDM4T(bh0, bh1, bh2, bh3, bvh + kk * 2304 + p * 32);
                LDM4T(bl0, bl1, bl2, bl3, bvl + kk * 2304 + p * 32);
                mma_bf16(accB[2 * p], thA[kk][0], thA[kk][1], thA[kk][2], thA[kk][3], bh0, bh2);
                mma_bf16(accB[2 * p], tlA[kk][0], tlA[kk][1], tlA[kk][2], tlA[kk][3], bh0, bh2);
                mma_bf16(accB[2 * p], thA[kk][0], thA[kk][1], thA[kk][2], thA[kk][3], bl0, bl2);
                mma_bf16(accB[2 * p + 1], thA[kk][0], thA[kk][1], thA[kk][2], thA[kk][3], bh1, bh3);
                mma_bf16(accB[2 * p + 1], tlA[kk][0], tlA[kk][1], tlA[kk][2], tlA[kk][3], bh1, bh3);
                mma_bf16(accB[2 * p + 1], thA[kk][0], thA[kk][1], thA[kk][2], thA[kk][3], bl1, bl3);
            }
        }
        const uint32_t bsh = sbase + B_SH + laneoff;
        const uint32_t bsl = sbase + B_SL + laneoff;
        #pragma unroll 1
        for (int kk = 0; kk < 8; kk++) {
            uint32_t ah0, ah1, ah2, ah3, al0, al1, al2, al3;
            LDM4(ah0, ah1, ah2, ah3, aqh + kk * 32);
            LDM4(al0, al1, al2, al3, aql + kk * 32);
            #pragma unroll
            for (int p = 0; p < 4; p++) {
                uint32_t bh0, bh1, bh2, bh3, bl0, bl1, bl2, bl3;
                LDM4(bh0, bh1, bh2, bh3, bsh + p * 4352 + kk * 32);
                LDM4(bl0, bl1, bl2, bl3, bsl + p * 4352 + kk * 32);
                mma_bf16(accB[2 * p], ah0, ah1, ah2, ah3, bh0, bh2);
                mma_bf16(accB[2 * p], al0, al1, al2, al3, bh0, bh2);
                mma_bf16(accB[2 * p], ah0, ah1, ah2, ah3, bl0, bl2);
                mma_bf16(accB[2 * p + 1], ah0, ah1, ah2, ah3, bh1, bh3);
                mma_bf16(accB[2 * p + 1], al0, al1, al2, al3, bh1, bh3);
                mma_bf16(accB[2 * p + 1], ah0, ah1, ah2, ah3, bl1, bl3);
            }
        }
    }

    // ---- epilogue B ----
    float dnv0 = 1.0f / (rs0 + QKPf[i0] + 1e-10f);
    float dnv1 = 1.0f / (rs1 + QKPf[i1] + 1e-10f);
    float* op = outg + cbase;
    #pragma unroll
    for (int t = 0; t < 8; t++) {
        int e = t * 8 + tq * 2;
        *(float2*)&op[i0 * DD + e] = make_float2(accB[t][0] * dnv0, accB[t][1] * dnv0);
        *(float2*)&op[i1 * DD + e] = make_float2(accB[t][2] * dnv1, accB[t][3] * dnv1);
    }
}

// ---------------------------------------------------------------------------
extern "C" void kernel_launch(void* const* d_in, const int* in_sizes, int n_in,
                              void* d_out, int out_size) {
    const float* q  = (const float*)d_in[0];
    const float* k  = (const float*)d_in[1];
    const float* qr = (const float*)d_in[2];
    const float* kr = (const float*)d_in[3];
    const float* v  = (const float*)d_in[4];
    float* out = (float*)d_out;

    cudaFuncSetAttribute(pass1_kernel, cudaFuncAttributeMaxDynamicSharedMemorySize, P1_SMEM);
    cudaFuncSetAttribute(pass3_kernel, cudaFuncAttributeMaxDynamicSharedMemorySize, SMEM3);

    dim3 g1(NC, G);
    pass1_kernel<<<g1, 256, P1_SMEM>>>(k, kr, v);
    dim3 g2(G, 2, 8);
    pass2_kernel<<<g2, 128>>>();
    dim3 g3(NC, G);
    pass3_kernel<<<g3, 256, SMEM3>>>(q, qr, k, kr, v, out);
}

// round 8
// speedup vs baseline: 3.4924x; 1.0322x over previous
#include <cuda_runtime.h>
#include <cuda_bf16.h>
#include <stdint.h>

#define G    16
#define NSEQ 4096
#define DD   64
#define CC   128
#define NC   32

// g_S holds S^T: ST[e][d] = sum_j v[j][e]*k[j][d], exclusive-prefixed by pass2
__device__ __align__(16) float g_S[2ull * G * NC * DD * DD];
__device__ __align__(16) float g_ksum[2ull * G * NC * DD];

__device__ __forceinline__ uint32_t smem_u32(const void* p) {
    uint32_t a;
    asm("{ .reg .u64 t; cvta.to.shared.u64 t, %1; cvt.u32.u64 %0, t; }" : "=r"(a) : "l"(p));
    return a;
}
#define LDM4(r0, r1, r2, r3, addr) \
    asm volatile("ldmatrix.sync.aligned.m8n8.x4.shared.b16 {%0,%1,%2,%3}, [%4];" \
                 : "=r"(r0), "=r"(r1), "=r"(r2), "=r"(r3) : "r"(addr))
#define LDM4T(r0, r1, r2, r3, addr) \
    asm volatile("ldmatrix.sync.aligned.m8n8.x4.trans.shared.b16 {%0,%1,%2,%3}, [%4];" \
                 : "=r"(r0), "=r"(r1), "=r"(r2), "=r"(r3) : "r"(addr))
__device__ __forceinline__ void mma_bf16(float* c, uint32_t a0, uint32_t a1, uint32_t a2, uint32_t a3,
                                         uint32_t b0, uint32_t b1) {
    asm("mma.sync.aligned.m16n8k16.row.col.f32.bf16.bf16.f32 "
        "{%0,%1,%2,%3},{%4,%5,%6,%7},{%8,%9},{%0,%1,%2,%3};"
        : "+f"(c[0]), "+f"(c[1]), "+f"(c[2]), "+f"(c[3])
        : "r"(a0), "r"(a1), "r"(a2), "r"(a3), "r"(b0), "r"(b1));
}
__device__ __forceinline__ void split2(float x, float y, uint32_t& hw, uint32_t& lw) {
    __nv_bfloat16 hx = __float2bfloat16(x), hy = __float2bfloat16(y);
    float rx = x - __bfloat162float(hx), ry = y - __bfloat162float(hy);
    __nv_bfloat16 lx = __float2bfloat16(rx), ly = __float2bfloat16(ry);
    hw = (uint32_t)*(uint16_t*)&hx | ((uint32_t)*(uint16_t*)&hy << 16);
    lw = (uint32_t)*(uint16_t*)&lx | ((uint32_t)*(uint16_t*)&ly << 16);
}

// ===========================================================================
// Pass 1 (unchanged from R7): row-major hi/lo tiles, pitch 36 words.
//   VH 0  VL 4608  K1H 9216  K1L 13824  K2H 18432  K2L 23040  -> 27648 w
// ===========================================================================
#define P1_SMEM (27648 * 4)
__global__ __launch_bounds__(256) void pass1_kernel(const float* __restrict__ k1g,
                                                    const float* __restrict__ k2g,
                                                    const float* __restrict__ vg) {
    extern __shared__ uint32_t smw[];
    const int c = blockIdx.x, g = blockIdx.y;
    const int tid = threadIdx.x, w = tid >> 5, lane = tid & 31;
    const int gq = lane >> 2, tq = lane & 3;
    const size_t cbase = ((size_t)g * NSEQ + (size_t)c * CC) * DD;

    {
        const float2* vp  = (const float2*)(vg + cbase);
        const float2* k1p = (const float2*)(k1g + cbase);
        const float2* k2p = (const float2*)(k2g + cbase);
        #pragma unroll
        for (int it = 0; it < 16; it++) {
            int idx = it * 256 + tid;
            int off = (idx >> 5) * 36 + (idx & 31);
            float2 xv; uint32_t hw, lw;
            xv = vp[idx];  split2(xv.x, xv.y, hw, lw); smw[off] = hw;          smw[4608 + off] = lw;
            xv = k1p[idx]; split2(xv.x, xv.y, hw, lw); smw[9216 + off] = hw;   smw[13824 + off] = lw;
            xv = k2p[idx]; split2(xv.x, xv.y, hw, lw); smw[18432 + off] = hw;  smw[23040 + off] = lw;
        }
    }
    if (tid < 128) {
        int m = tid >> 6, d = tid & 63;
        const float* kp = (m ? k2g : k1g) + cbase;
        float s = 0.f;
        #pragma unroll 8
        for (int j = 0; j < CC; j++) s += kp[j * DD + d];
        g_ksum[(((size_t)m * G + g) * NC + c) * DD + d] = s;
    }
    __syncthreads();

    const int band = (w >> 1) * 16, nh = w & 1;
    const uint32_t sbase = smem_u32(smw);
    const uint32_t lt = ((lane & 7) + ((lane >> 4) & 1) * 8) * 144 + ((lane >> 3) & 1) * 16;
    const uint32_t avh = sbase + lt + (uint32_t)band * 2;
    const uint32_t avl = avh + 4608 * 4;

    float accP[2][4][4];
    #pragma unroll
    for (int m = 0; m < 2; m++)
        #pragma unroll
        for (int t = 0; t < 4; t++)
            #pragma unroll
            for (int u = 0; u < 4; u++) accP[m][t][u] = 0.f;

    #pragma unroll
    for (int m = 0; m < 2; m++) {
        const uint32_t bkh = sbase + (m ? 18432u : 9216u) * 4 + lt + (uint32_t)nh * 64;
        const uint32_t bkl = bkh + 4608 * 4;
        #pragma unroll 1
        for (int kk = 0; kk < 8; kk++) {
            uint32_t ah0, ah1, ah2, ah3, al0, al1, al2, al3;
            LDM4T(ah0, ah1, ah2, ah3, avh + kk * 2304);
            LDM4T(al0, al1, al2, al3, avl + kk * 2304);
            #pragma unroll
            for (int p = 0; p < 2; p++) {
                uint32_t bh0, bh1, bh2, bh3, bl0, bl1, bl2, bl3;
                LDM4T(bh0, bh1, bh2, bh3, bkh + p * 32 + kk * 2304);
                LDM4T(bl0, bl1, bl2, bl3, bkl + p * 32 + kk * 2304);
                mma_bf16(accP[m][2 * p], ah0, ah1, ah2, ah3, bh0, bh2);
                mma_bf16(accP[m][2 * p], al0, al1, al2, al3, bh0, bh2);
                mma_bf16(accP[m][2 * p], ah0, ah1, ah2, ah3, bl0, bl2);
                mma_bf16(accP[m][2 * p + 1], ah0, ah1, ah2, ah3, bh1, bh3);
                mma_bf16(accP[m][2 * p + 1], al0, al1, al2, al3, bh1, bh3);
                mma_bf16(accP[m][2 * p + 1], ah0, ah1, ah2, ah3, bl1, bl3);
            }
        }
    }
    #pragma unroll
    for (int m = 0; m < 2; m++) {
        float* Sp = &g_S[(((size_t)m * G + g) * NC + c) * (size_t)(DD * DD)];
        #pragma unroll
        for (int t = 0; t < 4; t++) {
            int d0 = nh * 32 + t * 8 + tq * 2;
            int e0 = band + gq;
            *(float2*)&Sp[e0 * DD + d0] = make_float2(accP[m][t][0], accP[m][t][1]);
            *(float2*)&Sp[(e0 + 8) * DD + d0] = make_float2(accP[m][t][2], accP[m][t][3]);
        }
    }
}

// ===========================================================================
// Pass 2 (unchanged): exclusive prefix over chunks; 512 CTAs
// ===========================================================================
__global__ __launch_bounds__(128) void pass2_kernel() {
    const int g = blockIdx.x, m = blockIdx.y, h = blockIdx.z, tid = threadIdx.x;
    float* base = &g_S[(((size_t)m * G + g) * NC) * (size_t)(DD * DD)] + h * 512;
    float4 run = make_float4(0.f, 0.f, 0.f, 0.f);
    float4 cur = ((const float4*)base)[tid];
    #pragma unroll 1
    for (int c = 0; c < NC; c++) {
        float4 nxt;
        if (c + 1 < NC) nxt = ((const float4*)(base + (size_t)(c + 1) * (DD * DD)))[tid];
        ((float4*)(base + (size_t)c * (DD * DD)))[tid] = run;
        run.x += cur.x; run.y += cur.y; run.z += cur.z; run.w += cur.w;
        cur = nxt;
    }
    if (h == 0 && tid < DD) {
        float* kb = &g_ksum[(((size_t)m * G + g) * NC) * DD];
        float r = 0.f, cu = kb[tid];
        #pragma unroll 1
        for (int c = 0; c < NC; c++) {
            float nx = (c + 1 < NC) ? kb[(c + 1) * DD + tid] : 0.f;
            kb[c * DD + tid] = r;
            r += cu; cu = nx;
        }
    }
}

// ===========================================================================
// Pass 3: 512 threads / 16 warps. Warp (b = w>>1, nh = w&1):
//   stage A: rows b*16..+16, T cols nh*64..+64 (half the B tiles, full K)
//   stage B: k-dim split by nh (T.v over own j-half; q.S over kk in nh*4..+4)
//   partial accB reduced through smem RED (aliases dead K tile)
// Word offsets: QH 0 QL 8704 KH 17408 KL 26112 VH 34816 VL 39424
//   SH 44032 SL 48384 QKP 52736 KP 52864 DEN 52992(256) -> 53248 w
// ===========================================================================
#define B_QL  34816u
#define B_KH  69632u
#define B_KL  104448u
#define B_VH  139264u
#define B_VL  157696u
#define B_SH  176128u
#define B_SL  193536u
#define W_QL  8704
#define W_KH  17408
#define W_KL  26112
#define W_VH  34816
#define W_VL  39424
#define W_SH  44032
#define W_SL  48384
#define W_QKP 52736
#define W_KP  52864
#define W_DEN 52992
#define W_RED W_KH
#define SMEM3 (53248 * 4)

__global__ __launch_bounds__(512) void pass3_kernel(const float* __restrict__ q1g,
                                                    const float* __restrict__ q2g,
                                                    const float* __restrict__ k1g,
                                                    const float* __restrict__ k2g,
                                                    const float* __restrict__ vg,
                                                    float* __restrict__ outg) {
    extern __shared__ uint32_t smw[];
    const int c = blockIdx.x, g = blockIdx.y, tid = threadIdx.x;
    const int w = tid >> 5, lane = tid & 31;
    const int gq = lane >> 2, tq = lane & 3;
    const int band = (w >> 1) * 16, nh = w & 1;
    const size_t cbase = ((size_t)g * NSEQ + (size_t)c * CC) * DD;
    float* QKPf = (float*)(smw + W_QKP);
    float* KPf  = (float*)(smw + W_KP);
    float* DENf = (float*)(smw + W_DEN);
    float* REDf = (float*)(smw + W_RED);

    // ---- stage tiles (coalesced row-major) ----
    {
        const float2* q1p = (const float2*)(q1g + cbase);
        const float2* q2p = (const float2*)(q2g + cbase);
        const float2* k1p = (const float2*)(k1g + cbase);
        const float2* k2p = (const float2*)(k2g + cbase);
        const float2* vp  = (const float2*)(vg + cbase);
        #pragma unroll
        for (int it = 0; it < 8; it++) {
            int idx = it * 512 + tid;
            int off = (idx >> 5) * 68 + (idx & 31);
            int offv = (idx >> 5) * 36 + (idx & 31);
            float2 xv; uint32_t hw, lw;
            xv = q1p[idx]; split2(xv.x, xv.y, hw, lw); smw[off] = hw;           smw[W_QL + off] = lw;
            xv = q2p[idx]; split2(xv.x, xv.y, hw, lw); smw[off + 32] = hw;      smw[W_QL + off + 32] = lw;
            xv = k1p[idx]; split2(xv.x, xv.y, hw, lw); smw[W_KH + off] = hw;    smw[W_KL + off] = lw;
            xv = k2p[idx]; split2(xv.x, xv.y, hw, lw); smw[W_KH + off + 32] = hw; smw[W_KL + off + 32] = lw;
            xv = vp[idx];  split2(xv.x, xv.y, hw, lw); smw[W_VH + offv] = hw;   smw[W_VL + offv] = lw;
        }
        const float2* s1p = (const float2*)&g_S[(((size_t)0 * G + g) * NC + c) * (size_t)(DD * DD)];
        const float2* s2p = (const float2*)&g_S[(((size_t)1 * G + g) * NC + c) * (size_t)(DD * DD)];
        #pragma unroll
        for (int it = 0; it < 4; it++) {
            int idx = it * 512 + tid;
            int off = (idx >> 5) * 68 + (idx & 31);
            float2 xv; uint32_t hw, lw;
            xv = s1p[idx]; split2(xv.x, xv.y, hw, lw); smw[W_SH + off] = hw;      smw[W_SL + off] = lw;
            xv = s2p[idx]; split2(xv.x, xv.y, hw, lw); smw[W_SH + off + 32] = hw; smw[W_SL + off + 32] = lw;
        }
        if (tid < DD) {
            KPf[tid]      = g_ksum[(((size_t)0 * G + g) * NC + c) * DD + tid];
            KPf[64 + tid] = g_ksum[(((size_t)1 * G + g) * NC + c) * DD + tid];
        }
    }
    __syncthreads();

    // qkpre (f32 exact, overlaps MMA warps)
    if (tid < CC) {
        const float* qa = q1g + cbase + (size_t)tid * DD;
        const float* qb = q2g + cbase + (size_t)tid * DD;
        float a = 0.f;
        #pragma unroll 8
        for (int d = 0; d < DD; d++) a += qa[d] * KPf[d] + qb[d] * KPf[64 + d];
        QKPf[tid] = a;
    }

    const uint32_t sbase = smem_u32(smw);
    const uint32_t laneoff = ((lane & 7) + ((lane >> 3) & 1) * 8) * 272 + ((lane >> 4) & 1) * 16;
    const uint32_t lt = ((lane & 7) + ((lane >> 4) & 1) * 8) * 144 + ((lane >> 3) & 1) * 16;
    const uint32_t aqh = sbase + band * 272 + laneoff;
    const uint32_t aql = aqh + B_QL;

    // ---- Stage A: T[band rows][nh half] = Qcat Kcat^T ----
    float accA[8][4];
    #pragma unroll
    for (int t = 0; t < 8; t++)
        #pragma unroll
        for (int u = 0; u < 4; u++) accA[t][u] = 0.f;
    {
        const uint32_t bkh = sbase + B_KH + (uint32_t)nh * 17408u + laneoff;
        const uint32_t bkl = sbase + B_KL + (uint32_t)nh * 17408u + laneoff;
        #pragma unroll 1
        for (int kk = 0; kk < 8; kk++) {
            uint32_t ah0, ah1, ah2, ah3, al0, al1, al2, al3;
            LDM4(ah0, ah1, ah2, ah3, aqh + kk * 32);
            LDM4(al0, al1, al2, al3, aql + kk * 32);
            #pragma unroll
            for (int p = 0; p < 4; p++) {
                uint32_t bh0, bh1, bh2, bh3, bl0, bl1, bl2, bl3;
                LDM4(bh0, bh1, bh2, bh3, bkh + p * 4352 + kk * 32);
                LDM4(bl0, bl1, bl2, bl3, bkl + p * 4352 + kk * 32);
                mma_bf16(accA[2 * p], ah0, ah1, ah2, ah3, bh0, bh2);
                mma_bf16(accA[2 * p], al0, al1, al2, al3, bh0, bh2);
                mma_bf16(accA[2 * p], ah0, ah1, ah2, ah3, bl0, bl2);
                mma_bf16(accA[2 * p + 1], ah0, ah1, ah2, ah3, bh1, bh3);
                mma_bf16(accA[2 * p + 1], al0, al1, al2, al3, bh1, bh3);
                mma_bf16(accA[2 * p + 1], ah0, ah1, ah2, ah3, bl1, bl3);
            }
        }
    }

    // ---- epilogue A: mask, partial row sums, pack T into A-fragments ----
    const int i0 = band + gq, i1 = i0 + 8;
    uint32_t thA[4][4], tlA[4][4];
    float rs0 = 0.f, rs1 = 0.f;
    #pragma unroll
    for (int kkt = 0; kkt < 4; kkt++) {
        int ce = nh * 64 + kkt * 16 + tq * 2, co = ce + 8;
        float e00 = (ce <= i0) ? accA[2 * kkt][0] : 0.f;
        float e01 = (ce + 1 <= i0) ? accA[2 * kkt][1] : 0.f;
        float e10 = (ce <= i1) ? accA[2 * kkt][2] : 0.f;
        float e11 = (ce + 1 <= i1) ? accA[2 * kkt][3] : 0.f;
        float o00 = (co <= i0) ? accA[2 * kkt + 1][0] : 0.f;
        float o01 = (co + 1 <= i0) ? accA[2 * kkt + 1][1] : 0.f;
        float o10 = (co <= i1) ? accA[2 * kkt + 1][2] : 0.f;
        float o11 = (co + 1 <= i1) ? accA[2 * kkt + 1][3] : 0.f;
        rs0 += e00 + e01 + o00 + o01;
        rs1 += e10 + e11 + o10 + o11;
        split2(e00, e01, thA[kkt][0], tlA[kkt][0]);
        split2(e10, e11, thA[kkt][1], tlA[kkt][1]);
        split2(o00, o01, thA[kkt][2], tlA[kkt][2]);
        split2(o10, o11, thA[kkt][3], tlA[kkt][3]);
    }
    rs0 += __shfl_xor_sync(0xFFFFFFFFu, rs0, 1);
    rs0 += __shfl_xor_sync(0xFFFFFFFFu, rs0, 2);
    rs1 += __shfl_xor_sync(0xFFFFFFFFu, rs1, 1);
    rs1 += __shfl_xor_sync(0xFFFFFFFFu, rs1, 2);
    if (tq == 0) {
        DENf[i0 * 2 + nh] = rs0;
        DENf[i1 * 2 + nh] = rs1;
    }
    __syncthreads();   // K reads done (RED aliases K); DEN + QKP visible

    // ---- Stage B partials: T v (own j-half) + Qcat Scat^T (own kk-half) ----
    float accB[8][4];
    #pragma unroll
    for (int t = 0; t < 8; t++)
        #pragma unroll
        for (int u = 0; u < 4; u++) accB[t][u] = 0.f;
    {
        const uint32_t bvh = sbase + B_VH + (uint32_t)nh * 9216u + lt;
        const uint32_t bvl = sbase + B_VL + (uint32_t)nh * 9216u + lt;
        #pragma unroll
        for (int kkt = 0; kkt < 4; kkt++) {
            #pragma unroll
            for (int p = 0; p < 4; p++) {
                uint32_t bh0, bh1, bh2, bh3, bl0, bl1, bl2, bl3;
                LDM4T(bh0, bh1, bh2, bh3, bvh + kkt * 2304 + p * 32);
                LDM4T(bl0, bl1, bl2, bl3, bvl + kkt * 2304 + p * 32);
                mma_bf16(accB[2 * p], thA[kkt][0], thA[kkt][1], thA[kkt][2], thA[kkt][3], bh0, bh2);
                mma_bf16(accB[2 * p], tlA[kkt][0], tlA[kkt][1], tlA[kkt][2], tlA[kkt][3], bh0, bh2);
                mma_bf16(accB[2 * p], thA[kkt][0], thA[kkt][1], thA[kkt][2], thA[kkt][3], bl0, bl2);
                mma_bf16(accB[2 * p + 1], thA[kkt][0], thA[kkt][1], thA[kkt][2], thA[kkt][3], bh1, bh3);
                mma_bf16(accB[2 * p + 1], tlA[kkt][0], tlA[kkt][1], tlA[kkt][2], tlA[kkt][3], bh1, bh3);
                mma_bf16(accB[2 * p + 1], thA[kkt][0], thA[kkt][1], thA[kkt][2], thA[kkt][3], bl1, bl3);
            }
        }
        const uint32_t bsh = sbase + B_SH + laneoff;
        const uint32_t bsl = sbase + B_SL + laneoff;
        #pragma unroll 1
        for (int kkl = 0; kkl < 4; kkl++) {
            int kk = nh * 4 + kkl;
            uint32_t ah0, ah1, ah2, ah3, al0, al1, al2, al3;
            LDM4(ah0, ah1, ah2, ah3, aqh + kk * 32);
            LDM4(al0, al1, al2, al3, aql + kk * 32);
            #pragma unroll
            for (int p = 0; p < 4; p++) {
                uint32_t bh0, bh1, bh2, bh3, bl0, bl1, bl2, bl3;
                LDM4(bh0, bh1, bh2, bh3, bsh + p * 4352 + kk * 32);
                LDM4(bl0, bl1, bl2, bl3, bsl + p * 4352 + kk * 32);
                mma_bf16(accB[2 * p], ah0, ah1, ah2, ah3, bh0, bh2);
                mma_bf16(accB[2 * p], al0, al1, al2, al3, bh0, bh2);
                mma_bf16(accB[2 * p], ah0, ah1, ah2, ah3, bl0, bl2);
                mma_bf16(accB[2 * p + 1], ah0, ah1, ah2, ah3, bh1, bh3);
                mma_bf16(accB[2 * p + 1], al0, al1, al2, al3, bh1, bh3);
                mma_bf16(accB[2 * p + 1], ah0, ah1, ah2, ah3, bl1, bl3);
            }
        }
    }

    // ---- cross-warp reduction + epilogue ----
    if (nh == 1) {
        #pragma unroll
        for (int t = 0; t < 8; t++) {
            int e = t * 8 + tq * 2;
            *(float2*)&REDf[i0 * 64 + e] = make_float2(accB[t][0], accB[t][1]);
            *(float2*)&REDf[i1 * 64 + e] = make_float2(accB[t][2], accB[t][3]);
        }
    }
    __syncthreads();
    if (nh == 0) {
        float dnv0 = 1.0f / (DENf[i0 * 2] + DENf[i0 * 2 + 1] + QKPf[i0] + 1e-10f);
        float dnv1 = 1.0f / (DENf[i1 * 2] + DENf[i1 * 2 + 1] + QKPf[i1] + 1e-10f);
        float* op = outg + cbase;
        #pragma unroll
        for (int t = 0; t < 8; t++) {
            int e = t * 8 + tq * 2;
            float2 p0 = *(const float2*)&REDf[i0 * 64 + e];
            float2 p1 = *(const float2*)&REDf[i1 * 64 + e];
            *(float2*)&op[i0 * DD + e] = make_float2((accB[t][0] + p0.x) * dnv0, (accB[t][1] + p0.y) * dnv0);
            *(float2*)&op[i1 * DD + e] = make_float2((accB[t][2] + p1.x) * dnv1, (accB[t][3] + p1.y) * dnv1);
        }
    }
}

// ---------------------------------------------------------------------------
extern "C" void kernel_launch(void* const* d_in, const int* in_sizes, int n_in,
                              void* d_out, int out_size) {
    const float* q  = (const float*)d_in[0];
    const float* k  = (const float*)d_in[1];
    const float* qr = (const float*)d_in[2];
    const float* kr = (const float*)d_in[3];
    const float* v  = (const float*)d_in[4];
    float* out = (float*)d_out;

    cudaFuncSetAttribute(pass1_kernel, cudaFuncAttributeMaxDynamicSharedMemorySize, P1_SMEM);
    cudaFuncSetAttribute(pass3_kernel, cudaFuncAttributeMaxDynamicSharedMemorySize, SMEM3);

    dim3 g1(NC, G);
    pass1_kernel<<<g1, 256, P1_SMEM>>>(k, kr, v);
    dim3 g2(G, 2, 8);
    pass2_kernel<<<g2, 128>>>();
    dim3 g3(NC, G);
    pass3_kernel<<<g3, 512, SMEM3>>>(q, qr, k, kr, v, out);
}

// round 10
// speedup vs baseline: 4.6283x; 1.3253x over previous
#include <cuda_runtime.h>
#include <cuda_fp16.h>
#include <stdint.h>

#define G    16
#define NSEQ 4096
#define DD   64
#define CC   128
#define NC   32

// g_S holds S^T: ST[e][d] = sum_j v[j][e]*k[j][d], exclusive-prefixed by pass2
__device__ __align__(16) float g_S[2ull * G * NC * DD * DD];
__device__ __align__(16) float g_ksum[2ull * G * NC * DD];

__device__ __forceinline__ uint32_t smem_u32(const void* p) {
    uint32_t a;
    asm("{ .reg .u64 t; cvta.to.shared.u64 t, %1; cvt.u32.u64 %0, t; }" : "=r"(a) : "l"(p));
    return a;
}
#define LDM4(r0, r1, r2, r3, addr) \
    asm volatile("ldmatrix.sync.aligned.m8n8.x4.shared.b16 {%0,%1,%2,%3}, [%4];" \
                 : "=r"(r0), "=r"(r1), "=r"(r2), "=r"(r3) : "r"(addr))
#define LDM4T(r0, r1, r2, r3, addr) \
    asm volatile("ldmatrix.sync.aligned.m8n8.x4.trans.shared.b16 {%0,%1,%2,%3}, [%4];" \
                 : "=r"(r0), "=r"(r1), "=r"(r2), "=r"(r3) : "r"(addr))
__device__ __forceinline__ void mma_f16(float* c, uint32_t a0, uint32_t a1, uint32_t a2, uint32_t a3,
                                        uint32_t b0, uint32_t b1) {
    asm("mma.sync.aligned.m16n8k16.row.col.f32.f16.f16.f32 "
        "{%0,%1,%2,%3},{%4,%5,%6,%7},{%8,%9},{%0,%1,%2,%3};"
        : "+f"(c[0]), "+f"(c[1]), "+f"(c[2]), "+f"(c[3])
        : "r"(a0), "r"(a1), "r"(a2), "r"(a3), "r"(b0), "r"(b1));
}
__device__ __forceinline__ uint32_t packh2(float x, float y) {
    __half2 h = __floats2half2_rn(x, y);
    return *(uint32_t*)&h;
}

// ===========================================================================
// Pass 1 (fp16 single-term): ST_m[e][d] = sum_j v[j][e] k_m[j][d]; ksum exact.
// Row-major fp16 tiles, pitch 36 words: VH 0, K1H 4608, K2H 9216 -> 13824 w
// ===========================================================================
#define P1_SMEM (13824 * 4)
__global__ __launch_bounds__(256) void pass1_kernel(const float* __restrict__ k1g,
                                                    const float* __restrict__ k2g,
                                                    const float* __restrict__ vg) {
    extern __shared__ uint32_t smw[];
    const int c = blockIdx.x, g = blockIdx.y;
    const int tid = threadIdx.x, w = tid >> 5, lane = tid & 31;
    const int gq = lane >> 2, tq = lane & 3;
    const size_t cbase = ((size_t)g * NSEQ + (size_t)c * CC) * DD;

    {
        const float2* vp  = (const float2*)(vg + cbase);
        const float2* k1p = (const float2*)(k1g + cbase);
        const float2* k2p = (const float2*)(k2g + cbase);
        #pragma unroll
        for (int it = 0; it < 16; it++) {
            int idx = it * 256 + tid;
            int off = (idx >> 5) * 36 + (idx & 31);
            float2 xv;
            xv = vp[idx];  smw[off]        = packh2(xv.x, xv.y);
            xv = k1p[idx]; smw[4608 + off] = packh2(xv.x, xv.y);
            xv = k2p[idx]; smw[9216 + off] = packh2(xv.x, xv.y);
        }
    }
    if (tid < 128) {
        int m = tid >> 6, d = tid & 63;
        const float* kp = (m ? k2g : k1g) + cbase;
        float s = 0.f;
        #pragma unroll 8
        for (int j = 0; j < CC; j++) s += kp[j * DD + d];
        g_ksum[(((size_t)m * G + g) * NC + c) * DD + d] = s;
    }
    __syncthreads();

    const int band = (w >> 1) * 16, nh = w & 1;
    const uint32_t sbase = smem_u32(smw);
    // trans lane map: row (j dim) = (lane&7)+8*((lane>>4)&1); col half = (lane>>3)&1
    const uint32_t lt = ((lane & 7) + ((lane >> 4) & 1) * 8) * 144 + ((lane >> 3) & 1) * 16;
    const uint32_t avh = sbase + lt + (uint32_t)band * 2;   // A = v^T, m = e

    float accP[2][4][4];
    #pragma unroll
    for (int m = 0; m < 2; m++)
        #pragma unroll
        for (int t = 0; t < 4; t++)
            #pragma unroll
            for (int u = 0; u < 4; u++) accP[m][t][u] = 0.f;

    #pragma unroll
    for (int m = 0; m < 2; m++) {
        const uint32_t bkh = sbase + (m ? 9216u : 4608u) * 4 + lt + (uint32_t)nh * 64;
        #pragma unroll 1
        for (int kk = 0; kk < 8; kk++) {
            uint32_t ah0, ah1, ah2, ah3;
            LDM4T(ah0, ah1, ah2, ah3, avh + kk * 2304);
            #pragma unroll
            for (int p = 0; p < 2; p++) {
                uint32_t bh0, bh1, bh2, bh3;
                LDM4T(bh0, bh1, bh2, bh3, bkh + p * 32 + kk * 2304);
                mma_f16(accP[m][2 * p],     ah0, ah1, ah2, ah3, bh0, bh2);
                mma_f16(accP[m][2 * p + 1], ah0, ah1, ah2, ah3, bh1, bh3);
            }
        }
    }
    #pragma unroll
    for (int m = 0; m < 2; m++) {
        float* Sp = &g_S[(((size_t)m * G + g) * NC + c) * (size_t)(DD * DD)];
        #pragma unroll
        for (int t = 0; t < 4; t++) {
            int d0 = nh * 32 + t * 8 + tq * 2;
            int e0 = band + gq;
            *(float2*)&Sp[e0 * DD + d0] = make_float2(accP[m][t][0], accP[m][t][1]);
            *(float2*)&Sp[(e0 + 8) * DD + d0] = make_float2(accP[m][t][2], accP[m][t][3]);
        }
    }
}

// ===========================================================================
// Pass 2 (unchanged): exclusive prefix over chunks; 512 CTAs
// ===========================================================================
__global__ __launch_bounds__(128) void pass2_kernel() {
    const int g = blockIdx.x, m = blockIdx.y, h = blockIdx.z, tid = threadIdx.x;
    float* base = &g_S[(((size_t)m * G + g) * NC) * (size_t)(DD * DD)] + h * 512;
    float4 run = make_float4(0.f, 0.f, 0.f, 0.f);
    float4 cur = ((const float4*)base)[tid];
    #pragma unroll 1
    for (int c = 0; c < NC; c++) {
        float4 nxt;
        if (c + 1 < NC) nxt = ((const float4*)(base + (size_t)(c + 1) * (DD * DD)))[tid];
        ((float4*)(base + (size_t)c * (DD * DD)))[tid] = run;
        run.x += cur.x; run.y += cur.y; run.z += cur.z; run.w += cur.w;
        cur = nxt;
    }
    if (h == 0 && tid < DD) {
        float* kb = &g_ksum[(((size_t)m * G + g) * NC) * DD];
        float r = 0.f, cu = kb[tid];
        #pragma unroll 1
        for (int c = 0; c < NC; c++) {
            float nx = (c + 1 < NC) ? kb[(c + 1) * DD + tid] : 0.f;
            kb[c * DD + tid] = r;
            r += cu; cu = nx;
        }
    }
}

// ===========================================================================
// Pass 3 (fp16 single-term, 512 thr / 16 warps, 2 CTAs/SM).
// Word offsets: QH 0 (128x68)  KH 8704 (128x68)  VH 17408 (128x36)
//   SH 22016 (64x68)  QKP 26368  KP 26496  DEN 26624(256) -> 26880 w (107.5KB)
// RED (128x64 f32) aliases KH after stage A.
// ===========================================================================
#define B_KH  34816u
#define B_VH  69632u
#define B_SH  88064u
#define W_KH  8704
#define W_VH  17408
#define W_SH  22016
#define W_QKP 26368
#define W_KP  26496
#define W_DEN 26624
#define W_RED W_KH
#define SMEM3 (26880 * 4)

__global__ __launch_bounds__(512) void pass3_kernel(const float* __restrict__ q1g,
                                                    const float* __restrict__ q2g,
                                                    const float* __restrict__ k1g,
                                                    const float* __restrict__ k2g,
                                                    const float* __restrict__ vg,
                                                    float* __restrict__ outg) {
    extern __shared__ uint32_t smw[];
    const int c = blockIdx.x, g = blockIdx.y, tid = threadIdx.x;
    const int w = tid >> 5, lane = tid & 31;
    const int gq = lane >> 2, tq = lane & 3;
    const int band = (w >> 1) * 16, nh = w & 1;
    const size_t cbase = ((size_t)g * NSEQ + (size_t)c * CC) * DD;
    float* QKPf = (float*)(smw + W_QKP);
    float* KPf  = (float*)(smw + W_KP);
    float* DENf = (float*)(smw + W_DEN);
    float* REDf = (float*)(smw + W_RED);

    // ---- stage fp16 tiles (coalesced row-major) ----
    {
        const float2* q1p = (const float2*)(q1g + cbase);
        const float2* q2p = (const float2*)(q2g + cbase);
        const float2* k1p = (const float2*)(k1g + cbase);
        const float2* k2p = (const float2*)(k2g + cbase);
        const float2* vp  = (const float2*)(vg + cbase);
        #pragma unroll
        for (int it = 0; it < 8; it++) {
            int idx = it * 512 + tid;
            int off = (idx >> 5) * 68 + (idx & 31);
            int offv = (idx >> 5) * 36 + (idx & 31);
            float2 xv;
            xv = q1p[idx]; smw[off]             = packh2(xv.x, xv.y);
            xv = q2p[idx]; smw[off + 32]        = packh2(xv.x, xv.y);
            xv = k1p[idx]; smw[W_KH + off]      = packh2(xv.x, xv.y);
            xv = k2p[idx]; smw[W_KH + off + 32] = packh2(xv.x, xv.y);
            xv = vp[idx];  smw[W_VH + offv]     = packh2(xv.x, xv.y);
        }
        const float2* s1p = (const float2*)&g_S[(((size_t)0 * G + g) * NC + c) * (size_t)(DD * DD)];
        const float2* s2p = (const float2*)&g_S[(((size_t)1 * G + g) * NC + c) * (size_t)(DD * DD)];
        #pragma unroll
        for (int it = 0; it < 4; it++) {
            int idx = it * 512 + tid;
            int off = (idx >> 5) * 68 + (idx & 31);
            float2 xv;
            xv = s1p[idx]; smw[W_SH + off]      = packh2(xv.x, xv.y);
            xv = s2p[idx]; smw[W_SH + off + 32] = packh2(xv.x, xv.y);
        }
        if (tid < DD) {
            KPf[tid]      = g_ksum[(((size_t)0 * G + g) * NC + c) * DD + tid];
            KPf[64 + tid] = g_ksum[(((size_t)1 * G + g) * NC + c) * DD + tid];
        }
    }
    __syncthreads();

    // qkpre (f32 exact, overlaps MMA warps)
    if (tid < CC) {
        const float* qa = q1g + cbase + (size_t)tid * DD;
        const float* qb = q2g + cbase + (size_t)tid * DD;
        float a = 0.f;
        #pragma unroll 8
        for (int d = 0; d < DD; d++) a += qa[d] * KPf[d] + qb[d] * KPf[64 + d];
        QKPf[tid] = a;
    }

    const uint32_t sbase = smem_u32(smw);
    const uint32_t laneoff = ((lane & 7) + ((lane >> 3) & 1) * 8) * 272 + ((lane >> 4) & 1) * 16;
    const uint32_t lt = ((lane & 7) + ((lane >> 4) & 1) * 8) * 144 + ((lane >> 3) & 1) * 16;
    const uint32_t aqh = sbase + band * 272 + laneoff;

    // ---- Stage A: T[band rows][nh col-half] = Qcat Kcat^T ----
    float accA[8][4];
    #pragma unroll
    for (int t = 0; t < 8; t++)
        #pragma unroll
        for (int u = 0; u < 4; u++) accA[t][u] = 0.f;
    {
        const uint32_t bkh = sbase + B_KH + (uint32_t)nh * 17408u + laneoff;
        #pragma unroll 1
        for (int kk = 0; kk < 8; kk++) {
            uint32_t ah0, ah1, ah2, ah3;
            LDM4(ah0, ah1, ah2, ah3, aqh + kk * 32);
            #pragma unroll
            for (int p = 0; p < 4; p++) {
                uint32_t bh0, bh1, bh2, bh3;
                LDM4(bh0, bh1, bh2, bh3, bkh + p * 4352 + kk * 32);
                mma_f16(accA[2 * p],     ah0, ah1, ah2, ah3, bh0, bh2);
                mma_f16(accA[2 * p + 1], ah0, ah1, ah2, ah3, bh1, bh3);
            }
        }
    }

    // ---- epilogue A: mask, partial row sums, pack T into fp16 A-fragments ----
    const int i0 = band + gq, i1 = i0 + 8;
    uint32_t thA[4][4];
    float rs0 = 0.f, rs1 = 0.f;
    #pragma unroll
    for (int kkt = 0; kkt < 4; kkt++) {
        int ce = nh * 64 + kkt * 16 + tq * 2, co = ce + 8;
        float e00 = (ce <= i0) ? accA[2 * kkt][0] : 0.f;
        float e01 = (ce + 1 <= i0) ? accA[2 * kkt][1] : 0.f;
        float e10 = (ce <= i1) ? accA[2 * kkt][2] : 0.f;
        float e11 = (ce + 1 <= i1) ? accA[2 * kkt][3] : 0.f;
        float o00 = (co <= i0) ? accA[2 * kkt + 1][0] : 0.f;
        float o01 = (co + 1 <= i0) ? accA[2 * kkt + 1][1] : 0.f;
        float o10 = (co <= i1) ? accA[2 * kkt + 1][2] : 0.f;
        float o11 = (co + 1 <= i1) ? accA[2 * kkt + 1][3] : 0.f;
        rs0 += e00 + e01 + o00 + o01;
        rs1 += e10 + e11 + o10 + o11;
        thA[kkt][0] = packh2(e00, e01);
        thA[kkt][1] = packh2(e10, e11);
        thA[kkt][2] = packh2(o00, o01);
        thA[kkt][3] = packh2(o10, o11);
    }
    rs0 += __shfl_xor_sync(0xFFFFFFFFu, rs0, 1);
    rs0 += __shfl_xor_sync(0xFFFFFFFFu, rs0, 2);
    rs1 += __shfl_xor_sync(0xFFFFFFFFu, rs1, 1);
    rs1 += __shfl_xor_sync(0xFFFFFFFFu, rs1, 2);
    if (tq == 0) {
        DENf[i0 * 2 + nh] = rs0;
        DENf[i1 * 2 + nh] = rs1;
    }
    __syncthreads();   // K reads done (RED aliases K); DEN + QKP visible

    // ---- Stage B partials: T v (own j-half) + Qcat Scat^T (own kk-half) ----
    float accB[8][4];
    #pragma unroll
    for (int t = 0; t < 8; t++)
        #pragma unroll
        for (int u = 0; u < 4; u++) accB[t][u] = 0.f;
    {
        const uint32_t bvh = sbase + B_VH + (uint32_t)nh * 9216u + lt;
        #pragma unroll
        for (int kkt = 0; kkt < 4; kkt++) {
            #pragma unroll
            for (int p = 0; p < 4; p++) {
                uint32_t bh0, bh1, bh2, bh3;
                LDM4T(bh0, bh1, bh2, bh3, bvh + kkt * 2304 + p * 32);
                mma_f16(accB[2 * p],     thA[kkt][0], thA[kkt][1], thA[kkt][2], thA[kkt][3], bh0, bh2);
                mma_f16(accB[2 * p + 1], thA[kkt][0], thA[kkt][1], thA[kkt][2], thA[kkt][3], bh1, bh3);
            }
        }
        const uint32_t bsh = sbase + B_SH + laneoff;
        #pragma unroll 1
        for (int kkl = 0; kkl < 4; kkl++) {
            int kk = nh * 4 + kkl;
            uint32_t ah0, ah1, ah2, ah3;
            LDM4(ah0, ah1, ah2, ah3, aqh + kk * 32);
            #pragma unroll
            for (int p = 0; p < 4; p++) {
                uint32_t bh0, bh1, bh2, bh3;
                LDM4(bh0, bh1, bh2, bh3, bsh + p * 4352 + kk * 32);
                mma_f16(accB[2 * p],     ah0, ah1, ah2, ah3, bh0, bh2);
                mma_f16(accB[2 * p + 1], ah0, ah1, ah2, ah3, bh1, bh3);
            }
        }
    }

    // ---- cross-warp reduction + epilogue ----
    if (nh == 1) {
        #pragma unroll
        for (int t = 0; t < 8; t++) {
            int e = t * 8 + tq * 2;
            *(float2*)&REDf[i0 * 64 + e] = make_float2(accB[t][0], accB[t][1]);
            *(float2*)&REDf[i1 * 64 + e] = make_float2(accB[t][2], accB[t][3]);
        }
    }
    __syncthreads();
    if (nh == 0) {
        float dnv0 = 1.0f / (DENf[i0 * 2] + DENf[i0 * 2 + 1] + QKPf[i0] + 1e-10f);
        float dnv1 = 1.0f / (DENf[i1 * 2] + DENf[i1 * 2 + 1] + QKPf[i1] + 1e-10f);
        float* op = outg + cbase;
        #pragma unroll
        for (int t = 0; t < 8; t++) {
            int e = t * 8 + tq * 2;
            float2 p0 = *(const float2*)&REDf[i0 * 64 + e];
            float2 p1 = *(const float2*)&REDf[i1 * 64 + e];
            *(float2*)&op[i0 * DD + e] = make_float2((accB[t][0] + p0.x) * dnv0, (accB[t][1] + p0.y) * dnv0);
            *(float2*)&op[i1 * DD + e] = make_float2((accB[t][2] + p1.x) * dnv1, (accB[t][3] + p1.y) * dnv1);
        }
    }
}

// ---------------------------------------------------------------------------
extern "C" void kernel_launch(void* const* d_in, const int* in_sizes, int n_in,
                              void* d_out, int out_size) {
    const float* q  = (const float*)d_in[0];
    const float* k  = (const float*)d_in[1];
    const float* qr = (const float*)d_in[2];
    const float* kr = (const float*)d_in[3];
    const float* v  = (const float*)d_in[4];
    float* out = (float*)d_out;

    cudaFuncSetAttribute(pass1_kernel, cudaFuncAttributeMaxDynamicSharedMemorySize, P1_SMEM);
    cudaFuncSetAttribute(pass3_kernel, cudaFuncAttributeMaxDynamicSharedMemorySize, SMEM3);

    dim3 g1(NC, G);
    pass1_kernel<<<g1, 256, P1_SMEM>>>(k, kr, v);
    dim3 g2(G, 2, 8);
    pass2_kernel<<<g2, 128>>>();
    dim3 g3(NC, G);
    pass3_kernel<<<g3, 512, SMEM3>>>(q, qr, k, kr, v, out);
}

// round 11
// speedup vs baseline: 7.5529x; 1.6319x over previous
#include <cuda_runtime.h>
#include <cuda_fp16.h>
#include <stdint.h>

#define G    16
#define NSEQ 4096
#define DD   64
#define CC   128
#define NC   32

// g_Sh holds S^T in fp16 pairs: ST[e][d] = sum_j v[j][e]*k[j][d], exclusive-prefixed by pass2.
// word index = e*32 + d/2 within a chunk tile of 2048 uint32.
__device__ __align__(16) uint32_t g_Sh[2ull * G * NC * DD * DD / 2];
__device__ __align__(16) float g_ksum[2ull * G * NC * DD];

__device__ __forceinline__ uint32_t smem_u32(const void* p) {
    uint32_t a;
    asm("{ .reg .u64 t; cvta.to.shared.u64 t, %1; cvt.u32.u64 %0, t; }" : "=r"(a) : "l"(p));
    return a;
}
#define LDM4(r0, r1, r2, r3, addr) \
    asm volatile("ldmatrix.sync.aligned.m8n8.x4.shared.b16 {%0,%1,%2,%3}, [%4];" \
                 : "=r"(r0), "=r"(r1), "=r"(r2), "=r"(r3) : "r"(addr))
#define LDM4T(r0, r1, r2, r3, addr) \
    asm volatile("ldmatrix.sync.aligned.m8n8.x4.trans.shared.b16 {%0,%1,%2,%3}, [%4];" \
                 : "=r"(r0), "=r"(r1), "=r"(r2), "=r"(r3) : "r"(addr))
__device__ __forceinline__ void mma_f16(float* c, uint32_t a0, uint32_t a1, uint32_t a2, uint32_t a3,
                                        uint32_t b0, uint32_t b1) {
    asm("mma.sync.aligned.m16n8k16.row.col.f32.f16.f16.f32 "
        "{%0,%1,%2,%3},{%4,%5,%6,%7},{%8,%9},{%0,%1,%2,%3};"
        : "+f"(c[0]), "+f"(c[1]), "+f"(c[2]), "+f"(c[3])
        : "r"(a0), "r"(a1), "r"(a2), "r"(a3), "r"(b0), "r"(b1));
}
__device__ __forceinline__ uint32_t packh2(float x, float y) {
    __half2 h = __floats2half2_rn(x, y);
    return *(uint32_t*)&h;
}

// ===========================================================================
// Pass 1 (fp16): ST_m[e][d] = sum_j v[j][e] k_m[j][d]; ksum exact f32.
// Row-major fp16 tiles, pitch 36 words: VH 0, K1H 4608, K2H 9216 -> 13824 w
// ===========================================================================
#define P1_SMEM (13824 * 4)
__global__ __launch_bounds__(256) void pass1_kernel(const float* __restrict__ k1g,
                                                    const float* __restrict__ k2g,
                                                    const float* __restrict__ vg) {
    extern __shared__ uint32_t smw[];
    const int c = blockIdx.x, g = blockIdx.y;
    const int tid = threadIdx.x, w = tid >> 5, lane = tid & 31;
    const int gq = lane >> 2, tq = lane & 3;
    const size_t cbase = ((size_t)g * NSEQ + (size_t)c * CC) * DD;

    {
        const float2* vp  = (const float2*)(vg + cbase);
        const float2* k1p = (const float2*)(k1g + cbase);
        const float2* k2p = (const float2*)(k2g + cbase);
        #pragma unroll
        for (int it = 0; it < 16; it++) {
            int idx = it * 256 + tid;
            int off = (idx >> 5) * 36 + (idx & 31);
            float2 xv;
            xv = vp[idx];  smw[off]        = packh2(xv.x, xv.y);
            xv = k1p[idx]; smw[4608 + off] = packh2(xv.x, xv.y);
            xv = k2p[idx]; smw[9216 + off] = packh2(xv.x, xv.y);
        }
    }
    if (tid < 128) {
        int m = tid >> 6, d = tid & 63;
        const float* kp = (m ? k2g : k1g) + cbase;
        float s = 0.f;
        #pragma unroll 8
        for (int j = 0; j < CC; j++) s += kp[j * DD + d];
        g_ksum[(((size_t)m * G + g) * NC + c) * DD + d] = s;
    }
    __syncthreads();

    const int band = (w >> 1) * 16, nh = w & 1;
    const uint32_t sbase = smem_u32(smw);
    const uint32_t lt = ((lane & 7) + ((lane >> 4) & 1) * 8) * 144 + ((lane >> 3) & 1) * 16;
    const uint32_t avh = sbase + lt + (uint32_t)band * 2;   // A = v^T, m = e

    float accP[2][4][4];
    #pragma unroll
    for (int m = 0; m < 2; m++)
        #pragma unroll
        for (int t = 0; t < 4; t++)
            #pragma unroll
            for (int u = 0; u < 4; u++) accP[m][t][u] = 0.f;

    #pragma unroll
    for (int m = 0; m < 2; m++) {
        const uint32_t bkh = sbase + (m ? 9216u : 4608u) * 4 + lt + (uint32_t)nh * 64;
        #pragma unroll 1
        for (int kk = 0; kk < 8; kk++) {
            uint32_t ah0, ah1, ah2, ah3;
            LDM4T(ah0, ah1, ah2, ah3, avh + kk * 2304);
            #pragma unroll
            for (int p = 0; p < 2; p++) {
                uint32_t bh0, bh1, bh2, bh3;
                LDM4T(bh0, bh1, bh2, bh3, bkh + p * 32 + kk * 2304);
                mma_f16(accP[m][2 * p],     ah0, ah1, ah2, ah3, bh0, bh2);
                mma_f16(accP[m][2 * p + 1], ah0, ah1, ah2, ah3, bh1, bh3);
            }
        }
    }
    #pragma unroll
    for (int m = 0; m < 2; m++) {
        uint32_t* Sp = &g_Sh[(((size_t)m * G + g) * NC + c) * 2048];
        #pragma unroll
        for (int t = 0; t < 4; t++) {
            int wcol = nh * 16 + t * 4 + tq;  // (d-pair) word column
            int e0 = band + gq;
            Sp[e0 * 32 + wcol]       = packh2(accP[m][t][0], accP[m][t][1]);
            Sp[(e0 + 8) * 32 + wcol] = packh2(accP[m][t][2], accP[m][t][3]);
        }
    }
}

// ===========================================================================
// Pass 2: exclusive prefix over chunks on fp16 storage, f32 running sums.
// grid (G,2,8) x 128 thr; each thread scans one uint2 (4 halves) lane.
// ===========================================================================
__global__ __launch_bounds__(128) void pass2_kernel() {
    const int g = blockIdx.x, m = blockIdx.y, h = blockIdx.z, tid = threadIdx.x;
    uint32_t* base = g_Sh + (((size_t)m * G + g) * NC) * 2048 + ((size_t)(h * 128 + tid)) * 2;
    float4 run = make_float4(0.f, 0.f, 0.f, 0.f);
    uint2 cur = *(uint2*)base;
    #pragma unroll 1
    for (int c = 0; c < NC; c++) {
        uint2 nxt = make_uint2(0u, 0u);
        if (c + 1 < NC) nxt = *(uint2*)(base + (size_t)(c + 1) * 2048);
        uint2 wv;
        wv.x = packh2(run.x, run.y);
        wv.y = packh2(run.z, run.w);
        *(uint2*)(base + (size_t)c * 2048) = wv;
        __half2 a = *(__half2*)&cur.x, b = *(__half2*)&cur.y;
        run.x += __low2float(a); run.y += __high2float(a);
        run.z += __low2float(b); run.w += __high2float(b);
        cur = nxt;
    }
    if (h == 0 && tid < DD) {
        float* kb = &g_ksum[(((size_t)m * G + g) * NC) * DD];
        float r = 0.f, cu = kb[tid];
        #pragma unroll 1
        for (int c = 0; c < NC; c++) {
            float nx = (c + 1 < NC) ? kb[(c + 1) * DD + tid] : 0.f;
            kb[c * DD + tid] = r;
            r += cu; cu = nx;
        }
    }
}

// ===========================================================================
// Pass 3 (fp16, causal-sparse, 512 thr / 16 warps, 2 CTAs/SM).
// Word offsets: QH 0 (128x68)  KH 8704 (128x68)  VH 17408 (128x36)
//   SH 22016 (64x68)  QKP 26368  KP 26496  DEN 26624(256) -> 26880 w
// RED (128x64 f32) aliases KH after stage A.
// ===========================================================================
#define B_KH  34816u
#define B_VH  69632u
#define B_SH  88064u
#define W_KH  8704
#define W_VH  17408
#define W_SH  22016
#define W_QKP 26368
#define W_KP  26496
#define W_DEN 26624
#define W_RED W_KH
#define SMEM3 (26880 * 4)

__global__ __launch_bounds__(512) void pass3_kernel(const float* __restrict__ q1g,
                                                    const float* __restrict__ q2g,
                                                    const float* __restrict__ k1g,
                                                    const float* __restrict__ k2g,
                                                    const float* __restrict__ vg,
                                                    float* __restrict__ outg) {
    extern __shared__ uint32_t smw[];
    const int c = blockIdx.x, g = blockIdx.y, tid = threadIdx.x;
    const int w = tid >> 5, lane = tid & 31;
    const int gq = lane >> 2, tq = lane & 3;
    const int band = (w >> 1) * 16, nh = w & 1;
    const int ilast = band + 15;
    const size_t cbase = ((size_t)g * NSEQ + (size_t)c * CC) * DD;
    float* QKPf = (float*)(smw + W_QKP);
    float* KPf  = (float*)(smw + W_KP);
    float* DENf = (float*)(smw + W_DEN);
    float* REDf = (float*)(smw + W_RED);

    // ---- stage fp16 tiles (coalesced row-major) ----
    {
        const float2* q1p = (const float2*)(q1g + cbase);
        const float2* q2p = (const float2*)(q2g + cbase);
        const float2* k1p = (const float2*)(k1g + cbase);
        const float2* k2p = (const float2*)(k2g + cbase);
        const float2* vp  = (const float2*)(vg + cbase);
        #pragma unroll
        for (int it = 0; it < 8; it++) {
            int idx = it * 512 + tid;
            int off = (idx >> 5) * 68 + (idx & 31);
            int offv = (idx >> 5) * 36 + (idx & 31);
            float2 xv;
            xv = q1p[idx]; smw[off]             = packh2(xv.x, xv.y);
            xv = q2p[idx]; smw[off + 32]        = packh2(xv.x, xv.y);
            xv = k1p[idx]; smw[W_KH + off]      = packh2(xv.x, xv.y);
            xv = k2p[idx]; smw[W_KH + off + 32] = packh2(xv.x, xv.y);
            xv = vp[idx];  smw[W_VH + offv]     = packh2(xv.x, xv.y);
        }
        const uint32_t* s1p = &g_Sh[(((size_t)0 * G + g) * NC + c) * 2048];
        const uint32_t* s2p = &g_Sh[(((size_t)1 * G + g) * NC + c) * 2048];
        #pragma unroll
        for (int it = 0; it < 4; it++) {
            int idx = it * 512 + tid;
            int off = (idx >> 5) * 68 + (idx & 31);
            smw[W_SH + off]      = s1p[idx];
            smw[W_SH + off + 32] = s2p[idx];
        }
        if (tid < DD) {
            KPf[tid]      = g_ksum[(((size_t)0 * G + g) * NC + c) * DD + tid];
            KPf[64 + tid] = g_ksum[(((size_t)1 * G + g) * NC + c) * DD + tid];
        }
    }
    __syncthreads();

    // qkpre from staged fp16 q (overlaps MMA warps)
    if (tid < CC) {
        float a = 0.f;
        #pragma unroll 8
        for (int wd = 0; wd < 64; wd++) {
            uint32_t qw = smw[tid * 68 + wd];
            __half2 h = *(__half2*)&qw;
            a += __low2float(h) * KPf[2 * wd] + __high2float(h) * KPf[2 * wd + 1];
        }
        QKPf[tid] = a;
    }

    const uint32_t sbase = smem_u32(smw);
    const uint32_t laneoff = ((lane & 7) + ((lane >> 3) & 1) * 8) * 272 + ((lane >> 4) & 1) * 16;
    const uint32_t lt = ((lane & 7) + ((lane >> 4) & 1) * 8) * 144 + ((lane >> 3) & 1) * 16;
    const uint32_t aqh = sbase + band * 272 + laneoff;

    // ---- Stage A: T[band rows][nh col-half], skipping blocks above diagonal ----
    float accA[8][4];
    #pragma unroll
    for (int t = 0; t < 8; t++)
        #pragma unroll
        for (int u = 0; u < 4; u++) accA[t][u] = 0.f;
    if (nh * 64 <= ilast) {
        const uint32_t bkh = sbase + B_KH + (uint32_t)nh * 17408u + laneoff;
        #pragma unroll 1
        for (int kk = 0; kk < 8; kk++) {
            uint32_t ah0, ah1, ah2, ah3;
            LDM4(ah0, ah1, ah2, ah3, aqh + kk * 32);
            #pragma unroll
            for (int p = 0; p < 4; p++) {
                if (nh * 64 + p * 16 <= ilast) {
                    uint32_t bh0, bh1, bh2, bh3;
                    LDM4(bh0, bh1, bh2, bh3, bkh + p * 4352 + kk * 32);
                    mma_f16(accA[2 * p],     ah0, ah1, ah2, ah3, bh0, bh2);
                    mma_f16(accA[2 * p + 1], ah0, ah1, ah2, ah3, bh1, bh3);
                }
            }
        }
    }

    // ---- epilogue A: mask, partial row sums, pack T into fp16 A-fragments ----
    const int i0 = band + gq, i1 = i0 + 8;
    uint32_t thA[4][4];
    #pragma unroll
    for (int t = 0; t < 4; t++)
        #pragma unroll
        for (int u = 0; u < 4; u++) thA[t][u] = 0u;
    float rs0 = 0.f, rs1 = 0.f;
    #pragma unroll
    for (int kkt = 0; kkt < 4; kkt++) {
        if (nh * 64 + kkt * 16 <= ilast) {
            int ce = nh * 64 + kkt * 16 + tq * 2, co = ce + 8;
            float e00 = (ce <= i0) ? accA[2 * kkt][0] : 0.f;
            float e01 = (ce + 1 <= i0) ? accA[2 * kkt][1] : 0.f;
            float e10 = (ce <= i1) ? accA[2 * kkt][2] : 0.f;
            float e11 = (ce + 1 <= i1) ? accA[2 * kkt][3] : 0.f;
            float o00 = (co <= i0) ? accA[2 * kkt + 1][0] : 0.f;
            float o01 = (co + 1 <= i0) ? accA[2 * kkt + 1][1] : 0.f;
            float o10 = (co <= i1) ? accA[2 * kkt + 1][2] : 0.f;
            float o11 = (co + 1 <= i1) ? accA[2 * kkt + 1][3] : 0.f;
            rs0 += e00 + e01 + o00 + o01;
            rs1 += e10 + e11 + o10 + o11;
            thA[kkt][0] = packh2(e00, e01);
            thA[kkt][1] = packh2(e10, e11);
            thA[kkt][2] = packh2(o00, o01);
            thA[kkt][3] = packh2(o10, o11);
        }
    }
    rs0 += __shfl_xor_sync(0xFFFFFFFFu, rs0, 1);
    rs0 += __shfl_xor_sync(0xFFFFFFFFu, rs0, 2);
    rs1 += __shfl_xor_sync(0xFFFFFFFFu, rs1, 1);
    rs1 += __shfl_xor_sync(0xFFFFFFFFu, rs1, 2);
    if (tq == 0) {
        DENf[i0 * 2 + nh] = rs0;
        DENf[i1 * 2 + nh] = rs1;
    }
    __syncthreads();   // K reads done (RED aliases K); DEN + QKP visible

    // ---- Stage B partials: T v (own j-half, causal-sparse) + q Scat (own kk-half) ----
    float accB[8][4];
    #pragma unroll
    for (int t = 0; t < 8; t++)
        #pragma unroll
        for (int u = 0; u < 4; u++) accB[t][u] = 0.f;
    {
        const uint32_t bvh = sbase + B_VH + (uint32_t)nh * 9216u + lt;
        #pragma unroll
        for (int kkt = 0; kkt < 4; kkt++) {
            if (nh * 64 + kkt * 16 <= ilast) {
                #pragma unroll
                for (int p = 0; p < 4; p++) {
                    uint32_t bh0, bh1, bh2, bh3;
                    LDM4T(bh0, bh1, bh2, bh3, bvh + kkt * 2304 + p * 32);
                    mma_f16(accB[2 * p],     thA[kkt][0], thA[kkt][1], thA[kkt][2], thA[kkt][3], bh0, bh2);
                    mma_f16(accB[2 * p + 1], thA[kkt][0], thA[kkt][1], thA[kkt][2], thA[kkt][3], bh1, bh3);
                }
            }
        }
        const uint32_t bsh = sbase + B_SH + laneoff;
        #pragma unroll 1
        for (int kkl = 0; kkl < 4; kkl++) {
            int kk = nh * 4 + kkl;
            uint32_t ah0, ah1, ah2, ah3;
            LDM4(ah0, ah1, ah2, ah3, aqh + kk * 32);
            #pragma unroll
            for (int p = 0; p < 4; p++) {
                uint32_t bh0, bh1, bh2, bh3;
                LDM4(bh0, bh1, bh2, bh3, bsh + p * 4352 + kk * 32);
                mma_f16(accB[2 * p],     ah0, ah1, ah2, ah3, bh0, bh2);
                mma_f16(accB[2 * p + 1], ah0, ah1, ah2, ah3, bh1, bh3);
            }
        }
    }

    // ---- cross-warp reduction + epilogue ----
    if (nh == 1) {
        #pragma unroll
        for (int t = 0; t < 8; t++) {
            int e = t * 8 + tq * 2;
            *(float2*)&REDf[i0 * 64 + e] = make_float2(accB[t][0], accB[t][1]);
            *(float2*)&REDf[i1 * 64 + e] = make_float2(accB[t][2], accB[t][3]);
        }
    }
    __syncthreads();
    if (nh == 0) {
        float dnv0 = 1.0f / (DENf[i0 * 2] + DENf[i0 * 2 + 1] + QKPf[i0] + 1e-10f);
        float dnv1 = 1.0f / (DENf[i1 * 2] + DENf[i1 * 2 + 1] + QKPf[i1] + 1e-10f);
        float* op = outg + cbase;
        #pragma unroll
        for (int t = 0; t < 8; t++) {
            int e = t * 8 + tq * 2;
            float2 p0 = *(const float2*)&REDf[i0 * 64 + e];
            float2 p1 = *(const float2*)&REDf[i1 * 64 + e];
            *(float2*)&op[i0 * DD + e] = make_float2((accB[t][0] + p0.x) * dnv0, (accB[t][1] + p0.y) * dnv0);
            *(float2*)&op[i1 * DD + e] = make_float2((accB[t][2] + p1.x) * dnv1, (accB[t][3] + p1.y) * dnv1);
        }
    }
}

// ---------------------------------------------------------------------------
extern "C" void kernel_launch(void* const* d_in, const int* in_sizes, int n_in,
                              void* d_out, int out_size) {
    const float* q  = (const float*)d_in[0];
    const float* k  = (const float*)d_in[1];
    const float* qr = (const float*)d_in[2];
    const float* kr = (const float*)d_in[3];
    const float* v  = (const float*)d_in[4];
    float* out = (float*)d_out;

    cudaFuncSetAttribute(pass1_kernel, cudaFuncAttributeMaxDynamicSharedMemorySize, P1_SMEM);
    cudaFuncSetAttribute(pass3_kernel, cudaFuncAttributeMaxDynamicSharedMemorySize, SMEM3);

    dim3 g1(NC, G);
    pass1_kernel<<<g1, 256, P1_SMEM>>>(k, kr, v);
    dim3 g2(G, 2, 8);
    pass2_kernel<<<g2, 128>>>();
    dim3 g3(NC, G);
    pass3_kernel<<<g3, 512, SMEM3>>>(q, qr, k, kr, v, out);
}

// round 12
// speedup vs baseline: 9.2808x; 1.2288x over previous
#include <cuda_runtime.h>
#include <cuda_fp16.h>
#include <stdint.h>

#define G    16
#define NSEQ 4096
#define DD   64
#define CC   128
#define NC   32

// g_Sh holds S^T in fp16 pairs: ST[e][d] = sum_j v[j][e]*k[j][d], exclusive-prefixed by pass2.
// word index = e*32 + d/2 within a chunk tile of 2048 uint32.
__device__ __align__(16) uint32_t g_Sh[2ull * G * NC * DD * DD / 2];
__device__ __align__(16) float g_ksum[2ull * G * NC * DD];

__device__ __forceinline__ uint32_t smem_u32(const void* p) {
    uint32_t a;
    asm("{ .reg .u64 t; cvta.to.shared.u64 t, %1; cvt.u32.u64 %0, t; }" : "=r"(a) : "l"(p));
    return a;
}
#define LDM4(r0, r1, r2, r3, addr) \
    asm volatile("ldmatrix.sync.aligned.m8n8.x4.shared.b16 {%0,%1,%2,%3}, [%4];" \
                 : "=r"(r0), "=r"(r1), "=r"(r2), "=r"(r3) : "r"(addr))
#define LDM4T(r0, r1, r2, r3, addr) \
    asm volatile("ldmatrix.sync.aligned.m8n8.x4.trans.shared.b16 {%0,%1,%2,%3}, [%4];" \
                 : "=r"(r0), "=r"(r1), "=r"(r2), "=r"(r3) : "r"(addr))
__device__ __forceinline__ void mma_f16(float* c, uint32_t a0, uint32_t a1, uint32_t a2, uint32_t a3,
                                        uint32_t b0, uint32_t b1) {
    asm("mma.sync.aligned.m16n8k16.row.col.f32.f16.f16.f32 "
        "{%0,%1,%2,%3},{%4,%5,%6,%7},{%8,%9},{%0,%1,%2,%3};"
        : "+f"(c[0]), "+f"(c[1]), "+f"(c[2]), "+f"(c[3])
        : "r"(a0), "r"(a1), "r"(a2), "r"(a3), "r"(b0), "r"(b1));
}
__device__ __forceinline__ uint32_t packh2(float x, float y) {
    __half2 h = __floats2half2_rn(x, y);
    return *(uint32_t*)&h;
}

// ===========================================================================
// Pass 1 (fp16): ST_m[e][d] = sum_j v[j][e] k_m[j][d]; ksum from staged fp16.
// Row-major fp16 tiles, pitch 36 words: VH 0, K1H 4608, K2H 9216 -> 13824 w
// ===========================================================================
#define P1_SMEM (13824 * 4)
__global__ __launch_bounds__(256) void pass1_kernel(const float* __restrict__ k1g,
                                                    const float* __restrict__ k2g,
                                                    const float* __restrict__ vg) {
    extern __shared__ uint32_t smw[];
    const int c = blockIdx.x, g = blockIdx.y;
    const int tid = threadIdx.x, w = tid >> 5, lane = tid & 31;
    const int gq = lane >> 2, tq = lane & 3;
    const size_t cbase = ((size_t)g * NSEQ + (size_t)c * CC) * DD;

    {
        const float2* vp  = (const float2*)(vg + cbase);
        const float2* k1p = (const float2*)(k1g + cbase);
        const float2* k2p = (const float2*)(k2g + cbase);
        #pragma unroll
        for (int it = 0; it < 16; it++) {
            int idx = it * 256 + tid;
            int off = (idx >> 5) * 36 + (idx & 31);
            float2 xv;
            xv = vp[idx];  smw[off]        = packh2(xv.x, xv.y);
            xv = k1p[idx]; smw[4608 + off] = packh2(xv.x, xv.y);
            xv = k2p[idx]; smw[9216 + off] = packh2(xv.x, xv.y);
        }
    }
    __syncthreads();

    // ksum from staged fp16 k tiles (denominator-only error ~2^-12)
    if (tid < 128) {
        int m = tid >> 6, d = tid & 63;
        const uint32_t* kb = smw + (m ? 9216 : 4608) + (d >> 1);
        int hi = d & 1;
        float s = 0.f;
        #pragma unroll 16
        for (int j = 0; j < CC; j++) {
            __half2 h = *(const __half2*)&kb[j * 36];
            s += hi ? __high2float(h) : __low2float(h);
        }
        g_ksum[(((size_t)m * G + g) * NC + c) * DD + d] = s;
    }

    const int band = (w >> 1) * 16, nh = w & 1;
    const uint32_t sbase = smem_u32(smw);
    const uint32_t lt = ((lane & 7) + ((lane >> 4) & 1) * 8) * 144 + ((lane >> 3) & 1) * 16;
    const uint32_t avh = sbase + lt + (uint32_t)band * 2;   // A = v^T, m = e

    float accP[2][4][4];
    #pragma unroll
    for (int m = 0; m < 2; m++)
        #pragma unroll
        for (int t = 0; t < 4; t++)
            #pragma unroll
            for (int u = 0; u < 4; u++) accP[m][t][u] = 0.f;

    #pragma unroll
    for (int m = 0; m < 2; m++) {
        const uint32_t bkh = sbase + (m ? 9216u : 4608u) * 4 + lt + (uint32_t)nh * 64;
        #pragma unroll 1
        for (int kk = 0; kk < 8; kk++) {
            uint32_t ah0, ah1, ah2, ah3;
            LDM4T(ah0, ah1, ah2, ah3, avh + kk * 2304);
            #pragma unroll
            for (int p = 0; p < 2; p++) {
                uint32_t bh0, bh1, bh2, bh3;
                LDM4T(bh0, bh1, bh2, bh3, bkh + p * 32 + kk * 2304);
                mma_f16(accP[m][2 * p],     ah0, ah1, ah2, ah3, bh0, bh2);
                mma_f16(accP[m][2 * p + 1], ah0, ah1, ah2, ah3, bh1, bh3);
            }
        }
    }
    #pragma unroll
    for (int m = 0; m < 2; m++) {
        uint32_t* Sp = &g_Sh[(((size_t)m * G + g) * NC + c) * 2048];
        #pragma unroll
        for (int t = 0; t < 4; t++) {
            int wcol = nh * 16 + t * 4 + tq;  // (d-pair) word column
            int e0 = band + gq;
            Sp[e0 * 32 + wcol]       = packh2(accP[m][t][0], accP[m][t][1]);
            Sp[(e0 + 8) * 32 + wcol] = packh2(accP[m][t][2], accP[m][t][3]);
        }
    }
}

// ===========================================================================
// Pass 2: exclusive prefix over chunks on fp16 storage, f32 running sums.
// Prefetch depth 4 to hide the dependent-load chain.
// ===========================================================================
__global__ __launch_bounds__(128) void pass2_kernel() {
    const int g = blockIdx.x, m = blockIdx.y, h = blockIdx.z, tid = threadIdx.x;
    uint32_t* base = g_Sh + (((size_t)m * G + g) * NC) * 2048 + ((size_t)(h * 128 + tid)) * 2;
    float4 run = make_float4(0.f, 0.f, 0.f, 0.f);
    uint2 buf[4];
    #pragma unroll
    for (int i = 0; i < 4; i++) buf[i] = *(uint2*)(base + (size_t)i * 2048);
    #pragma unroll 4
    for (int c = 0; c < NC; c++) {
        uint2 cur = buf[c & 3];
        if (c + 4 < NC) buf[c & 3] = *(uint2*)(base + (size_t)(c + 4) * 2048);
        uint2 wv;
        wv.x = packh2(run.x, run.y);
        wv.y = packh2(run.z, run.w);
        *(uint2*)(base + (size_t)c * 2048) = wv;
        __half2 a = *(__half2*)&cur.x, b = *(__half2*)&cur.y;
        run.x += __low2float(a); run.y += __high2float(a);
        run.z += __low2float(b); run.w += __high2float(b);
    }
    if (h == 0 && tid < DD) {
        float* kb = &g_ksum[(((size_t)m * G + g) * NC) * DD];
        float fb[4];
        #pragma unroll
        for (int i = 0; i < 4; i++) fb[i] = kb[i * DD + tid];
        float r = 0.f;
        #pragma unroll 4
        for (int c = 0; c < NC; c++) {
            float cu = fb[c & 3];
            if (c + 4 < NC) fb[c & 3] = kb[(c + 4) * DD + tid];
            kb[c * DD + tid] = r;
            r += cu;
        }
    }
}

// ===========================================================================
// Pass 3 (fp16, causal-sparse, 512 thr / 16 warps, 2 CTAs/SM).
// Word offsets: QH 0 (128x68)  KH 8704 (128x68)  VH 17408 (128x36)
//   SH 22016 (64x68)  QKP 26368  KP 26496  DEN 26624(256) -> 26880 w
// RED (128x64 f32) aliases KH after stage A.
// ===========================================================================
#define B_KH  34816u
#define B_VH  69632u
#define B_SH  88064u
#define W_KH  8704
#define W_VH  17408
#define W_SH  22016
#define W_QKP 26368
#define W_KP  26496
#define W_DEN 26624
#define W_RED W_KH
#define SMEM3 (26880 * 4)

__global__ __launch_bounds__(512) void pass3_kernel(const float* __restrict__ q1g,
                                                    const float* __restrict__ q2g,
                                                    const float* __restrict__ k1g,
                                                    const float* __restrict__ k2g,
                                                    const float* __restrict__ vg,
                                                    float* __restrict__ outg) {
    extern __shared__ uint32_t smw[];
    const int c = blockIdx.x, g = blockIdx.y, tid = threadIdx.x;
    const int w = tid >> 5, lane = tid & 31;
    const int gq = lane >> 2, tq = lane & 3;
    const int band = (w >> 1) * 16, nh = w & 1;
    const int ilast = band + 15;
    const size_t cbase = ((size_t)g * NSEQ + (size_t)c * CC) * DD;
    float* QKPf = (float*)(smw + W_QKP);
    float* KPf  = (float*)(smw + W_KP);
    float* DENf = (float*)(smw + W_DEN);
    float* REDf = (float*)(smw + W_RED);

    // ---- stage fp16 tiles (coalesced row-major) ----
    {
        const float2* q1p = (const float2*)(q1g + cbase);
        const float2* q2p = (const float2*)(q2g + cbase);
        const float2* k1p = (const float2*)(k1g + cbase);
        const float2* k2p = (const float2*)(k2g + cbase);
        const float2* vp  = (const float2*)(vg + cbase);
        #pragma unroll
        for (int it = 0; it < 8; it++) {
            int idx = it * 512 + tid;
            int off = (idx >> 5) * 68 + (idx & 31);
            int offv = (idx >> 5) * 36 + (idx & 31);
            float2 xv;
            xv = q1p[idx]; smw[off]             = packh2(xv.x, xv.y);
            xv = q2p[idx]; smw[off + 32]        = packh2(xv.x, xv.y);
            xv = k1p[idx]; smw[W_KH + off]      = packh2(xv.x, xv.y);
            xv = k2p[idx]; smw[W_KH + off + 32] = packh2(xv.x, xv.y);
            xv = vp[idx];  smw[W_VH + offv]     = packh2(xv.x, xv.y);
        }
        const uint32_t* s1p = &g_Sh[(((size_t)0 * G + g) * NC + c) * 2048];
        const uint32_t* s2p = &g_Sh[(((size_t)1 * G + g) * NC + c) * 2048];
        #pragma unroll
        for (int it = 0; it < 4; it++) {
            int idx = it * 512 + tid;
            int off = (idx >> 5) * 68 + (idx & 31);
            smw[W_SH + off]      = s1p[idx];
            smw[W_SH + off + 32] = s2p[idx];
        }
        if (tid < DD) {
            KPf[tid]      = g_ksum[(((size_t)0 * G + g) * NC + c) * DD + tid];
            KPf[64 + tid] = g_ksum[(((size_t)1 * G + g) * NC + c) * DD + tid];
        }
    }
    __syncthreads();

    // qkpre from staged fp16 q (overlaps MMA warps)
    if (tid < CC) {
        float a = 0.f;
        #pragma unroll 8
        for (int wd = 0; wd < 64; wd++) {
            uint32_t qw = smw[tid * 68 + wd];
            __half2 h = *(__half2*)&qw;
            a += __low2float(h) * KPf[2 * wd] + __high2float(h) * KPf[2 * wd + 1];
        }
        QKPf[tid] = a;
    }

    const uint32_t sbase = smem_u32(smw);
    const uint32_t laneoff = ((lane & 7) + ((lane >> 3) & 1) * 8) * 272 + ((lane >> 4) & 1) * 16;
    const uint32_t lt = ((lane & 7) + ((lane >> 4) & 1) * 8) * 144 + ((lane >> 3) & 1) * 16;
    const uint32_t aqh = sbase + band * 272 + laneoff;

    // ---- Stage A: T[band rows][nh col-half], skipping blocks above diagonal ----
    float accA[8][4];
    #pragma unroll
    for (int t = 0; t < 8; t++)
        #pragma unroll
        for (int u = 0; u < 4; u++) accA[t][u] = 0.f;
    if (nh * 64 <= ilast) {
        const uint32_t bkh = sbase + B_KH + (uint32_t)nh * 17408u + laneoff;
        #pragma unroll 1
        for (int kk = 0; kk < 8; kk++) {
            uint32_t ah0, ah1, ah2, ah3;
            LDM4(ah0, ah1, ah2, ah3, aqh + kk * 32);
            #pragma unroll
            for (int p = 0; p < 4; p++) {
                if (nh * 64 + p * 16 <= ilast) {
                    uint32_t bh0, bh1, bh2, bh3;
                    LDM4(bh0, bh1, bh2, bh3, bkh + p * 4352 + kk * 32);
                    mma_f16(accA[2 * p],     ah0, ah1, ah2, ah3, bh0, bh2);
                    mma_f16(accA[2 * p + 1], ah0, ah1, ah2, ah3, bh1, bh3);
                }
            }
        }
    }

    // ---- epilogue A: mask, partial row sums, pack T into fp16 A-fragments ----
    const int i0 = band + gq, i1 = i0 + 8;
    uint32_t thA[4][4];
    #pragma unroll
    for (int t = 0; t < 4; t++)
        #pragma unroll
        for (int u = 0; u < 4; u++) thA[t][u] = 0u;
    float rs0 = 0.f, rs1 = 0.f;
    #pragma unroll
    for (int kkt = 0; kkt < 4; kkt++) {
        if (nh * 64 + kkt * 16 <= ilast) {
            int ce = nh * 64 + kkt * 16 + tq * 2, co = ce + 8;
            float e00 = (ce <= i0) ? accA[2 * kkt][0] : 0.f;
            float e01 = (ce + 1 <= i0) ? accA[2 * kkt][1] : 0.f;
            float e10 = (ce <= i1) ? accA[2 * kkt][2] : 0.f;
            float e11 = (ce + 1 <= i1) ? accA[2 * kkt][3] : 0.f;
            float o00 = (co <= i0) ? accA[2 * kkt + 1][0] : 0.f;
            float o01 = (co + 1 <= i0) ? accA[2 * kkt + 1][1] : 0.f;
            float o10 = (co <= i1) ? accA[2 * kkt + 1][2] : 0.f;
            float o11 = (co + 1 <= i1) ? accA[2 * kkt + 1][3] : 0.f;
            rs0 += e00 + e01 + o00 + o01;
            rs1 += e10 + e11 + o10 + o11;
            thA[kkt][0] = packh2(e00, e01);
            thA[kkt][1] = packh2(e10, e11);
            thA[kkt][2] = packh2(o00, o01);
            thA[kkt][3] = packh2(o10, o11);
        }
    }
    rs0 += __shfl_xor_sync(0xFFFFFFFFu, rs0, 1);
    rs0 += __shfl_xor_sync(0xFFFFFFFFu, rs0, 2);
    rs1 += __shfl_xor_sync(0xFFFFFFFFu, rs1, 1);
    rs1 += __shfl_xor_sync(0xFFFFFFFFu, rs1, 2);
    if (tq == 0) {
        DENf[i0 * 2 + nh] = rs0;
        DENf[i1 * 2 + nh] = rs1;
    }
    __syncthreads();   // K reads done (RED aliases K); DEN + QKP visible

    // ---- Stage B partials: T v (own j-half, causal-sparse) + q Scat (own kk-half) ----
    float accB[8][4];
    #pragma unroll
    for (int t = 0; t < 8; t++)
        #pragma unroll
        for (int u = 0; u < 4; u++) accB[t][u] = 0.f;
    {
        const uint32_t bvh = sbase + B_VH + (uint32_t)nh * 9216u + lt;
        #pragma unroll
        for (int kkt = 0; kkt < 4; kkt++) {
            if (nh * 64 + kkt * 16 <= ilast) {
                #pragma unroll
                for (int p = 0; p < 4; p++) {
                    uint32_t bh0, bh1, bh2, bh3;
                    LDM4T(bh0, bh1, bh2, bh3, bvh + kkt * 2304 + p * 32);
                    mma_f16(accB[2 * p],     thA[kkt][0], thA[kkt][1], thA[kkt][2], thA[kkt][3], bh0, bh2);
                    mma_f16(accB[2 * p + 1], thA[kkt][0], thA[kkt][1], thA[kkt][2], thA[kkt][3], bh1, bh3);
                }
            }
        }
        const uint32_t bsh = sbase + B_SH + laneoff;
        #pragma unroll 1
        for (int kkl = 0; kkl < 4; kkl++) {
            int kk = nh * 4 + kkl;
            uint32_t ah0, ah1, ah2, ah3;
            LDM4(ah0, ah1, ah2, ah3, aqh + kk * 32);
            #pragma unroll
            for (int p = 0; p < 4; p++) {
                uint32_t bh0, bh1, bh2, bh3;
                LDM4(bh0, bh1, bh2, bh3, bsh + p * 4352 + kk * 32);
                mma_f16(accB[2 * p],     ah0, ah1, ah2, ah3, bh0, bh2);
                mma_f16(accB[2 * p + 1], ah0, ah1, ah2, ah3, bh1, bh3);
            }
        }
    }

    // ---- cross-warp reduction + epilogue ----
    if (nh == 1) {
        #pragma unroll
        for (int t = 0; t < 8; t++) {
            int e = t * 8 + tq * 2;
            *(float2*)&REDf[i0 * 64 + e] = make_float2(accB[t][0], accB[t][1]);
            *(float2*)&REDf[i1 * 64 + e] = make_float2(accB[t][2], accB[t][3]);
        }
    }
    __syncthreads();
    if (nh == 0) {
        float dnv0 = 1.0f / (DENf[i0 * 2] + DENf[i0 * 2 + 1] + QKPf[i0] + 1e-10f);
        float dnv1 = 1.0f / (DENf[i1 * 2] + DENf[i1 * 2 + 1] + QKPf[i1] + 1e-10f);
        float* op = outg + cbase;
        #pragma unroll
        for (int t = 0; t < 8; t++) {
            int e = t * 8 + tq * 2;
            float2 p0 = *(const float2*)&REDf[i0 * 64 + e];
            float2 p1 = *(const float2*)&REDf[i1 * 64 + e];
            *(float2*)&op[i0 * DD + e] = make_float2((accB[t][0] + p0.x) * dnv0, (accB[t][1] + p0.y) * dnv0);
            *(float2*)&op[i1 * DD + e] = make_float2((accB[t][2] + p1.x) * dnv1, (accB[t][3] + p1.y) * dnv1);
        }
    }
}

// ---------------------------------------------------------------------------
extern "C" void kernel_launch(void* const* d_in, const int* in_sizes, int n_in,
                              void* d_out, int out_size) {
    const float* q  = (const float*)d_in[0];
    const float* k  = (const float*)d_in[1];
    const float* qr = (const float*)d_in[2];
    const float* kr = (const float*)d_in[3];
    const float* v  = (const float*)d_in[4];
    float* out = (float*)d_out;

    cudaFuncSetAttribute(pass1_kernel, cudaFuncAttributeMaxDynamicSharedMemorySize, P1_SMEM);
    cudaFuncSetAttribute(pass3_kernel, cudaFuncAttributeMaxDynamicSharedMemorySize, SMEM3);

    dim3 g1(NC, G);
    pass1_kernel<<<g1, 256, P1_SMEM>>>(k, kr, v);
    dim3 g2(G, 2, 8);
    pass2_kernel<<<g2, 128>>>();
    dim3 g3(NC, G);
    pass3_kernel<<<g3, 512, SMEM3>>>(q, qr, k, kr, v, out);
}

// round 13
// speedup vs baseline: 9.6429x; 1.0390x over previous
#include <cuda_runtime.h>
#include <cuda_fp16.h>
#include <stdint.h>

#define G    16
#define NSEQ 4096
#define DD   64
#define CC   128
#define NC   32

// g_Sh holds S^T in fp16 pairs: ST[e][d] = sum_j v[j][e]*k[j][d], exclusive-prefixed by pass2.
// word index = e*32 + d/2 within a chunk tile of 2048 uint32.
__device__ __align__(16) uint32_t g_Sh[2ull * G * NC * DD * DD / 2];
__device__ __align__(16) float g_ksum[2ull * G * NC * DD];

__device__ __forceinline__ uint32_t smem_u32(const void* p) {
    uint32_t a;
    asm("{ .reg .u64 t; cvta.to.shared.u64 t, %1; cvt.u32.u64 %0, t; }" : "=r"(a) : "l"(p));
    return a;
}
#define LDM4(r0, r1, r2, r3, addr) \
    asm volatile("ldmatrix.sync.aligned.m8n8.x4.shared.b16 {%0,%1,%2,%3}, [%4];" \
                 : "=r"(r0), "=r"(r1), "=r"(r2), "=r"(r3) : "r"(addr))
#define LDM4T(r0, r1, r2, r3, addr) \
    asm volatile("ldmatrix.sync.aligned.m8n8.x4.trans.shared.b16 {%0,%1,%2,%3}, [%4];" \
                 : "=r"(r0), "=r"(r1), "=r"(r2), "=r"(r3) : "r"(addr))
__device__ __forceinline__ void mma_f16(float* c, uint32_t a0, uint32_t a1, uint32_t a2, uint32_t a3,
                                        uint32_t b0, uint32_t b1) {
    asm("mma.sync.aligned.m16n8k16.row.col.f32.f16.f16.f32 "
        "{%0,%1,%2,%3},{%4,%5,%6,%7},{%8,%9},{%0,%1,%2,%3};"
        : "+f"(c[0]), "+f"(c[1]), "+f"(c[2]), "+f"(c[3])
        : "r"(a0), "r"(a1), "r"(a2), "r"(a3), "r"(b0), "r"(b1));
}
__device__ __forceinline__ uint32_t packh2(float x, float y) {
    __half2 h = __floats2half2_rn(x, y);
    return *(uint32_t*)&h;
}

// ===========================================================================
// Pass 1 (fp16): ST_m[e][d] = sum_j v[j][e] k_m[j][d]; ksum from staged fp16.
// Row-major fp16 tiles, pitch 36 words: VH 0, K1H 4608, K2H 9216 -> 13824 w
// ===========================================================================
#define P1_SMEM (13824 * 4)
__global__ __launch_bounds__(256) void pass1_kernel(const float* __restrict__ k1g,
                                                    const float* __restrict__ k2g,
                                                    const float* __restrict__ vg) {
    extern __shared__ uint32_t smw[];
    const int c = blockIdx.x, g = blockIdx.y;
    const int tid = threadIdx.x, w = tid >> 5, lane = tid & 31;
    const int gq = lane >> 2, tq = lane & 3;
    const size_t cbase = ((size_t)g * NSEQ + (size_t)c * CC) * DD;

    {   // float4 staging: 2048 float4 per tensor, 8 iters x 256 thr
        const float4* vp  = (const float4*)(vg + cbase);
        const float4* k1p = (const float4*)(k1g + cbase);
        const float4* k2p = (const float4*)(k2g + cbase);
        #pragma unroll
        for (int it = 0; it < 8; it++) {
            int idx4 = it * 256 + tid;
            int wi = idx4 * 2;
            int off = (wi >> 5) * 36 + (wi & 31);
            float4 xv;
            xv = vp[idx4];
            smw[off]     = packh2(xv.x, xv.y);
            smw[off + 1] = packh2(xv.z, xv.w);
            xv = k1p[idx4];
            smw[4608 + off]     = packh2(xv.x, xv.y);
            smw[4608 + off + 1] = packh2(xv.z, xv.w);
            xv = k2p[idx4];
            smw[9216 + off]     = packh2(xv.x, xv.y);
            smw[9216 + off + 1] = packh2(xv.z, xv.w);
        }
    }
    __syncthreads();

    // ksum from staged fp16 k tiles (denominator-only error ~2^-12)
    if (tid < 128) {
        int m = tid >> 6, d = tid & 63;
        const uint32_t* kb = smw + (m ? 9216 : 4608) + (d >> 1);
        int hi = d & 1;
        float s = 0.f;
        #pragma unroll 16
        for (int j = 0; j < CC; j++) {
            __half2 h = *(const __half2*)&kb[j * 36];
            s += hi ? __high2float(h) : __low2float(h);
        }
        g_ksum[(((size_t)m * G + g) * NC + c) * DD + d] = s;
    }

    const int band = (w >> 1) * 16, nh = w & 1;
    const uint32_t sbase = smem_u32(smw);
    const uint32_t lt = ((lane & 7) + ((lane >> 4) & 1) * 8) * 144 + ((lane >> 3) & 1) * 16;
    const uint32_t avh = sbase + lt + (uint32_t)band * 2;   // A = v^T, m = e

    float accP[2][4][4];
    #pragma unroll
    for (int m = 0; m < 2; m++)
        #pragma unroll
        for (int t = 0; t < 4; t++)
            #pragma unroll
            for (int u = 0; u < 4; u++) accP[m][t][u] = 0.f;

    #pragma unroll
    for (int m = 0; m < 2; m++) {
        const uint32_t bkh = sbase + (m ? 9216u : 4608u) * 4 + lt + (uint32_t)nh * 64;
        #pragma unroll 1
        for (int kk = 0; kk < 8; kk++) {
            uint32_t ah0, ah1, ah2, ah3;
            LDM4T(ah0, ah1, ah2, ah3, avh + kk * 2304);
            #pragma unroll
            for (int p = 0; p < 2; p++) {
                uint32_t bh0, bh1, bh2, bh3;
                LDM4T(bh0, bh1, bh2, bh3, bkh + p * 32 + kk * 2304);
                mma_f16(accP[m][2 * p],     ah0, ah1, ah2, ah3, bh0, bh2);
                mma_f16(accP[m][2 * p + 1], ah0, ah1, ah2, ah3, bh1, bh3);
            }
        }
    }
    #pragma unroll
    for (int m = 0; m < 2; m++) {
        uint32_t* Sp = &g_Sh[(((size_t)m * G + g) * NC + c) * 2048];
        #pragma unroll
        for (int t = 0; t < 4; t++) {
            int wcol = nh * 16 + t * 4 + tq;  // (d-pair) word column
            int e0 = band + gq;
            Sp[e0 * 32 + wcol]       = packh2(accP[m][t][0], accP[m][t][1]);
            Sp[(e0 + 8) * 32 + wcol] = packh2(accP[m][t][2], accP[m][t][3]);
        }
    }
}

// ===========================================================================
// Pass 2: exclusive prefix over chunks on fp16 storage, f32 running sums.
// Prefetch depth 8 to hide the dependent-load chain.
// ===========================================================================
__global__ __launch_bounds__(128) void pass2_kernel() {
    const int g = blockIdx.x, m = blockIdx.y, h = blockIdx.z, tid = threadIdx.x;
    uint32_t* base = g_Sh + (((size_t)m * G + g) * NC) * 2048 + ((size_t)(h * 128 + tid)) * 2;
    float4 run = make_float4(0.f, 0.f, 0.f, 0.f);
    uint2 buf[8];
    #pragma unroll
    for (int i = 0; i < 8; i++) buf[i] = *(uint2*)(base + (size_t)i * 2048);
    #pragma unroll 8
    for (int c = 0; c < NC; c++) {
        uint2 cur = buf[c & 7];
        if (c + 8 < NC) buf[c & 7] = *(uint2*)(base + (size_t)(c + 8) * 2048);
        uint2 wv;
        wv.x = packh2(run.x, run.y);
        wv.y = packh2(run.z, run.w);
        *(uint2*)(base + (size_t)c * 2048) = wv;
        __half2 a = *(__half2*)&cur.x, b = *(__half2*)&cur.y;
        run.x += __low2float(a); run.y += __high2float(a);
        run.z += __low2float(b); run.w += __high2float(b);
    }
    if (h == 0 && tid < DD) {
        float* kb = &g_ksum[(((size_t)m * G + g) * NC) * DD];
        float fb[8];
        #pragma unroll
        for (int i = 0; i < 8; i++) fb[i] = kb[i * DD + tid];
        float r = 0.f;
        #pragma unroll 8
        for (int c = 0; c < NC; c++) {
            float cu = fb[c & 7];
            if (c + 8 < NC) fb[c & 7] = kb[(c + 8) * DD + tid];
            kb[c * DD + tid] = r;
            r += cu;
        }
    }
}

// ===========================================================================
// Pass 3 (fp16, causal-sparse, 512 thr / 16 warps, 2 CTAs/SM).
// Word offsets: QH 0 (128x68)  KH 8704 (128x68)  VH 17408 (128x36)
//   SH 22016 (64x68)  QKP 26368  KP 26496  DEN 26624(256) -> 26880 w
// RED (128x64 f32) aliases KH after stage A.
// ===========================================================================
#define B_KH  34816u
#define B_VH  69632u
#define B_SH  88064u
#define W_KH  8704
#define W_VH  17408
#define W_SH  22016
#define W_QKP 26368
#define W_KP  26496
#define W_DEN 26624
#define W_RED W_KH
#define SMEM3 (26880 * 4)

__global__ __launch_bounds__(512) void pass3_kernel(const float* __restrict__ q1g,
                                                    const float* __restrict__ q2g,
                                                    const float* __restrict__ k1g,
                                                    const float* __restrict__ k2g,
                                                    const float* __restrict__ vg,
                                                    float* __restrict__ outg) {
    extern __shared__ uint32_t smw[];
    const int c = blockIdx.x, g = blockIdx.y, tid = threadIdx.x;
    const int w = tid >> 5, lane = tid & 31;
    const int gq = lane >> 2, tq = lane & 3;
    const int band = (w >> 1) * 16, nh = w & 1;
    const int ilast = band + 15;
    const size_t cbase = ((size_t)g * NSEQ + (size_t)c * CC) * DD;
    float* QKPf = (float*)(smw + W_QKP);
    float* KPf  = (float*)(smw + W_KP);
    float* DENf = (float*)(smw + W_DEN);
    float* REDf = (float*)(smw + W_RED);

    // ---- stage fp16 tiles (float4 loads, coalesced row-major) ----
    {
        const float4* q1p = (const float4*)(q1g + cbase);
        const float4* q2p = (const float4*)(q2g + cbase);
        const float4* k1p = (const float4*)(k1g + cbase);
        const float4* k2p = (const float4*)(k2g + cbase);
        const float4* vp  = (const float4*)(vg + cbase);
        #pragma unroll
        for (int it = 0; it < 4; it++) {
            int idx4 = it * 512 + tid;
            int wi = idx4 * 2;
            int off = (wi >> 5) * 68 + (wi & 31);
            int offv = (wi >> 5) * 36 + (wi & 31);
            float4 xv;
            xv = q1p[idx4];
            smw[off]     = packh2(xv.x, xv.y);
            smw[off + 1] = packh2(xv.z, xv.w);
            xv = q2p[idx4];
            smw[off + 32] = packh2(xv.x, xv.y);
            smw[off + 33] = packh2(xv.z, xv.w);
            xv = k1p[idx4];
            smw[W_KH + off]     = packh2(xv.x, xv.y);
            smw[W_KH + off + 1] = packh2(xv.z, xv.w);
            xv = k2p[idx4];
            smw[W_KH + off + 32] = packh2(xv.x, xv.y);
            smw[W_KH + off + 33] = packh2(xv.z, xv.w);
            xv = vp[idx4];
            smw[W_VH + offv]     = packh2(xv.x, xv.y);
            smw[W_VH + offv + 1] = packh2(xv.z, xv.w);
        }
        const uint2* s1p = (const uint2*)&g_Sh[(((size_t)0 * G + g) * NC + c) * 2048];
        const uint2* s2p = (const uint2*)&g_Sh[(((size_t)1 * G + g) * NC + c) * 2048];
        #pragma unroll
        for (int it = 0; it < 2; it++) {
            int idx2 = it * 512 + tid;
            int wi = idx2 * 2;
            int off = (wi >> 5) * 68 + (wi & 31);
            uint2 xv;
            xv = s1p[idx2];
            smw[W_SH + off]     = xv.x;
            smw[W_SH + off + 1] = xv.y;
            xv = s2p[idx2];
            smw[W_SH + off + 32] = xv.x;
            smw[W_SH + off + 33] = xv.y;
        }
        if (tid < DD) {
            KPf[tid]      = g_ksum[(((size_t)0 * G + g) * NC + c) * DD + tid];
            KPf[64 + tid] = g_ksum[(((size_t)1 * G + g) * NC + c) * DD + tid];
        }
    }
    __syncthreads();

    // qkpre from staged fp16 q (overlaps MMA warps)
    if (tid < CC) {
        float a = 0.f;
        #pragma unroll 8
        for (int wd = 0; wd < 64; wd++) {
            uint32_t qw = smw[tid * 68 + wd];
            __half2 h = *(__half2*)&qw;
            a += __low2float(h) * KPf[2 * wd] + __high2float(h) * KPf[2 * wd + 1];
        }
        QKPf[tid] = a;
    }

    const uint32_t sbase = smem_u32(smw);
    const uint32_t laneoff = ((lane & 7) + ((lane >> 3) & 1) * 8) * 272 + ((lane >> 4) & 1) * 16;
    const uint32_t lt = ((lane & 7) + ((lane >> 4) & 1) * 8) * 144 + ((lane >> 3) & 1) * 16;
    const uint32_t aqh = sbase + band * 272 + laneoff;

    // ---- Stage A: T[band rows][nh col-half], skipping blocks above diagonal ----
    float accA[8][4];
    #pragma unroll
    for (int t = 0; t < 8; t++)
        #pragma unroll
        for (int u = 0; u < 4; u++) accA[t][u] = 0.f;
    if (nh * 64 <= ilast) {
        const uint32_t bkh = sbase + B_KH + (uint32_t)nh * 17408u + laneoff;
        #pragma unroll 1
        for (int kk = 0; kk < 8; kk++) {
            uint32_t ah0, ah1, ah2, ah3;
            LDM4(ah0, ah1, ah2, ah3, aqh + kk * 32);
            #pragma unroll
            for (int p = 0; p < 4; p++) {
                if (nh * 64 + p * 16 <= ilast) {
                    uint32_t bh0, bh1, bh2, bh3;
                    LDM4(bh0, bh1, bh2, bh3, bkh + p * 4352 + kk * 32);
                    mma_f16(accA[2 * p],     ah0, ah1, ah2, ah3, bh0, bh2);
                    mma_f16(accA[2 * p + 1], ah0, ah1, ah2, ah3, bh1, bh3);
                }
            }
        }
    }

    // ---- epilogue A: mask, partial row sums, pack T into fp16 A-fragments ----
    const int i0 = band + gq, i1 = i0 + 8;
    uint32_t thA[4][4];
    #pragma unroll
    for (int t = 0; t < 4; t++)
        #pragma unroll
        for (int u = 0; u < 4; u++) thA[t][u] = 0u;
    float rs0 = 0.f, rs1 = 0.f;
    #pragma unroll
    for (int kkt = 0; kkt < 4; kkt++) {
        if (nh * 64 + kkt * 16 <= ilast) {
            int ce = nh * 64 + kkt * 16 + tq * 2, co = ce + 8;
            float e00 = (ce <= i0) ? accA[2 * kkt][0] : 0.f;
            float e01 = (ce + 1 <= i0) ? accA[2 * kkt][1] : 0.f;
            float e10 = (ce <= i1) ? accA[2 * kkt][2] : 0.f;
            float e11 = (ce + 1 <= i1) ? accA[2 * kkt][3] : 0.f;
            float o00 = (co <= i0) ? accA[2 * kkt + 1][0] : 0.f;
            float o01 = (co + 1 <= i0) ? accA[2 * kkt + 1][1] : 0.f;
            float o10 = (co <= i1) ? accA[2 * kkt + 1][2] : 0.f;
            float o11 = (co + 1 <= i1) ? accA[2 * kkt + 1][3] : 0.f;
            rs0 += e00 + e01 + o00 + o01;
            rs1 += e10 + e11 + o10 + o11;
            thA[kkt][0] = packh2(e00, e01);
            thA[kkt][1] = packh2(e10, e11);
            thA[kkt][2] = packh2(o00, o01);
            thA[kkt][3] = packh2(o10, o11);
        }
    }
    rs0 += __shfl_xor_sync(0xFFFFFFFFu, rs0, 1);
    rs0 += __shfl_xor_sync(0xFFFFFFFFu, rs0, 2);
    rs1 += __shfl_xor_sync(0xFFFFFFFFu, rs1, 1);
    rs1 += __shfl_xor_sync(0xFFFFFFFFu, rs1, 2);
    if (tq == 0) {
        DENf[i0 * 2 + nh] = rs0;
        DENf[i1 * 2 + nh] = rs1;
    }
    __syncthreads();   // K reads done (RED aliases K); DEN + QKP visible

    // ---- Stage B partials: T v (own j-half, causal-sparse) + q Scat (own kk-half) ----
    float accB[8][4];
    #pragma unroll
    for (int t = 0; t < 8; t++)
        #pragma unroll
        for (int u = 0; u < 4; u++) accB[t][u] = 0.f;
    {
        const uint32_t bvh = sbase + B_VH + (uint32_t)nh * 9216u + lt;
        #pragma unroll
        for (int kkt = 0; kkt < 4; kkt++) {
            if (nh * 64 + kkt * 16 <= ilast) {
                #pragma unroll
                for (int p = 0; p < 4; p++) {
                    uint32_t bh0, bh1, bh2, bh3;
                    LDM4T(bh0, bh1, bh2, bh3, bvh + kkt * 2304 + p * 32);
                    mma_f16(accB[2 * p],     thA[kkt][0], thA[kkt][1], thA[kkt][2], thA[kkt][3], bh0, bh2);
                    mma_f16(accB[2 * p + 1], thA[kkt][0], thA[kkt][1], thA[kkt][2], thA[kkt][3], bh1, bh3);
                }
            }
        }
        const uint32_t bsh = sbase + B_SH + laneoff;
        #pragma unroll 1
        for (int kkl = 0; kkl < 4; kkl++) {
            int kk = nh * 4 + kkl;
            uint32_t ah0, ah1, ah2, ah3;
            LDM4(ah0, ah1, ah2, ah3, aqh + kk * 32);
            #pragma unroll
            for (int p = 0; p < 4; p++) {
                uint32_t bh0, bh1, bh2, bh3;
                LDM4(bh0, bh1, bh2, bh3, bsh + p * 4352 + kk * 32);
                mma_f16(accB[2 * p],     ah0, ah1, ah2, ah3, bh0, bh2);
                mma_f16(accB[2 * p + 1], ah0, ah1, ah2, ah3, bh1, bh3);
            }
        }
    }

    // ---- cross-warp reduction + epilogue ----
    if (nh == 1) {
        #pragma unroll
        for (int t = 0; t < 8; t++) {
            int e = t * 8 + tq * 2;
            *(float2*)&REDf[i0 * 64 + e] = make_float2(accB[t][0], accB[t][1]);
            *(float2*)&REDf[i1 * 64 + e] = make_float2(accB[t][2], accB[t][3]);
        }
    }
    __syncthreads();
    if (nh == 0) {
        float dnv0 = 1.0f / (DENf[i0 * 2] + DENf[i0 * 2 + 1] + QKPf[i0] + 1e-10f);
        float dnv1 = 1.0f / (DENf[i1 * 2] + DENf[i1 * 2 + 1] + QKPf[i1] + 1e-10f);
        float* op = outg + cbase;
        #pragma unroll
        for (int t = 0; t < 8; t++) {
            int e = t * 8 + tq * 2;
            float2 p0 = *(const float2*)&REDf[i0 * 64 + e];
            float2 p1 = *(const float2*)&REDf[i1 * 64 + e];
            *(float2*)&op[i0 * DD + e] = make_float2((accB[t][0] + p0.x) * dnv0, (accB[t][1] + p0.y) * dnv0);
            *(float2*)&op[i1 * DD + e] = make_float2((accB[t][2] + p1.x) * dnv1, (accB[t][3] + p1.y) * dnv1);
        }
    }
}

// ---------------------------------------------------------------------------
extern "C" void kernel_launch(void* const* d_in, const int* in_sizes, int n_in,
                              void* d_out, int out_size) {
    const float* q  = (const float*)d_in[0];
    const float* k  = (const float*)d_in[1];
    const float* qr = (const float*)d_in[2];
    const float* kr = (const float*)d_in[3];
    const float* v  = (const float*)d_in[4];
    float* out = (float*)d_out;

    cudaFuncSetAttribute(pass1_kernel, cudaFuncAttributeMaxDynamicSharedMemorySize, P1_SMEM);
    cudaFuncSetAttribute(pass3_kernel, cudaFuncAttributeMaxDynamicSharedMemorySize, SMEM3);

    dim3 g1(NC, G);
    pass1_kernel<<<g1, 256, P1_SMEM>>>(k, kr, v);
    dim3 g2(G, 2, 8);
    pass2_kernel<<<g2, 128>>>();
    dim3 g3(NC, G);
    pass3_kernel<<<g3, 512, SMEM3>>>(q, qr, k, kr, v, out);
}

// round 14
// speedup vs baseline: 9.9659x; 1.0335x over previous
#include <cuda_runtime.h>
#include <cuda_fp16.h>
#include <stdint.h>

#define G    16
#define NSEQ 4096
#define DD   64
#define CC   128
#define NC   32

// g_Sh holds S^T in fp16 pairs: ST[e][d] = sum_j v[j][e]*k[j][d], exclusive-prefixed by pass2.
__device__ __align__(16) uint32_t g_Sh[2ull * G * NC * DD * DD / 2];
__device__ __align__(16) float g_ksum[2ull * G * NC * DD];

__device__ __forceinline__ uint32_t smem_u32(const void* p) {
    uint32_t a;
    asm("{ .reg .u64 t; cvta.to.shared.u64 t, %1; cvt.u32.u64 %0, t; }" : "=r"(a) : "l"(p));
    return a;
}
#define LDM4(r0, r1, r2, r3, addr) \
    asm volatile("ldmatrix.sync.aligned.m8n8.x4.shared.b16 {%0,%1,%2,%3}, [%4];" \
                 : "=r"(r0), "=r"(r1), "=r"(r2), "=r"(r3) : "r"(addr))
#define LDM4T(r0, r1, r2, r3, addr) \
    asm volatile("ldmatrix.sync.aligned.m8n8.x4.trans.shared.b16 {%0,%1,%2,%3}, [%4];" \
                 : "=r"(r0), "=r"(r1), "=r"(r2), "=r"(r3) : "r"(addr))
__device__ __forceinline__ void mma_f16(float* c, uint32_t a0, uint32_t a1, uint32_t a2, uint32_t a3,
                                        uint32_t b0, uint32_t b1) {
    asm("mma.sync.aligned.m16n8k16.row.col.f32.f16.f16.f32 "
        "{%0,%1,%2,%3},{%4,%5,%6,%7},{%8,%9},{%0,%1,%2,%3};"
        : "+f"(c[0]), "+f"(c[1]), "+f"(c[2]), "+f"(c[3])
        : "r"(a0), "r"(a1), "r"(a2), "r"(a3), "r"(b0), "r"(b1));
}
__device__ __forceinline__ uint32_t packh2(float x, float y) {
    __half2 h = __floats2half2_rn(x, y);
    return *(uint32_t*)&h;
}

// ===========================================================================
// Pass 1 (fp16): ST_m[e][d] = sum_j v[j][e] k_m[j][d]; ksum from staged fp16.
// Row-major fp16 tiles, pitch 36 words: VH 0, K1H 4608, K2H 9216 -> 13824 w
// ===========================================================================
#define P1_SMEM (13824 * 4)
__global__ __launch_bounds__(256) void pass1_kernel(const float* __restrict__ k1g,
                                                    const float* __restrict__ k2g,
                                                    const float* __restrict__ vg) {
    extern __shared__ uint32_t smw[];
    const int c = blockIdx.x, g = blockIdx.y;
    const int tid = threadIdx.x, w = tid >> 5, lane = tid & 31;
    const int gq = lane >> 2, tq = lane & 3;
    const size_t cbase = ((size_t)g * NSEQ + (size_t)c * CC) * DD;

    {   // register-batched staging: 8 LDG.128 in flight per tensor
        const float4* srcs[3] = {(const float4*)(vg + cbase), (const float4*)(k1g + cbase),
                                 (const float4*)(k2g + cbase)};
        const int dsts[3] = {0, 4608, 9216};
        #pragma unroll
        for (int t = 0; t < 3; t++) {
            float4 r[8];
            #pragma unroll
            for (int it = 0; it < 8; it++) r[it] = srcs[t][it * 256 + tid];
            #pragma unroll
            for (int it = 0; it < 8; it++) {
                int wi = (it * 256 + tid) * 2;
                int off = dsts[t] + (wi >> 5) * 36 + (wi & 31);
                smw[off]     = packh2(r[it].x, r[it].y);
                smw[off + 1] = packh2(r[it].z, r[it].w);
            }
        }
    }
    __syncthreads();

    // ksum from staged fp16 k tiles (denominator-only error ~2^-12)
    if (tid < 128) {
        int m = tid >> 6, d = tid & 63;
        const uint32_t* kb = smw + (m ? 9216 : 4608) + (d >> 1);
        int hi = d & 1;
        float s = 0.f;
        #pragma unroll 16
        for (int j = 0; j < CC; j++) {
            __half2 h = *(const __half2*)&kb[j * 36];
            s += hi ? __high2float(h) : __low2float(h);
        }
        g_ksum[(((size_t)m * G + g) * NC + c) * DD + d] = s;
    }

    const int band = (w >> 1) * 16, nh = w & 1;
    const uint32_t sbase = smem_u32(smw);
    const uint32_t lt = ((lane & 7) + ((lane >> 4) & 1) * 8) * 144 + ((lane >> 3) & 1) * 16;
    const uint32_t avh = sbase + lt + (uint32_t)band * 2;   // A = v^T, m = e

    float accP[2][4][4];
    #pragma unroll
    for (int m = 0; m < 2; m++)
        #pragma unroll
        for (int t = 0; t < 4; t++)
            #pragma unroll
            for (int u = 0; u < 4; u++) accP[m][t][u] = 0.f;

    #pragma unroll
    for (int m = 0; m < 2; m++) {
        const uint32_t bkh = sbase + (m ? 9216u : 4608u) * 4 + lt + (uint32_t)nh * 64;
        #pragma unroll 1
        for (int kk = 0; kk < 8; kk++) {
            uint32_t ah0, ah1, ah2, ah3;
            LDM4T(ah0, ah1, ah2, ah3, avh + kk * 2304);
            #pragma unroll
            for (int p = 0; p < 2; p++) {
                uint32_t bh0, bh1, bh2, bh3;
                LDM4T(bh0, bh1, bh2, bh3, bkh + p * 32 + kk * 2304);
                mma_f16(accP[m][2 * p],     ah0, ah1, ah2, ah3, bh0, bh2);
                mma_f16(accP[m][2 * p + 1], ah0, ah1, ah2, ah3, bh1, bh3);
            }
        }
    }
    #pragma unroll
    for (int m = 0; m < 2; m++) {
        uint32_t* Sp = &g_Sh[(((size_t)m * G + g) * NC + c) * 2048];
        #pragma unroll
        for (int t = 0; t < 4; t++) {
            int wcol = nh * 16 + t * 4 + tq;
            int e0 = band + gq;
            Sp[e0 * 32 + wcol]       = packh2(accP[m][t][0], accP[m][t][1]);
            Sp[(e0 + 8) * 32 + wcol] = packh2(accP[m][t][2], accP[m][t][3]);
        }
    }
}

// ===========================================================================
// Pass 2: exclusive prefix over chunks on fp16 storage, f32 running sums.
// ===========================================================================
__global__ __launch_bounds__(128) void pass2_kernel() {
    const int g = blockIdx.x, m = blockIdx.y, h = blockIdx.z, tid = threadIdx.x;
    uint32_t* base = g_Sh + (((size_t)m * G + g) * NC) * 2048 + ((size_t)(h * 128 + tid)) * 2;
    float4 run = make_float4(0.f, 0.f, 0.f, 0.f);
    uint2 buf[8];
    #pragma unroll
    for (int i = 0; i < 8; i++) buf[i] = *(uint2*)(base + (size_t)i * 2048);
    #pragma unroll 8
    for (int c = 0; c < NC; c++) {
        uint2 cur = buf[c & 7];
        if (c + 8 < NC) buf[c & 7] = *(uint2*)(base + (size_t)(c + 8) * 2048);
        uint2 wv;
        wv.x = packh2(run.x, run.y);
        wv.y = packh2(run.z, run.w);
        *(uint2*)(base + (size_t)c * 2048) = wv;
        __half2 a = *(__half2*)&cur.x, b = *(__half2*)&cur.y;
        run.x += __low2float(a); run.y += __high2float(a);
        run.z += __low2float(b); run.w += __high2float(b);
    }
    if (h == 0 && tid < DD) {
        float* kb = &g_ksum[(((size_t)m * G + g) * NC) * DD];
        float fb[8];
        #pragma unroll
        for (int i = 0; i < 8; i++) fb[i] = kb[i * DD + tid];
        float r = 0.f;
        #pragma unroll 8
        for (int c = 0; c < NC; c++) {
            float cu = fb[c & 7];
            if (c + 8 < NC) fb[c & 7] = kb[(c + 8) * DD + tid];
            kb[c * DD + tid] = r;
            r += cu;
        }
    }
}

// ===========================================================================
// Pass 3 (fp16, causal-sparse, 512 thr / 16 warps, 2 CTAs/SM).
// ===========================================================================
#define B_KH  34816u
#define B_VH  69632u
#define B_SH  88064u
#define W_KH  8704
#define W_VH  17408
#define W_SH  22016
#define W_QKP 26368
#define W_KP  26496
#define W_DEN 26624
#define W_RED W_KH
#define SMEM3 (26880 * 4)

__global__ __launch_bounds__(512) void pass3_kernel(const float* __restrict__ q1g,
                                                    const float* __restrict__ q2g,
                                                    const float* __restrict__ k1g,
                                                    const float* __restrict__ k2g,
                                                    const float* __restrict__ vg,
                                                    float* __restrict__ outg) {
    extern __shared__ uint32_t smw[];
    const int c = blockIdx.x, g = blockIdx.y, tid = threadIdx.x;
    const int w = tid >> 5, lane = tid & 31;
    const int gq = lane >> 2, tq = lane & 3;
    const int band = (w >> 1) * 16, nh = w & 1;
    const int ilast = band + 15;
    const size_t cbase = ((size_t)g * NSEQ + (size_t)c * CC) * DD;
    float* QKPf = (float*)(smw + W_QKP);
    float* KPf  = (float*)(smw + W_KP);
    float* DENf = (float*)(smw + W_DEN);
    float* REDf = (float*)(smw + W_RED);

    // ---- register-batched staging (4 LDG.128 in flight per tensor) ----
    {
        const float4* srcs[5] = {(const float4*)(q1g + cbase), (const float4*)(q2g + cbase),
                                 (const float4*)(k1g + cbase), (const float4*)(k2g + cbase),
                                 (const float4*)(vg + cbase)};
        #pragma unroll
        for (int t = 0; t < 5; t++) {
            float4 r[4];
            #pragma unroll
            for (int it = 0; it < 4; it++) r[it] = srcs[t][it * 512 + tid];
            #pragma unroll
            for (int it = 0; it < 4; it++) {
                int wi = (it * 512 + tid) * 2;
                int off;
                if (t == 4)      off = W_VH + (wi >> 5) * 36 + (wi & 31);
                else if (t == 0) off = (wi >> 5) * 68 + (wi & 31);
                else if (t == 1) off = (wi >> 5) * 68 + (wi & 31) + 32;
                else if (t == 2) off = W_KH + (wi >> 5) * 68 + (wi & 31);
                else             off = W_KH + (wi >> 5) * 68 + (wi & 31) + 32;
                smw[off]     = packh2(r[it].x, r[it].y);
                smw[off + 1] = packh2(r[it].z, r[it].w);
            }
        }
        const uint2* s1p = (const uint2*)&g_Sh[(((size_t)0 * G + g) * NC + c) * 2048];
        const uint2* s2p = (const uint2*)&g_Sh[(((size_t)1 * G + g) * NC + c) * 2048];
        uint2 s1r[2], s2r[2];
        #pragma unroll
        for (int it = 0; it < 2; it++) { s1r[it] = s1p[it * 512 + tid]; s2r[it] = s2p[it * 512 + tid]; }
        #pragma unroll
        for (int it = 0; it < 2; it++) {
            int wi = (it * 512 + tid) * 2;
            int off = (wi >> 5) * 68 + (wi & 31);
            smw[W_SH + off]      = s1r[it].x;
            smw[W_SH + off + 1]  = s1r[it].y;
            smw[W_SH + off + 32] = s2r[it].x;
            smw[W_SH + off + 33] = s2r[it].y;
        }
        if (tid < DD) {
            KPf[tid]      = g_ksum[(((size_t)0 * G + g) * NC + c) * DD + tid];
            KPf[64 + tid] = g_ksum[(((size_t)1 * G + g) * NC + c) * DD + tid];
        }
    }
    __syncthreads();

    // qkpre from staged fp16 q
    if (tid < CC) {
        float a = 0.f;
        #pragma unroll 8
        for (int wd = 0; wd < 64; wd++) {
            uint32_t qw = smw[tid * 68 + wd];
            __half2 h = *(__half2*)&qw;
            a += __low2float(h) * KPf[2 * wd] + __high2float(h) * KPf[2 * wd + 1];
        }
        QKPf[tid] = a;
    }

    const uint32_t sbase = smem_u32(smw);
    const uint32_t laneoff = ((lane & 7) + ((lane >> 3) & 1) * 8) * 272 + ((lane >> 4) & 1) * 16;
    const uint32_t lt = ((lane & 7) + ((lane >> 4) & 1) * 8) * 144 + ((lane >> 3) & 1) * 16;
    const uint32_t aqh = sbase + band * 272 + laneoff;

    // ---- Stage A: T[band rows][nh col-half], causal-sparse ----
    float accA[8][4];
    #pragma unroll
    for (int t = 0; t < 8; t++)
        #pragma unroll
        for (int u = 0; u < 4; u++) accA[t][u] = 0.f;
    if (nh * 64 <= ilast) {
        const uint32_t bkh = sbase + B_KH + (uint32_t)nh * 17408u + laneoff;
        #pragma unroll 1
        for (int kk = 0; kk < 8; kk++) {
            uint32_t ah0, ah1, ah2, ah3;
            LDM4(ah0, ah1, ah2, ah3, aqh + kk * 32);
            #pragma unroll
            for (int p = 0; p < 4; p++) {
                if (nh * 64 + p * 16 <= ilast) {
                    uint32_t bh0, bh1, bh2, bh3;
                    LDM4(bh0, bh1, bh2, bh3, bkh + p * 4352 + kk * 32);
                    mma_f16(accA[2 * p],     ah0, ah1, ah2, ah3, bh0, bh2);
                    mma_f16(accA[2 * p + 1], ah0, ah1, ah2, ah3, bh1, bh3);
                }
            }
        }
    }

    // ---- epilogue A ----
    const int i0 = band + gq, i1 = i0 + 8;
    uint32_t thA[4][4];
    #pragma unroll
    for (int t = 0; t < 4; t++)
        #pragma unroll
        for (int u = 0; u < 4; u++) thA[t][u] = 0u;
    float rs0 = 0.f, rs1 = 0.f;
    #pragma unroll
    for (int kkt = 0; kkt < 4; kkt++) {
        if (nh * 64 + kkt * 16 <= ilast) {
            int ce = nh * 64 + kkt * 16 + tq * 2, co = ce + 8;
            float e00 = (ce <= i0) ? accA[2 * kkt][0] : 0.f;
            float e01 = (ce + 1 <= i0) ? accA[2 * kkt][1] : 0.f;
            float e10 = (ce <= i1) ? accA[2 * kkt][2] : 0.f;
            float e11 = (ce + 1 <= i1) ? accA[2 * kkt][3] : 0.f;
            float o00 = (co <= i0) ? accA[2 * kkt + 1][0] : 0.f;
            float o01 = (co + 1 <= i0) ? accA[2 * kkt + 1][1] : 0.f;
            float o10 = (co <= i1) ? accA[2 * kkt + 1][2] : 0.f;
            float o11 = (co + 1 <= i1) ? accA[2 * kkt + 1][3] : 0.f;
            rs0 += e00 + e01 + o00 + o01;
            rs1 += e10 + e11 + o10 + o11;
            thA[kkt][0] = packh2(e00, e01);
            thA[kkt][1] = packh2(e10, e11);
            thA[kkt][2] = packh2(o00, o01);
            thA[kkt][3] = packh2(o10, o11);
        }
    }
    rs0 += __shfl_xor_sync(0xFFFFFFFFu, rs0, 1);
    rs0 += __shfl_xor_sync(0xFFFFFFFFu, rs0, 2);
    rs1 += __shfl_xor_sync(0xFFFFFFFFu, rs1, 1);
    rs1 += __shfl_xor_sync(0xFFFFFFFFu, rs1, 2);
    if (tq == 0) {
        DENf[i0 * 2 + nh] = rs0;
        DENf[i1 * 2 + nh] = rs1;
    }
    __syncthreads();   // K reads done (RED aliases K); DEN + QKP visible

    // ---- Stage B partials ----
    float accB[8][4];
    #pragma unroll
    for (int t = 0; t < 8; t++)
        #pragma unroll
        for (int u = 0; u < 4; u++) accB[t][u] = 0.f;
    {
        const uint32_t bvh = sbase + B_VH + (uint32_t)nh * 9216u + lt;
        #pragma unroll
        for (int kkt = 0; kkt < 4; kkt++) {
            if (nh * 64 + kkt * 16 <= ilast) {
                #pragma unroll
                for (int p = 0; p < 4; p++) {
                    uint32_t bh0, bh1, bh2, bh3;
                    LDM4T(bh0, bh1, bh2, bh3, bvh + kkt * 2304 + p * 32);
                    mma_f16(accB[2 * p],     thA[kkt][0], thA[kkt][1], thA[kkt][2], thA[kkt][3], bh0, bh2);
                    mma_f16(accB[2 * p + 1], thA[kkt][0], thA[kkt][1], thA[kkt][2], thA[kkt][3], bh1, bh3);
                }
            }
        }
        const uint32_t bsh = sbase + B_SH + laneoff;
        #pragma unroll 1
        for (int kkl = 0; kkl < 4; kkl++) {
            int kk = nh * 4 + kkl;
            uint32_t ah0, ah1, ah2, ah3;
            LDM4(ah0, ah1, ah2, ah3, aqh + kk * 32);
            #pragma unroll
            for (int p = 0; p < 4; p++) {
                uint32_t bh0, bh1, bh2, bh3;
                LDM4(bh0, bh1, bh2, bh3, bsh + p * 4352 + kk * 32);
                mma_f16(accB[2 * p],     ah0, ah1, ah2, ah3, bh0, bh2);
                mma_f16(accB[2 * p + 1], ah0, ah1, ah2, ah3, bh1, bh3);
            }
        }
    }

    // ---- cross-warp reduction + epilogue ----
    if (nh == 1) {
        #pragma unroll
        for (int t = 0; t < 8; t++) {
            int e = t * 8 + tq * 2;
            *(float2*)&REDf[i0 * 64 + e] = make_float2(accB[t][0], accB[t][1]);
            *(float2*)&REDf[i1 * 64 + e] = make_float2(accB[t][2], accB[t][3]);
        }
    }
    __syncthreads();
    if (nh == 0) {
        float dnv0 = 1.0f / (DENf[i0 * 2] + DENf[i0 * 2 + 1] + QKPf[i0] + 1e-10f);
        float dnv1 = 1.0f / (DENf[i1 * 2] + DENf[i1 * 2 + 1] + QKPf[i1] + 1e-10f);
        float* op = outg + cbase;
        #pragma unroll
        for (int t = 0; t < 8; t++) {
            int e = t * 8 + tq * 2;
            float2 p0 = *(const float2*)&REDf[i0 * 64 + e];
            float2 p1 = *(const float2*)&REDf[i1 * 64 + e];
            *(float2*)&op[i0 * DD + e] = make_float2((accB[t][0] + p0.x) * dnv0, (accB[t][1] + p0.y) * dnv0);
            *(float2*)&op[i1 * DD + e] = make_float2((accB[t][2] + p1.x) * dnv1, (accB[t][3] + p1.y) * dnv1);
        }
    }
}

// ---------------------------------------------------------------------------
extern "C" void kernel_launch(void* const* d_in, const int* in_sizes, int n_in,
                              void* d_out, int out_size) {
    const float* q  = (const float*)d_in[0];
    const float* k  = (const float*)d_in[1];
    const float* qr = (const float*)d_in[2];
    const float* kr = (const float*)d_in[3];
    const float* v  = (const float*)d_in[4];
    float* out = (float*)d_out;

    cudaFuncSetAttribute(pass1_kernel, cudaFuncAttributeMaxDynamicSharedMemorySize, P1_SMEM);
    cudaFuncSetAttribute(pass3_kernel, cudaFuncAttributeMaxDynamicSharedMemorySize, SMEM3);

    dim3 g1(NC, G);
    pass1_kernel<<<g1, 256, P1_SMEM>>>(k, kr, v);
    dim3 g2(G, 2, 8);
    pass2_kernel<<<g2, 128>>>();
    dim3 g3(NC, G);
    pass3_kernel<<<g3, 512, SMEM3>>>(q, qr, k, kr, v, out);
}